// round 1
// baseline (speedup 1.0000x reference)
#include <cuda_runtime.h>
#include <math.h>
#include <stdint.h>

// Problem constants
#define BB   2
#define SS   2048
#define DD   1024
#define HH   16
#define DH   64
#define FF   4096
#define NTOK (BB*SS)          // 4096 rows
#define D3   (3*DD)           // 3072

// ---------------------------------------------------------------------------
// Scratch (static device globals — no runtime allocation allowed)
// ---------------------------------------------------------------------------
__device__ float g_qkv [NTOK * D3];       // 50 MB
__device__ float g_attn[NTOK * DD];       // attention output (pre-proj)
__device__ float g_proj[NTOK * DD];       // after Wo
__device__ float g_hbuf[NTOK * DD];       // LN1 output (residual source for LN2)
__device__ float g_u   [NTOK * 2 * FF];   // 134 MB
__device__ float g_mbuf[NTOK * FF];       // gelu*gate
__device__ float g_m2  [NTOK * DD];       // after W2

// ---------------------------------------------------------------------------
// SGEMM: C[m][n] = sum_k A[m][k] * W[n][k] + bias[n]
// A: [M,K] row-major, W: [N,K] row-major ("NT"). Requires M%128==0, N%128==0,
// K%8==0 (all shapes here satisfy this).
// BM=BN=128, BK=8, 256 threads, 8x8 micro-tile per thread.
// ---------------------------------------------------------------------------
__global__ void __launch_bounds__(256) sgemm_nt_bias(
    const float* __restrict__ A, const float* __restrict__ W,
    const float* __restrict__ bias, float* __restrict__ C,
    int M, int N, int K)
{
    __shared__ float As[8][128];
    __shared__ float Ws[8][128];

    const int tid = threadIdx.x;
    const int m0 = blockIdx.y * 128;
    const int n0 = blockIdx.x * 128;

    const int lr = tid >> 1;            // 0..127 : tile row for loads
    const int lc = (tid & 1) << 2;      // 0 or 4 : k offset for loads

    const int tr = (tid >> 4) << 3;     // 0..120 step 8 : micro-tile row base
    const int tc = (tid & 15) << 3;     // 0..120 step 8 : micro-tile col base

    const float* Aptr = A + (size_t)(m0 + lr) * K + lc;
    const float* Wptr = W + (size_t)(n0 + lr) * K + lc;

    float acc[8][8];
#pragma unroll
    for (int i = 0; i < 8; i++)
#pragma unroll
        for (int j = 0; j < 8; j++) acc[i][j] = 0.f;

    for (int k0 = 0; k0 < K; k0 += 8) {
        float4 av = *(const float4*)(Aptr + k0);
        float4 wv = *(const float4*)(Wptr + k0);
        As[lc + 0][lr] = av.x; As[lc + 1][lr] = av.y;
        As[lc + 2][lr] = av.z; As[lc + 3][lr] = av.w;
        Ws[lc + 0][lr] = wv.x; Ws[lc + 1][lr] = wv.y;
        Ws[lc + 2][lr] = wv.z; Ws[lc + 3][lr] = wv.w;
        __syncthreads();

#pragma unroll
        for (int k = 0; k < 8; k++) {
            float rm[8], rn[8];
#pragma unroll
            for (int i = 0; i < 8; i++) rm[i] = As[k][tr + i];
#pragma unroll
            for (int j = 0; j < 8; j++) rn[j] = Ws[k][tc + j];
#pragma unroll
            for (int i = 0; i < 8; i++)
#pragma unroll
                for (int j = 0; j < 8; j++)
                    acc[i][j] += rm[i] * rn[j];
        }
        __syncthreads();
    }

#pragma unroll
    for (int i = 0; i < 8; i++) {
        size_t crow = (size_t)(m0 + tr + i) * N + n0 + tc;
#pragma unroll
        for (int j = 0; j < 8; j += 4) {
            float4 o;
            o.x = acc[i][j + 0] + bias[n0 + tc + j + 0];
            o.y = acc[i][j + 1] + bias[n0 + tc + j + 1];
            o.z = acc[i][j + 2] + bias[n0 + tc + j + 2];
            o.w = acc[i][j + 3] + bias[n0 + tc + j + 3];
            *(float4*)&C[crow + j] = o;
        }
    }
}

// ---------------------------------------------------------------------------
// RoPE, in-place on q and k slices of g_qkv.
// qkv row = b*S+s, col = part*D + h*64 + dh. One thread per (row, part, h, dh<32).
// ---------------------------------------------------------------------------
__global__ void __launch_bounds__(256) rope_kernel(
    float* __restrict__ qkv, const int* __restrict__ p,
    const float* __restrict__ freqs)
{
    int gid = blockIdx.x * blockDim.x + threadIdx.x;  // < NTOK*2*H*32
    int dh2  = gid & 31;
    int h    = (gid >> 5) & (HH - 1);
    int part = (gid >> 9) & 1;
    int row  = gid >> 10;
    if (row >= NTOK) return;

    float pos = (float)p[row];
    float a1 = pos * freqs[dh2];
    float a2 = pos * freqs[dh2 + 32];
    float c1, s1, c2, s2;
    sincosf(a1, &s1, &c1);
    sincosf(a2, &s2, &c2);

    float* base = qkv + (size_t)row * D3 + part * DD + h * DH + dh2;
    float x1 = base[0];
    float x2 = base[32];
    base[0]  = x1 * c1 + x2 * s1;   // rotate_half: first half picks x2
    base[32] = x2 * c2 + x1 * s2;   // second half picks x1
}

// ---------------------------------------------------------------------------
// Flash attention, fp32, 64x64 tiles, online softmax.
// grid (S/64, H, B), 256 threads arranged 16x16, 4x4 micro-tile.
// Dynamic smem: QsT[64][68] (d-major, pre-scaled), KsT[64][68] (d-major),
//               Vs[64][68] (row-major), PsT[64][68] (col-major).
// ---------------------------------------------------------------------------
#define FA_STRIDE 68
#define FA_SMEM   (4 * 64 * FA_STRIDE * (int)sizeof(float))

__global__ void __launch_bounds__(256) flash_attn_kernel(
    const float* __restrict__ qkv, float* __restrict__ O)
{
    extern __shared__ float sm[];
    float* QsT = sm;
    float* KsT = sm + 1 * 64 * FA_STRIDE;
    float* Vs  = sm + 2 * 64 * FA_STRIDE;
    float* PsT = sm + 3 * 64 * FA_STRIDE;

    const int tid = threadIdx.x;
    const int ty = tid >> 4;          // 0..15 : q-row group
    const int tx = tid & 15;          // 0..15 : col group
    const int qt = blockIdx.x, h = blockIdx.y, b = blockIdx.z;
    const int rowBase = b * SS + qt * 64;
    const int cq = h * DH;

    // Load Q tile (scaled by DH^-0.5), stored d-major
    for (int i = tid; i < 64 * 64; i += 256) {
        int r = i >> 6, c = i & 63;
        QsT[c * FA_STRIDE + r] =
            qkv[(size_t)(rowBase + r) * D3 + cq + c] * 0.125f;
    }

    float m_i[4], l_i[4], acc[4][4];
#pragma unroll
    for (int i = 0; i < 4; i++) {
        m_i[i] = -1e30f; l_i[i] = 0.f;
#pragma unroll
        for (int j = 0; j < 4; j++) acc[i][j] = 0.f;
    }
    __syncthreads();

    for (int kt = 0; kt < SS / 64; kt++) {
        const int kRow = b * SS + kt * 64;
        for (int i = tid; i < 64 * 64; i += 256) {
            int r = i >> 6, c = i & 63;
            const float* src = qkv + (size_t)(kRow + r) * D3 + cq + c;
            KsT[c * FA_STRIDE + r] = src[DD];        // K, d-major
            Vs [r * FA_STRIDE + c] = src[2 * DD];    // V, row-major
        }
        __syncthreads();

        // S = Q * K^T (already scaled)
        float s[4][4];
#pragma unroll
        for (int i = 0; i < 4; i++)
#pragma unroll
            for (int j = 0; j < 4; j++) s[i][j] = 0.f;

        for (int d = 0; d < 64; d++) {
            float4 qv = *(const float4*)&QsT[d * FA_STRIDE + ty * 4];
            float4 kv = *(const float4*)&KsT[d * FA_STRIDE + tx * 4];
            float qa[4] = {qv.x, qv.y, qv.z, qv.w};
            float ka[4] = {kv.x, kv.y, kv.z, kv.w};
#pragma unroll
            for (int i = 0; i < 4; i++)
#pragma unroll
                for (int j = 0; j < 4; j++)
                    s[i][j] += qa[i] * ka[j];
        }

        // Online softmax (row stats reduced across the 16 tx lanes)
#pragma unroll
        for (int i = 0; i < 4; i++) {
            float tmax = fmaxf(fmaxf(s[i][0], s[i][1]), fmaxf(s[i][2], s[i][3]));
#pragma unroll
            for (int o = 8; o; o >>= 1)
                tmax = fmaxf(tmax, __shfl_xor_sync(0xffffffffu, tmax, o));
            float mnew = fmaxf(m_i[i], tmax);
            float corr = __expf(m_i[i] - mnew);
            float tsum = 0.f;
#pragma unroll
            for (int j = 0; j < 4; j++) {
                s[i][j] = __expf(s[i][j] - mnew);
                tsum += s[i][j];
            }
#pragma unroll
            for (int o = 8; o; o >>= 1)
                tsum += __shfl_xor_sync(0xffffffffu, tsum, o);
            l_i[i] = l_i[i] * corr + tsum;
            m_i[i] = mnew;
#pragma unroll
            for (int j = 0; j < 4; j++) acc[i][j] *= corr;
            // store P transposed: PsT[col][row]
#pragma unroll
            for (int j = 0; j < 4; j++)
                PsT[(tx * 4 + j) * FA_STRIDE + ty * 4 + i] = s[i][j];
        }
        __syncthreads();

        // acc += P @ V
        for (int j = 0; j < 64; j++) {
            float4 pv = *(const float4*)&PsT[j * FA_STRIDE + ty * 4];
            float4 vv = *(const float4*)&Vs [j * FA_STRIDE + tx * 4];
            float pa[4] = {pv.x, pv.y, pv.z, pv.w};
            float va[4] = {vv.x, vv.y, vv.z, vv.w};
#pragma unroll
            for (int i = 0; i < 4; i++)
#pragma unroll
                for (int dd = 0; dd < 4; dd++)
                    acc[i][dd] += pa[i] * va[dd];
        }
        __syncthreads();
    }

    // Write O[b, s, h*64 + d]
#pragma unroll
    for (int i = 0; i < 4; i++) {
        float inv = 1.0f / l_i[i];
        float4 o4 = make_float4(acc[i][0] * inv, acc[i][1] * inv,
                                acc[i][2] * inv, acc[i][3] * inv);
        *(float4*)&O[(size_t)(rowBase + ty * 4 + i) * DD + cq + tx * 4] = o4;
    }
}

// ---------------------------------------------------------------------------
// Fused residual add + LayerNorm. One block per row (D=1024), 256 threads.
// out = LN(A + R) * g + be
// ---------------------------------------------------------------------------
__global__ void __launch_bounds__(256) add_ln_kernel(
    const float* __restrict__ A, const float* __restrict__ R,
    const float* __restrict__ g, const float* __restrict__ be,
    float* __restrict__ out)
{
    __shared__ float red[8];
    const int row = blockIdx.x, tid = threadIdx.x;
    const int lane = tid & 31, wid = tid >> 5;

    float4 a = ((const float4*)(A + (size_t)row * DD))[tid];
    float4 r = ((const float4*)(R + (size_t)row * DD))[tid];
    float4 t = make_float4(a.x + r.x, a.y + r.y, a.z + r.z, a.w + r.w);

    float ssum = t.x + t.y + t.z + t.w;
#pragma unroll
    for (int o = 16; o; o >>= 1) ssum += __shfl_xor_sync(0xffffffffu, ssum, o);
    if (lane == 0) red[wid] = ssum;
    __syncthreads();
    float mean = (red[0] + red[1] + red[2] + red[3] +
                  red[4] + red[5] + red[6] + red[7]) * (1.0f / DD);
    __syncthreads();

    float4 d = make_float4(t.x - mean, t.y - mean, t.z - mean, t.w - mean);
    float sq = d.x * d.x + d.y * d.y + d.z * d.z + d.w * d.w;
#pragma unroll
    for (int o = 16; o; o >>= 1) sq += __shfl_xor_sync(0xffffffffu, sq, o);
    if (lane == 0) red[wid] = sq;
    __syncthreads();
    float var = (red[0] + red[1] + red[2] + red[3] +
                 red[4] + red[5] + red[6] + red[7]) * (1.0f / DD);
    float rs = rsqrtf(var + 1e-5f);

    float4 gv = ((const float4*)g)[tid];
    float4 bv = ((const float4*)be)[tid];
    float4 o4 = make_float4(d.x * rs * gv.x + bv.x,
                            d.y * rs * gv.y + bv.y,
                            d.z * rs * gv.z + bv.z,
                            d.w * rs * gv.w + bv.w);
    ((float4*)(out + (size_t)row * DD))[tid] = o4;
}

// ---------------------------------------------------------------------------
// GELU(exact) * gate. u: [NTOK, 2*FF], m: [NTOK, FF]. float4-vectorized.
// ---------------------------------------------------------------------------
__global__ void __launch_bounds__(256) gelu_gate_kernel(
    const float* __restrict__ u, float* __restrict__ m)
{
    int gid = blockIdx.x * blockDim.x + threadIdx.x;   // < NTOK * FF/4
    const int f4_per_row = FF / 4;                     // 1024
    int row  = gid / f4_per_row;
    int col4 = gid - row * f4_per_row;
    if (row >= NTOK) return;

    const float4* U4 = (const float4*)(u + (size_t)row * 2 * FF);
    float4 a = U4[col4];
    float4 gt = U4[f4_per_row + col4];

    const float inv_sqrt2 = 0.70710678118654752f;
    float4 o;
    o.x = 0.5f * a.x * (1.0f + erff(a.x * inv_sqrt2)) * gt.x;
    o.y = 0.5f * a.y * (1.0f + erff(a.y * inv_sqrt2)) * gt.y;
    o.z = 0.5f * a.z * (1.0f + erff(a.z * inv_sqrt2)) * gt.z;
    o.w = 0.5f * a.w * (1.0f + erff(a.w * inv_sqrt2)) * gt.w;
    ((float4*)(m + (size_t)row * FF))[col4] = o;
}

// ---------------------------------------------------------------------------
// kernel_launch — one full encoder layer, graph-capturable (launches only)
// ---------------------------------------------------------------------------
extern "C" void kernel_launch(void* const* d_in, const int* in_sizes, int n_in,
                              void* d_out, int out_size)
{
    const float* x      = (const float*)d_in[0];
    const int*   p      = (const int*)  d_in[1];
    const float* Wqkv   = (const float*)d_in[2];
    const float* bqkv   = (const float*)d_in[3];
    const float* Wo     = (const float*)d_in[4];
    const float* bo     = (const float*)d_in[5];
    const float* gattn  = (const float*)d_in[6];
    const float* battn  = (const float*)d_in[7];
    const float* W1     = (const float*)d_in[8];
    const float* b1     = (const float*)d_in[9];
    const float* W2     = (const float*)d_in[10];
    const float* b2     = (const float*)d_in[11];
    const float* gmlp   = (const float*)d_in[12];
    const float* bmlp   = (const float*)d_in[13];
    const float* freqs  = (const float*)d_in[14];
    float* out = (float*)d_out;

    float *qkv, *attn, *proj, *hbuf, *u, *mbuf, *m2;
    cudaGetSymbolAddress((void**)&qkv,  g_qkv);
    cudaGetSymbolAddress((void**)&attn, g_attn);
    cudaGetSymbolAddress((void**)&proj, g_proj);
    cudaGetSymbolAddress((void**)&hbuf, g_hbuf);
    cudaGetSymbolAddress((void**)&u,    g_u);
    cudaGetSymbolAddress((void**)&mbuf, g_mbuf);
    cudaGetSymbolAddress((void**)&m2,   g_m2);

    cudaFuncSetAttribute(flash_attn_kernel,
                         cudaFuncAttributeMaxDynamicSharedMemorySize, FA_SMEM);

    // 1) QKV projection: [4096,1024] @ [3072,1024]^T -> [4096,3072]
    sgemm_nt_bias<<<dim3(D3 / 128, NTOK / 128), 256>>>(
        x, Wqkv, bqkv, qkv, NTOK, D3, DD);

    // 2) RoPE in place on q,k
    rope_kernel<<<(NTOK * 2 * HH * 32) / 256, 256>>>(qkv, p, freqs);

    // 3) Flash attention -> attn [4096,1024]
    flash_attn_kernel<<<dim3(SS / 64, HH, BB), 256, FA_SMEM>>>(qkv, attn);

    // 4) Output projection
    sgemm_nt_bias<<<dim3(DD / 128, NTOK / 128), 256>>>(
        attn, Wo, bo, proj, NTOK, DD, DD);

    // 5) h = LN(proj + x)
    add_ln_kernel<<<NTOK, 256>>>(proj, x, gattn, battn, hbuf);

    // 6) u = h @ W1^T + b1   [4096, 8192]
    sgemm_nt_bias<<<dim3(2 * FF / 128, NTOK / 128), 256>>>(
        hbuf, W1, b1, u, NTOK, 2 * FF, DD);

    // 7) m = gelu(a) * gate  [4096, 4096]
    gelu_gate_kernel<<<(NTOK * FF / 4) / 256, 256>>>(u, mbuf);

    // 8) m2 = m @ W2^T + b2  [4096, 1024]
    sgemm_nt_bias<<<dim3(DD / 128, NTOK / 128), 256>>>(
        mbuf, W2, b2, m2, NTOK, DD, FF);

    // 9) out = LN(m2 + h)
    add_ln_kernel<<<NTOK, 256>>>(m2, hbuf, gmlp, bmlp, out);
}

// round 2
// speedup vs baseline: 2.0543x; 2.0543x over previous
#include <cuda_runtime.h>
#include <math.h>
#include <stdint.h>

// Problem constants
#define BB   2
#define SS   2048
#define DD   1024
#define HH   16
#define DH   64
#define FF   4096
#define NTOK (BB*SS)          // 4096 rows
#define D3   (3*DD)           // 3072

// ---------------------------------------------------------------------------
// Scratch (static device globals — no runtime allocation allowed)
// ---------------------------------------------------------------------------
__device__ float g_qkv [NTOK * D3];
__device__ float g_attn[NTOK * DD];
__device__ float g_proj[NTOK * DD];
__device__ float g_hbuf[NTOK * DD];
__device__ float g_u   [NTOK * 2 * FF];
__device__ float g_mbuf[NTOK * FF];
__device__ float g_m2  [NTOK * DD];

// ---------------------------------------------------------------------------
// TF32 helpers
// ---------------------------------------------------------------------------
__device__ __forceinline__ float f2tf32(float x) {
    uint32_t u;
    asm("cvt.rna.tf32.f32 %0, %1;" : "=r"(u) : "f"(x));
    return __uint_as_float(u);
}

__device__ __forceinline__ void mma_tf32(
    float& d0, float& d1, float& d2, float& d3,
    uint32_t a0, uint32_t a1, uint32_t a2, uint32_t a3,
    uint32_t b0, uint32_t b1)
{
    asm volatile(
        "mma.sync.aligned.m16n8k8.row.col.f32.tf32.tf32.f32 "
        "{%0,%1,%2,%3}, {%4,%5,%6,%7}, {%8,%9}, {%0,%1,%2,%3};"
        : "+f"(d0), "+f"(d1), "+f"(d2), "+f"(d3)
        : "r"(a0), "r"(a1), "r"(a2), "r"(a3), "r"(b0), "r"(b1));
}

// ---------------------------------------------------------------------------
// TF32 tensor-core GEMM: C[m][n] = sum_k A[m][k]*W[n][k] + bias[n]
// A:[M,K] row-major fp32, W:[N,K] row-major fp32 (NT). M%128==0, N%128==0,
// K%16==0. CTA tile 128x128x16, 8 warps (2x4), warp tile 64x32.
// fp32 -> tf32 conversion happens once at the global->smem stage.
// ---------------------------------------------------------------------------
#define GPAD 20   // smem row stride (floats) — conflict-free fragment loads

__global__ void __launch_bounds__(256) gemm_tf32_nt_bias(
    const float* __restrict__ A, const float* __restrict__ W,
    const float* __restrict__ bias, float* __restrict__ C,
    int M, int N, int K)
{
    __shared__ float As[2][128 * GPAD];
    __shared__ float Ws[2][128 * GPAD];

    const int tid  = threadIdx.x;
    const int m0   = blockIdx.y * 128;
    const int n0   = blockIdx.x * 128;
    const int warp = tid >> 5;
    const int lane = tid & 31;
    const int wm   = (warp >> 2) * 64;   // warp row base within tile
    const int wn   = (warp & 3) * 32;    // warp col base within tile
    const int g    = lane >> 2;          // 0..7
    const int t    = lane & 3;           // 0..3

    // global load mapping: thread -> (row=tid>>2 [+64], kquad=(tid&3)*4)
    const int lrow = tid >> 2;           // 0..63
    const int lq   = (tid & 3) << 2;     // 0,4,8,12
    const float* Ag = A + (size_t)(m0 + lrow) * K + lq;
    const float* Wg = W + (size_t)(n0 + lrow) * K + lq;

    float acc[4][4][4];
#pragma unroll
    for (int i = 0; i < 4; i++)
#pragma unroll
        for (int j = 0; j < 4; j++)
#pragma unroll
            for (int r = 0; r < 4; r++) acc[i][j][r] = 0.f;

    const int NK = K >> 4;  // BK = 16

    // helper lambdas (inlined)
    auto stage = [&](int buf, float4 a0v, float4 a1v, float4 w0v, float4 w1v) {
        float4 c0 = make_float4(f2tf32(a0v.x), f2tf32(a0v.y), f2tf32(a0v.z), f2tf32(a0v.w));
        float4 c1 = make_float4(f2tf32(a1v.x), f2tf32(a1v.y), f2tf32(a1v.z), f2tf32(a1v.w));
        float4 c2 = make_float4(f2tf32(w0v.x), f2tf32(w0v.y), f2tf32(w0v.z), f2tf32(w0v.w));
        float4 c3 = make_float4(f2tf32(w1v.x), f2tf32(w1v.y), f2tf32(w1v.z), f2tf32(w1v.w));
        *(float4*)&As[buf][lrow        * GPAD + lq] = c0;
        *(float4*)&As[buf][(lrow + 64) * GPAD + lq] = c1;
        *(float4*)&Ws[buf][lrow        * GPAD + lq] = c2;
        *(float4*)&Ws[buf][(lrow + 64) * GPAD + lq] = c3;
    };

    // prologue: stage tile 0
    {
        float4 a0v = *(const float4*)(Ag);
        float4 a1v = *(const float4*)(Ag + (size_t)64 * K);
        float4 w0v = *(const float4*)(Wg);
        float4 w1v = *(const float4*)(Wg + (size_t)64 * K);
        stage(0, a0v, a1v, w0v, w1v);
    }
    __syncthreads();

    for (int kt = 0; kt < NK; kt++) {
        const int cur = kt & 1;

        float4 a0v, a1v, w0v, w1v;
        const bool more = (kt + 1) < NK;
        if (more) {
            const float* Ap = Ag + (size_t)(kt + 1) * 16;
            const float* Wp = Wg + (size_t)(kt + 1) * 16;
            a0v = *(const float4*)(Ap);
            a1v = *(const float4*)(Ap + (size_t)64 * K);
            w0v = *(const float4*)(Wp);
            w1v = *(const float4*)(Wp + (size_t)64 * K);
        }

        const uint32_t* Asb = (const uint32_t*)As[cur];
        const uint32_t* Wsb = (const uint32_t*)Ws[cur];

#pragma unroll
        for (int ks = 0; ks < 2; ks++) {
            const int kk = ks * 8;
            uint32_t af[4][4];
#pragma unroll
            for (int i = 0; i < 4; i++) {
                const int rb = wm + i * 16;
                af[i][0] = Asb[(rb + g    ) * GPAD + kk + t    ];
                af[i][1] = Asb[(rb + g + 8) * GPAD + kk + t    ];
                af[i][2] = Asb[(rb + g    ) * GPAD + kk + t + 4];
                af[i][3] = Asb[(rb + g + 8) * GPAD + kk + t + 4];
            }
#pragma unroll
            for (int j = 0; j < 4; j++) {
                const int cb = wn + j * 8 + g;
                uint32_t b0 = Wsb[cb * GPAD + kk + t    ];
                uint32_t b1 = Wsb[cb * GPAD + kk + t + 4];
#pragma unroll
                for (int i = 0; i < 4; i++)
                    mma_tf32(acc[i][j][0], acc[i][j][1], acc[i][j][2], acc[i][j][3],
                             af[i][0], af[i][1], af[i][2], af[i][3], b0, b1);
            }
        }

        if (more) {
            stage(1 - cur, a0v, a1v, w0v, w1v);
        }
        __syncthreads();
    }

    // epilogue: bias add, float2 stores (cols 2t, 2t+1 contiguous)
#pragma unroll
    for (int i = 0; i < 4; i++) {
        const int r0 = m0 + wm + i * 16 + g;
        const int r1 = r0 + 8;
#pragma unroll
        for (int j = 0; j < 4; j++) {
            const int col = n0 + wn + j * 8 + 2 * t;
            float2 bv = *(const float2*)&bias[col];
            float2 o0 = make_float2(acc[i][j][0] + bv.x, acc[i][j][1] + bv.y);
            float2 o1 = make_float2(acc[i][j][2] + bv.x, acc[i][j][3] + bv.y);
            *(float2*)&C[(size_t)r0 * N + col] = o0;
            *(float2*)&C[(size_t)r1 * N + col] = o1;
        }
    }
}

// ---------------------------------------------------------------------------
// RoPE, in-place on q and k slices of g_qkv.
// ---------------------------------------------------------------------------
__global__ void __launch_bounds__(256) rope_kernel(
    float* __restrict__ qkv, const int* __restrict__ p,
    const float* __restrict__ freqs)
{
    int gid = blockIdx.x * blockDim.x + threadIdx.x;
    int dh2  = gid & 31;
    int h    = (gid >> 5) & (HH - 1);
    int part = (gid >> 9) & 1;
    int row  = gid >> 10;
    if (row >= NTOK) return;

    float pos = (float)p[row];
    float a1 = pos * freqs[dh2];
    float a2 = pos * freqs[dh2 + 32];
    float c1, s1, c2, s2;
    sincosf(a1, &s1, &c1);
    sincosf(a2, &s2, &c2);

    float* base = qkv + (size_t)row * D3 + part * DD + h * DH + dh2;
    float x1 = base[0];
    float x2 = base[32];
    base[0]  = x1 * c1 + x2 * s1;
    base[32] = x2 * c2 + x1 * s2;
}

// ---------------------------------------------------------------------------
// Flash attention, fp32, 64x64 tiles, online softmax (unchanged from R1)
// ---------------------------------------------------------------------------
#define FA_STRIDE 68
#define FA_SMEM   (4 * 64 * FA_STRIDE * (int)sizeof(float))

__global__ void __launch_bounds__(256) flash_attn_kernel(
    const float* __restrict__ qkv, float* __restrict__ O)
{
    extern __shared__ float sm[];
    float* QsT = sm;
    float* KsT = sm + 1 * 64 * FA_STRIDE;
    float* Vs  = sm + 2 * 64 * FA_STRIDE;
    float* PsT = sm + 3 * 64 * FA_STRIDE;

    const int tid = threadIdx.x;
    const int ty = tid >> 4;
    const int tx = tid & 15;
    const int qt = blockIdx.x, h = blockIdx.y, b = blockIdx.z;
    const int rowBase = b * SS + qt * 64;
    const int cq = h * DH;

    for (int i = tid; i < 64 * 64; i += 256) {
        int r = i >> 6, c = i & 63;
        QsT[c * FA_STRIDE + r] =
            qkv[(size_t)(rowBase + r) * D3 + cq + c] * 0.125f;
    }

    float m_i[4], l_i[4], acc[4][4];
#pragma unroll
    for (int i = 0; i < 4; i++) {
        m_i[i] = -1e30f; l_i[i] = 0.f;
#pragma unroll
        for (int j = 0; j < 4; j++) acc[i][j] = 0.f;
    }
    __syncthreads();

    for (int kt = 0; kt < SS / 64; kt++) {
        const int kRow = b * SS + kt * 64;
        for (int i = tid; i < 64 * 64; i += 256) {
            int r = i >> 6, c = i & 63;
            const float* src = qkv + (size_t)(kRow + r) * D3 + cq + c;
            KsT[c * FA_STRIDE + r] = src[DD];
            Vs [r * FA_STRIDE + c] = src[2 * DD];
        }
        __syncthreads();

        float s[4][4];
#pragma unroll
        for (int i = 0; i < 4; i++)
#pragma unroll
            for (int j = 0; j < 4; j++) s[i][j] = 0.f;

        for (int d = 0; d < 64; d++) {
            float4 qv = *(const float4*)&QsT[d * FA_STRIDE + ty * 4];
            float4 kv = *(const float4*)&KsT[d * FA_STRIDE + tx * 4];
            float qa[4] = {qv.x, qv.y, qv.z, qv.w};
            float ka[4] = {kv.x, kv.y, kv.z, kv.w};
#pragma unroll
            for (int i = 0; i < 4; i++)
#pragma unroll
                for (int j = 0; j < 4; j++)
                    s[i][j] += qa[i] * ka[j];
        }

#pragma unroll
        for (int i = 0; i < 4; i++) {
            float tmax = fmaxf(fmaxf(s[i][0], s[i][1]), fmaxf(s[i][2], s[i][3]));
#pragma unroll
            for (int o = 8; o; o >>= 1)
                tmax = fmaxf(tmax, __shfl_xor_sync(0xffffffffu, tmax, o));
            float mnew = fmaxf(m_i[i], tmax);
            float corr = __expf(m_i[i] - mnew);
            float tsum = 0.f;
#pragma unroll
            for (int j = 0; j < 4; j++) {
                s[i][j] = __expf(s[i][j] - mnew);
                tsum += s[i][j];
            }
#pragma unroll
            for (int o = 8; o; o >>= 1)
                tsum += __shfl_xor_sync(0xffffffffu, tsum, o);
            l_i[i] = l_i[i] * corr + tsum;
            m_i[i] = mnew;
#pragma unroll
            for (int j = 0; j < 4; j++) acc[i][j] *= corr;
#pragma unroll
            for (int j = 0; j < 4; j++)
                PsT[(tx * 4 + j) * FA_STRIDE + ty * 4 + i] = s[i][j];
        }
        __syncthreads();

        for (int j = 0; j < 64; j++) {
            float4 pv = *(const float4*)&PsT[j * FA_STRIDE + ty * 4];
            float4 vv = *(const float4*)&Vs [j * FA_STRIDE + tx * 4];
            float pa[4] = {pv.x, pv.y, pv.z, pv.w};
            float va[4] = {vv.x, vv.y, vv.z, vv.w};
#pragma unroll
            for (int i = 0; i < 4; i++)
#pragma unroll
                for (int dd = 0; dd < 4; dd++)
                    acc[i][dd] += pa[i] * va[dd];
        }
        __syncthreads();
    }

#pragma unroll
    for (int i = 0; i < 4; i++) {
        float inv = 1.0f / l_i[i];
        float4 o4 = make_float4(acc[i][0] * inv, acc[i][1] * inv,
                                acc[i][2] * inv, acc[i][3] * inv);
        *(float4*)&O[(size_t)(rowBase + ty * 4 + i) * DD + cq + tx * 4] = o4;
    }
}

// ---------------------------------------------------------------------------
// Fused residual add + LayerNorm
// ---------------------------------------------------------------------------
__global__ void __launch_bounds__(256) add_ln_kernel(
    const float* __restrict__ A, const float* __restrict__ R,
    const float* __restrict__ g, const float* __restrict__ be,
    float* __restrict__ out)
{
    __shared__ float red[8];
    const int row = blockIdx.x, tid = threadIdx.x;
    const int lane = tid & 31, wid = tid >> 5;

    float4 a = ((const float4*)(A + (size_t)row * DD))[tid];
    float4 r = ((const float4*)(R + (size_t)row * DD))[tid];
    float4 t = make_float4(a.x + r.x, a.y + r.y, a.z + r.z, a.w + r.w);

    float ssum = t.x + t.y + t.z + t.w;
#pragma unroll
    for (int o = 16; o; o >>= 1) ssum += __shfl_xor_sync(0xffffffffu, ssum, o);
    if (lane == 0) red[wid] = ssum;
    __syncthreads();
    float mean = (red[0] + red[1] + red[2] + red[3] +
                  red[4] + red[5] + red[6] + red[7]) * (1.0f / DD);
    __syncthreads();

    float4 d = make_float4(t.x - mean, t.y - mean, t.z - mean, t.w - mean);
    float sq = d.x * d.x + d.y * d.y + d.z * d.z + d.w * d.w;
#pragma unroll
    for (int o = 16; o; o >>= 1) sq += __shfl_xor_sync(0xffffffffu, sq, o);
    if (lane == 0) red[wid] = sq;
    __syncthreads();
    float var = (red[0] + red[1] + red[2] + red[3] +
                 red[4] + red[5] + red[6] + red[7]) * (1.0f / DD);
    float rs = rsqrtf(var + 1e-5f);

    float4 gv = ((const float4*)g)[tid];
    float4 bv = ((const float4*)be)[tid];
    float4 o4 = make_float4(d.x * rs * gv.x + bv.x,
                            d.y * rs * gv.y + bv.y,
                            d.z * rs * gv.z + bv.z,
                            d.w * rs * gv.w + bv.w);
    ((float4*)(out + (size_t)row * DD))[tid] = o4;
}

// ---------------------------------------------------------------------------
// GELU(exact) * gate
// ---------------------------------------------------------------------------
__global__ void __launch_bounds__(256) gelu_gate_kernel(
    const float* __restrict__ u, float* __restrict__ m)
{
    int gid = blockIdx.x * blockDim.x + threadIdx.x;
    const int f4_per_row = FF / 4;
    int row  = gid / f4_per_row;
    int col4 = gid - row * f4_per_row;
    if (row >= NTOK) return;

    const float4* U4 = (const float4*)(u + (size_t)row * 2 * FF);
    float4 a = U4[col4];
    float4 gt = U4[f4_per_row + col4];

    const float inv_sqrt2 = 0.70710678118654752f;
    float4 o;
    o.x = 0.5f * a.x * (1.0f + erff(a.x * inv_sqrt2)) * gt.x;
    o.y = 0.5f * a.y * (1.0f + erff(a.y * inv_sqrt2)) * gt.y;
    o.z = 0.5f * a.z * (1.0f + erff(a.z * inv_sqrt2)) * gt.z;
    o.w = 0.5f * a.w * (1.0f + erff(a.w * inv_sqrt2)) * gt.w;
    ((float4*)(m + (size_t)row * FF))[col4] = o;
}

// ---------------------------------------------------------------------------
// kernel_launch
// ---------------------------------------------------------------------------
extern "C" void kernel_launch(void* const* d_in, const int* in_sizes, int n_in,
                              void* d_out, int out_size)
{
    const float* x      = (const float*)d_in[0];
    const int*   p      = (const int*)  d_in[1];
    const float* Wqkv   = (const float*)d_in[2];
    const float* bqkv   = (const float*)d_in[3];
    const float* Wo     = (const float*)d_in[4];
    const float* bo     = (const float*)d_in[5];
    const float* gattn  = (const float*)d_in[6];
    const float* battn  = (const float*)d_in[7];
    const float* W1     = (const float*)d_in[8];
    const float* b1     = (const float*)d_in[9];
    const float* W2     = (const float*)d_in[10];
    const float* b2     = (const float*)d_in[11];
    const float* gmlp   = (const float*)d_in[12];
    const float* bmlp   = (const float*)d_in[13];
    const float* freqs  = (const float*)d_in[14];
    float* out = (float*)d_out;

    float *qkv, *attn, *proj, *hbuf, *u, *mbuf, *m2;
    cudaGetSymbolAddress((void**)&qkv,  g_qkv);
    cudaGetSymbolAddress((void**)&attn, g_attn);
    cudaGetSymbolAddress((void**)&proj, g_proj);
    cudaGetSymbolAddress((void**)&hbuf, g_hbuf);
    cudaGetSymbolAddress((void**)&u,    g_u);
    cudaGetSymbolAddress((void**)&mbuf, g_mbuf);
    cudaGetSymbolAddress((void**)&m2,   g_m2);

    cudaFuncSetAttribute(flash_attn_kernel,
                         cudaFuncAttributeMaxDynamicSharedMemorySize, FA_SMEM);

    // 1) QKV projection
    gemm_tf32_nt_bias<<<dim3(D3 / 128, NTOK / 128), 256>>>(
        x, Wqkv, bqkv, qkv, NTOK, D3, DD);

    // 2) RoPE
    rope_kernel<<<(NTOK * 2 * HH * 32) / 256, 256>>>(qkv, p, freqs);

    // 3) Flash attention
    flash_attn_kernel<<<dim3(SS / 64, HH, BB), 256, FA_SMEM>>>(qkv, attn);

    // 4) Output projection
    gemm_tf32_nt_bias<<<dim3(DD / 128, NTOK / 128), 256>>>(
        attn, Wo, bo, proj, NTOK, DD, DD);

    // 5) h = LN(proj + x)
    add_ln_kernel<<<NTOK, 256>>>(proj, x, gattn, battn, hbuf);

    // 6) u = h @ W1^T + b1
    gemm_tf32_nt_bias<<<dim3(2 * FF / 128, NTOK / 128), 256>>>(
        hbuf, W1, b1, u, NTOK, 2 * FF, DD);

    // 7) m = gelu(a) * gate
    gelu_gate_kernel<<<(NTOK * FF / 4) / 256, 256>>>(u, mbuf);

    // 8) m2 = m @ W2^T + b2
    gemm_tf32_nt_bias<<<dim3(DD / 128, NTOK / 128), 256>>>(
        mbuf, W2, b2, m2, NTOK, DD, FF);

    // 9) out = LN(m2 + h)
    add_ln_kernel<<<NTOK, 256>>>(m2, hbuf, gmlp, bmlp, out);
}

// round 3
// speedup vs baseline: 3.0050x; 1.4628x over previous
#include <cuda_runtime.h>
#include <math.h>
#include <stdint.h>

// Problem constants
#define BB   2
#define SS   2048
#define DD   1024
#define HH   16
#define DH   64
#define FF   4096
#define NTOK (BB*SS)          // 4096 rows
#define D3   (3*DD)           // 3072

// ---------------------------------------------------------------------------
// Scratch (static device globals — no runtime allocation allowed)
// ---------------------------------------------------------------------------
__device__ float g_qkv [NTOK * D3];
__device__ float g_attn[NTOK * DD];
__device__ float g_proj[NTOK * DD];
__device__ float g_hbuf[NTOK * DD];
__device__ float g_u   [NTOK * 2 * FF];
__device__ float g_mbuf[NTOK * FF];
__device__ float g_m2  [NTOK * DD];

// ---------------------------------------------------------------------------
// TF32 / MMA / cp.async helpers
// ---------------------------------------------------------------------------
__device__ __forceinline__ float f2tf32(float x) {
    uint32_t u;
    asm("cvt.rna.tf32.f32 %0, %1;" : "=r"(u) : "f"(x));
    return __uint_as_float(u);
}

__device__ __forceinline__ void mma_tf32(
    float& d0, float& d1, float& d2, float& d3,
    uint32_t a0, uint32_t a1, uint32_t a2, uint32_t a3,
    uint32_t b0, uint32_t b1)
{
    asm volatile(
        "mma.sync.aligned.m16n8k8.row.col.f32.tf32.tf32.f32 "
        "{%0,%1,%2,%3}, {%4,%5,%6,%7}, {%8,%9}, {%0,%1,%2,%3};"
        : "+f"(d0), "+f"(d1), "+f"(d2), "+f"(d3)
        : "r"(a0), "r"(a1), "r"(a2), "r"(a3), "r"(b0), "r"(b1));
}

__device__ __forceinline__ uint32_t smem_u32(const void* p) {
    uint32_t a;
    asm("{ .reg .u64 t; cvta.to.shared.u64 t, %1; cvt.u32.u64 %0, t; }"
        : "=r"(a) : "l"(p));
    return a;
}

__device__ __forceinline__ void cp_async16(uint32_t s, const void* g) {
    asm volatile("cp.async.cg.shared.global [%0], [%1], 16;\n"
                 :: "r"(s), "l"(g));
}
__device__ __forceinline__ void cp_commit() {
    asm volatile("cp.async.commit_group;\n");
}

// ---------------------------------------------------------------------------
// TF32 tensor-core GEMM (unchanged from R2): C = A @ W^T + bias
// ---------------------------------------------------------------------------
#define GPAD 20

__global__ void __launch_bounds__(256) gemm_tf32_nt_bias(
    const float* __restrict__ A, const float* __restrict__ W,
    const float* __restrict__ bias, float* __restrict__ C,
    int M, int N, int K)
{
    __shared__ float As[2][128 * GPAD];
    __shared__ float Ws[2][128 * GPAD];

    const int tid  = threadIdx.x;
    const int m0   = blockIdx.y * 128;
    const int n0   = blockIdx.x * 128;
    const int warp = tid >> 5;
    const int lane = tid & 31;
    const int wm   = (warp >> 2) * 64;
    const int wn   = (warp & 3) * 32;
    const int g    = lane >> 2;
    const int t    = lane & 3;

    const int lrow = tid >> 2;
    const int lq   = (tid & 3) << 2;
    const float* Ag = A + (size_t)(m0 + lrow) * K + lq;
    const float* Wg = W + (size_t)(n0 + lrow) * K + lq;

    float acc[4][4][4];
#pragma unroll
    for (int i = 0; i < 4; i++)
#pragma unroll
        for (int j = 0; j < 4; j++)
#pragma unroll
            for (int r = 0; r < 4; r++) acc[i][j][r] = 0.f;

    const int NK = K >> 4;

    auto stage = [&](int buf, float4 a0v, float4 a1v, float4 w0v, float4 w1v) {
        float4 c0 = make_float4(f2tf32(a0v.x), f2tf32(a0v.y), f2tf32(a0v.z), f2tf32(a0v.w));
        float4 c1 = make_float4(f2tf32(a1v.x), f2tf32(a1v.y), f2tf32(a1v.z), f2tf32(a1v.w));
        float4 c2 = make_float4(f2tf32(w0v.x), f2tf32(w0v.y), f2tf32(w0v.z), f2tf32(w0v.w));
        float4 c3 = make_float4(f2tf32(w1v.x), f2tf32(w1v.y), f2tf32(w1v.z), f2tf32(w1v.w));
        *(float4*)&As[buf][lrow        * GPAD + lq] = c0;
        *(float4*)&As[buf][(lrow + 64) * GPAD + lq] = c1;
        *(float4*)&Ws[buf][lrow        * GPAD + lq] = c2;
        *(float4*)&Ws[buf][(lrow + 64) * GPAD + lq] = c3;
    };

    {
        float4 a0v = *(const float4*)(Ag);
        float4 a1v = *(const float4*)(Ag + (size_t)64 * K);
        float4 w0v = *(const float4*)(Wg);
        float4 w1v = *(const float4*)(Wg + (size_t)64 * K);
        stage(0, a0v, a1v, w0v, w1v);
    }
    __syncthreads();

    for (int kt = 0; kt < NK; kt++) {
        const int cur = kt & 1;

        float4 a0v, a1v, w0v, w1v;
        const bool more = (kt + 1) < NK;
        if (more) {
            const float* Ap = Ag + (size_t)(kt + 1) * 16;
            const float* Wp = Wg + (size_t)(kt + 1) * 16;
            a0v = *(const float4*)(Ap);
            a1v = *(const float4*)(Ap + (size_t)64 * K);
            w0v = *(const float4*)(Wp);
            w1v = *(const float4*)(Wp + (size_t)64 * K);
        }

        const uint32_t* Asb = (const uint32_t*)As[cur];
        const uint32_t* Wsb = (const uint32_t*)Ws[cur];

#pragma unroll
        for (int ks = 0; ks < 2; ks++) {
            const int kk = ks * 8;
            uint32_t af[4][4];
#pragma unroll
            for (int i = 0; i < 4; i++) {
                const int rb = wm + i * 16;
                af[i][0] = Asb[(rb + g    ) * GPAD + kk + t    ];
                af[i][1] = Asb[(rb + g + 8) * GPAD + kk + t    ];
                af[i][2] = Asb[(rb + g    ) * GPAD + kk + t + 4];
                af[i][3] = Asb[(rb + g + 8) * GPAD + kk + t + 4];
            }
#pragma unroll
            for (int j = 0; j < 4; j++) {
                const int cb = wn + j * 8 + g;
                uint32_t b0 = Wsb[cb * GPAD + kk + t    ];
                uint32_t b1 = Wsb[cb * GPAD + kk + t + 4];
#pragma unroll
                for (int i = 0; i < 4; i++)
                    mma_tf32(acc[i][j][0], acc[i][j][1], acc[i][j][2], acc[i][j][3],
                             af[i][0], af[i][1], af[i][2], af[i][3], b0, b1);
            }
        }

        if (more) stage(1 - cur, a0v, a1v, w0v, w1v);
        __syncthreads();
    }

#pragma unroll
    for (int i = 0; i < 4; i++) {
        const int r0 = m0 + wm + i * 16 + g;
        const int r1 = r0 + 8;
#pragma unroll
        for (int j = 0; j < 4; j++) {
            const int col = n0 + wn + j * 8 + 2 * t;
            float2 bv = *(const float2*)&bias[col];
            float2 o0 = make_float2(acc[i][j][0] + bv.x, acc[i][j][1] + bv.y);
            float2 o1 = make_float2(acc[i][j][2] + bv.x, acc[i][j][3] + bv.y);
            *(float2*)&C[(size_t)r0 * N + col] = o0;
            *(float2*)&C[(size_t)r1 * N + col] = o1;
        }
    }
}

// ---------------------------------------------------------------------------
// RoPE + TF32 pre-rounding of the entire qkv buffer (in place).
// q-part additionally scaled by DH^-0.5 (attention score scale).
// One thread = one float4. RoPE pairs (dh, dh+32) never cross a float4.
// ---------------------------------------------------------------------------
__global__ void __launch_bounds__(256) rope_tf32_kernel(
    float* __restrict__ qkv, const int* __restrict__ p,
    const float* __restrict__ freqs)
{
    const int idx4 = blockIdx.x * blockDim.x + threadIdx.x;
    const int per_row = D3 / 4;                  // 768
    const int row = idx4 / per_row;
    const int c   = (idx4 - row * per_row) * 4;  // float col
    if (row >= NTOK) return;

    float* base = qkv + (size_t)row * D3 + c;
    float4 v = *(float4*)base;

    if (c < 2 * DD) {                            // q or k: apply RoPE
        const float pos = (float)p[row];
        const int dh = c & 63;
        const int off = (dh < 32) ? 32 : -32;
        float4 o = *(const float4*)(base + off);
        float vv[4] = {v.x, v.y, v.z, v.w};
        float oo[4] = {o.x, o.y, o.z, o.w};
#pragma unroll
        for (int j = 0; j < 4; j++) {
            float a = pos * freqs[dh + j];
            float sn, cs;
            __sincosf(a, &sn, &cs);
            vv[j] = vv[j] * cs + oo[j] * sn;
        }
        v = make_float4(vv[0], vv[1], vv[2], vv[3]);
    }
    if (c < DD) {                                // q: fold in score scale
        v.x *= 0.125f; v.y *= 0.125f; v.z *= 0.125f; v.w *= 0.125f;
    }
    v = make_float4(f2tf32(v.x), f2tf32(v.y), f2tf32(v.z), f2tf32(v.w));
    *(float4*)base = v;
}

// ---------------------------------------------------------------------------
// Flash attention with TF32 tensor cores.
// Block: 64 q-rows x 1 head. 4 warps, each owns 16 q-rows.
// Key tiles of 64, cp.async double-buffered K/V.
// smem strides: Q/K/P = 68, V = 72 (conflict-free fragment LDS).
// ---------------------------------------------------------------------------
#define QS_OFF  0
#define KS_OFF  (64*68)                 // 4352
#define KS_SZ   (64*68)
#define VS_OFF  (KS_OFF + 2*KS_SZ)      // 13056
#define VS_SZ   (64*72)
#define PS_OFF  (VS_OFF + 2*VS_SZ)      // 22272
#define PS_SZ   (16*68)
#define FA2_SMEM ((PS_OFF + 4*PS_SZ) * (int)sizeof(float))  // 106496 B

__global__ void __launch_bounds__(128) flash_attn_tc_kernel(
    const float* __restrict__ qkv, float* __restrict__ O)
{
    extern __shared__ float sm[];
    const int tid  = threadIdx.x;
    const int warp = tid >> 5;
    const int lane = tid & 31;
    const int g = lane >> 2;
    const int t = lane & 3;
    const int wq = warp * 16;            // warp's q-row base in tile

    const int qt = blockIdx.x, h = blockIdx.y, b = blockIdx.z;
    const int rowBase = b * SS + qt * 64;
    const int cq = h * DH;
    const int bS = b * SS;

    float* Qs = sm + QS_OFF;
    float* Psw = sm + PS_OFF + warp * PS_SZ;
    const uint32_t smb = smem_u32(sm);

    // Load Q tile (already tf32-rounded & scaled): row-major [64][68]
    for (int i = tid; i < 64 * 16; i += 128) {
        int r = i >> 4, q4 = (i & 15) << 2;
        float4 v = *(const float4*)&qkv[(size_t)(rowBase + r) * D3 + cq + q4];
        *(float4*)&Qs[r * 68 + q4] = v;
    }

    // cp.async stage of one K/V tile into buffer `buf`
    auto issue_tile = [&](int kt, int buf) {
        const float* gK = qkv + (size_t)(bS + kt * 64) * D3 + cq + DD;
        const uint32_t sK = smb + (KS_OFF + buf * KS_SZ) * 4;
        const uint32_t sV = smb + (VS_OFF + buf * VS_SZ) * 4;
#pragma unroll
        for (int it = 0; it < 8; it++) {
            int i = tid + it * 128;          // 0..1023
            int r = i >> 4, q4 = (i & 15) << 2;
            const float* gp = gK + (size_t)r * D3 + q4;
            cp_async16(sK + (r * 68 + q4) * 4, gp);
            cp_async16(sV + (r * 72 + q4) * 4, gp + DD);
        }
        cp_commit();
    };

    issue_tile(0, 0);

    float m_i[2] = {-1e30f, -1e30f};
    float l_i[2] = {0.f, 0.f};
    float acc[8][4];
#pragma unroll
    for (int d = 0; d < 8; d++)
#pragma unroll
        for (int r = 0; r < 4; r++) acc[d][r] = 0.f;

    const int NT = SS / 64;   // 32
    for (int kt = 0; kt < NT; kt++) {
        const int cur = kt & 1;
        if (kt + 1 < NT) {
            issue_tile(kt + 1, 1 - cur);
            asm volatile("cp.async.wait_group 1;\n");
        } else {
            asm volatile("cp.async.wait_group 0;\n");
        }
        __syncthreads();

        const float* Ks = sm + KS_OFF + cur * KS_SZ;
        const float* Vs = sm + VS_OFF + cur * VS_SZ;

        // ---- S = Q K^T (16 x 64 per warp) ----
        float s[8][4];
#pragma unroll
        for (int n = 0; n < 8; n++)
#pragma unroll
            for (int r = 0; r < 4; r++) s[n][r] = 0.f;

#pragma unroll
        for (int kk8 = 0; kk8 < 8; kk8++) {
            const int kk = kk8 * 8;
            uint32_t a0 = __float_as_uint(Qs[(wq + g    ) * 68 + kk + t    ]);
            uint32_t a1 = __float_as_uint(Qs[(wq + g + 8) * 68 + kk + t    ]);
            uint32_t a2 = __float_as_uint(Qs[(wq + g    ) * 68 + kk + t + 4]);
            uint32_t a3 = __float_as_uint(Qs[(wq + g + 8) * 68 + kk + t + 4]);
#pragma unroll
            for (int n = 0; n < 8; n++) {
                uint32_t b0 = __float_as_uint(Ks[(n * 8 + g) * 68 + kk + t    ]);
                uint32_t b1 = __float_as_uint(Ks[(n * 8 + g) * 68 + kk + t + 4]);
                mma_tf32(s[n][0], s[n][1], s[n][2], s[n][3],
                         a0, a1, a2, a3, b0, b1);
            }
        }

        // ---- online softmax; rows r0 = wq+g, r1 = wq+g+8 ----
        float mx0 = -1e30f, mx1 = -1e30f;
#pragma unroll
        for (int n = 0; n < 8; n++) {
            mx0 = fmaxf(mx0, fmaxf(s[n][0], s[n][1]));
            mx1 = fmaxf(mx1, fmaxf(s[n][2], s[n][3]));
        }
        mx0 = fmaxf(mx0, __shfl_xor_sync(0xffffffffu, mx0, 1));
        mx0 = fmaxf(mx0, __shfl_xor_sync(0xffffffffu, mx0, 2));
        mx1 = fmaxf(mx1, __shfl_xor_sync(0xffffffffu, mx1, 1));
        mx1 = fmaxf(mx1, __shfl_xor_sync(0xffffffffu, mx1, 2));

        float mn0 = fmaxf(m_i[0], mx0);
        float mn1 = fmaxf(m_i[1], mx1);
        float cr0 = __expf(m_i[0] - mn0);
        float cr1 = __expf(m_i[1] - mn1);

        float sum0 = 0.f, sum1 = 0.f;
#pragma unroll
        for (int n = 0; n < 8; n++) {
            s[n][0] = __expf(s[n][0] - mn0);
            s[n][1] = __expf(s[n][1] - mn0);
            s[n][2] = __expf(s[n][2] - mn1);
            s[n][3] = __expf(s[n][3] - mn1);
            sum0 += s[n][0] + s[n][1];
            sum1 += s[n][2] + s[n][3];
        }
        sum0 += __shfl_xor_sync(0xffffffffu, sum0, 1);
        sum0 += __shfl_xor_sync(0xffffffffu, sum0, 2);
        sum1 += __shfl_xor_sync(0xffffffffu, sum1, 1);
        sum1 += __shfl_xor_sync(0xffffffffu, sum1, 2);

        l_i[0] = l_i[0] * cr0 + sum0;
        l_i[1] = l_i[1] * cr1 + sum1;
        m_i[0] = mn0; m_i[1] = mn1;

#pragma unroll
        for (int d = 0; d < 8; d++) {
            acc[d][0] *= cr0; acc[d][1] *= cr0;
            acc[d][2] *= cr1; acc[d][3] *= cr1;
        }

        // ---- store P (tf32) to per-warp smem, reshape C-layout -> A-layout
#pragma unroll
        for (int n = 0; n < 8; n++) {
            Psw[ g      * 68 + n * 8 + 2 * t    ] = f2tf32(s[n][0]);
            Psw[ g      * 68 + n * 8 + 2 * t + 1] = f2tf32(s[n][1]);
            Psw[(g + 8) * 68 + n * 8 + 2 * t    ] = f2tf32(s[n][2]);
            Psw[(g + 8) * 68 + n * 8 + 2 * t + 1] = f2tf32(s[n][3]);
        }
        __syncwarp();

        // ---- acc += P @ V ----
#pragma unroll
        for (int kk8 = 0; kk8 < 8; kk8++) {
            const int kk = kk8 * 8;
            uint32_t a0 = __float_as_uint(Psw[ g      * 68 + kk + t    ]);
            uint32_t a1 = __float_as_uint(Psw[(g + 8) * 68 + kk + t    ]);
            uint32_t a2 = __float_as_uint(Psw[ g      * 68 + kk + t + 4]);
            uint32_t a3 = __float_as_uint(Psw[(g + 8) * 68 + kk + t + 4]);
#pragma unroll
            for (int d = 0; d < 8; d++) {
                uint32_t b0 = __float_as_uint(Vs[(kk + t    ) * 72 + d * 8 + g]);
                uint32_t b1 = __float_as_uint(Vs[(kk + t + 4) * 72 + d * 8 + g]);
                mma_tf32(acc[d][0], acc[d][1], acc[d][2], acc[d][3],
                         a0, a1, a2, a3, b0, b1);
            }
        }
        __syncthreads();   // done with `cur` buffers before they're refilled
    }

    // ---- write O ----
    const float inv0 = 1.0f / l_i[0];
    const float inv1 = 1.0f / l_i[1];
    const int r0 = rowBase + wq + g;
    const int r1 = r0 + 8;
#pragma unroll
    for (int d = 0; d < 8; d++) {
        const int col = cq + d * 8 + 2 * t;
        *(float2*)&O[(size_t)r0 * DD + col] =
            make_float2(acc[d][0] * inv0, acc[d][1] * inv0);
        *(float2*)&O[(size_t)r1 * DD + col] =
            make_float2(acc[d][2] * inv1, acc[d][3] * inv1);
    }
}

// ---------------------------------------------------------------------------
// Fused residual add + LayerNorm
// ---------------------------------------------------------------------------
__global__ void __launch_bounds__(256) add_ln_kernel(
    const float* __restrict__ A, const float* __restrict__ R,
    const float* __restrict__ g, const float* __restrict__ be,
    float* __restrict__ out)
{
    __shared__ float red[8];
    const int row = blockIdx.x, tid = threadIdx.x;
    const int lane = tid & 31, wid = tid >> 5;

    float4 a = ((const float4*)(A + (size_t)row * DD))[tid];
    float4 r = ((const float4*)(R + (size_t)row * DD))[tid];
    float4 t = make_float4(a.x + r.x, a.y + r.y, a.z + r.z, a.w + r.w);

    float ssum = t.x + t.y + t.z + t.w;
#pragma unroll
    for (int o = 16; o; o >>= 1) ssum += __shfl_xor_sync(0xffffffffu, ssum, o);
    if (lane == 0) red[wid] = ssum;
    __syncthreads();
    float mean = (red[0] + red[1] + red[2] + red[3] +
                  red[4] + red[5] + red[6] + red[7]) * (1.0f / DD);
    __syncthreads();

    float4 d = make_float4(t.x - mean, t.y - mean, t.z - mean, t.w - mean);
    float sq = d.x * d.x + d.y * d.y + d.z * d.z + d.w * d.w;
#pragma unroll
    for (int o = 16; o; o >>= 1) sq += __shfl_xor_sync(0xffffffffu, sq, o);
    if (lane == 0) red[wid] = sq;
    __syncthreads();
    float var = (red[0] + red[1] + red[2] + red[3] +
                 red[4] + red[5] + red[6] + red[7]) * (1.0f / DD);
    float rs = rsqrtf(var + 1e-5f);

    float4 gv = ((const float4*)g)[tid];
    float4 bv = ((const float4*)be)[tid];
    float4 o4 = make_float4(d.x * rs * gv.x + bv.x,
                            d.y * rs * gv.y + bv.y,
                            d.z * rs * gv.z + bv.z,
                            d.w * rs * gv.w + bv.w);
    ((float4*)(out + (size_t)row * DD))[tid] = o4;
}

// ---------------------------------------------------------------------------
// GELU(exact) * gate
// ---------------------------------------------------------------------------
__global__ void __launch_bounds__(256) gelu_gate_kernel(
    const float* __restrict__ u, float* __restrict__ m)
{
    int gid = blockIdx.x * blockDim.x + threadIdx.x;
    const int f4_per_row = FF / 4;
    int row  = gid / f4_per_row;
    int col4 = gid - row * f4_per_row;
    if (row >= NTOK) return;

    const float4* U4 = (const float4*)(u + (size_t)row * 2 * FF);
    float4 a = U4[col4];
    float4 gt = U4[f4_per_row + col4];

    const float inv_sqrt2 = 0.70710678118654752f;
    float4 o;
    o.x = 0.5f * a.x * (1.0f + erff(a.x * inv_sqrt2)) * gt.x;
    o.y = 0.5f * a.y * (1.0f + erff(a.y * inv_sqrt2)) * gt.y;
    o.z = 0.5f * a.z * (1.0f + erff(a.z * inv_sqrt2)) * gt.z;
    o.w = 0.5f * a.w * (1.0f + erff(a.w * inv_sqrt2)) * gt.w;
    ((float4*)(m + (size_t)row * FF))[col4] = o;
}

// ---------------------------------------------------------------------------
// kernel_launch
// ---------------------------------------------------------------------------
extern "C" void kernel_launch(void* const* d_in, const int* in_sizes, int n_in,
                              void* d_out, int out_size)
{
    const float* x      = (const float*)d_in[0];
    const int*   p      = (const int*)  d_in[1];
    const float* Wqkv   = (const float*)d_in[2];
    const float* bqkv   = (const float*)d_in[3];
    const float* Wo     = (const float*)d_in[4];
    const float* bo     = (const float*)d_in[5];
    const float* gattn  = (const float*)d_in[6];
    const float* battn  = (const float*)d_in[7];
    const float* W1     = (const float*)d_in[8];
    const float* b1     = (const float*)d_in[9];
    const float* W2     = (const float*)d_in[10];
    const float* b2     = (const float*)d_in[11];
    const float* gmlp   = (const float*)d_in[12];
    const float* bmlp   = (const float*)d_in[13];
    const float* freqs  = (const float*)d_in[14];
    float* out = (float*)d_out;

    float *qkv, *attn, *proj, *hbuf, *u, *mbuf, *m2;
    cudaGetSymbolAddress((void**)&qkv,  g_qkv);
    cudaGetSymbolAddress((void**)&attn, g_attn);
    cudaGetSymbolAddress((void**)&proj, g_proj);
    cudaGetSymbolAddress((void**)&hbuf, g_hbuf);
    cudaGetSymbolAddress((void**)&u,    g_u);
    cudaGetSymbolAddress((void**)&mbuf, g_mbuf);
    cudaGetSymbolAddress((void**)&m2,   g_m2);

    cudaFuncSetAttribute(flash_attn_tc_kernel,
                         cudaFuncAttributeMaxDynamicSharedMemorySize, FA2_SMEM);

    // 1) QKV projection
    gemm_tf32_nt_bias<<<dim3(D3 / 128, NTOK / 128), 256>>>(
        x, Wqkv, bqkv, qkv, NTOK, D3, DD);

    // 2) RoPE + tf32 rounding of q,k,v (q also pre-scaled)
    rope_tf32_kernel<<<(NTOK * D3 / 4) / 256, 256>>>(qkv, p, freqs);

    // 3) Flash attention (tensor cores)
    flash_attn_tc_kernel<<<dim3(SS / 64, HH, BB), 128, FA2_SMEM>>>(qkv, attn);

    // 4) Output projection
    gemm_tf32_nt_bias<<<dim3(DD / 128, NTOK / 128), 256>>>(
        attn, Wo, bo, proj, NTOK, DD, DD);

    // 5) h = LN(proj + x)
    add_ln_kernel<<<NTOK, 256>>>(proj, x, gattn, battn, hbuf);

    // 6) u = h @ W1^T + b1
    gemm_tf32_nt_bias<<<dim3(2 * FF / 128, NTOK / 128), 256>>>(
        hbuf, W1, b1, u, NTOK, 2 * FF, DD);

    // 7) m = gelu(a) * gate
    gelu_gate_kernel<<<(NTOK * FF / 4) / 256, 256>>>(u, mbuf);

    // 8) m2 = m @ W2^T + b2
    gemm_tf32_nt_bias<<<dim3(DD / 128, NTOK / 128), 256>>>(
        mbuf, W2, b2, m2, NTOK, DD, FF);

    // 9) out = LN(m2 + h)
    add_ln_kernel<<<NTOK, 256>>>(m2, hbuf, gmlp, bmlp, out);
}

// round 4
// speedup vs baseline: 3.1188x; 1.0379x over previous
#include <cuda_runtime.h>
#include <math.h>
#include <stdint.h>

// Problem constants
#define BB   2
#define SS   2048
#define DD   1024
#define HH   16
#define DH   64
#define FF   4096
#define NTOK (BB*SS)          // 4096 rows
#define D3   (3*DD)           // 3072

// ---------------------------------------------------------------------------
// Scratch (static device globals — no runtime allocation allowed)
// ---------------------------------------------------------------------------
__device__ float g_qkv [NTOK * D3];
__device__ float g_attn[NTOK * DD];
__device__ float g_proj[NTOK * DD];
__device__ float g_hbuf[NTOK * DD];
__device__ float g_u   [NTOK * 2 * FF];
__device__ float g_mbuf[NTOK * FF];
__device__ float g_m2  [NTOK * DD];

// ---------------------------------------------------------------------------
// TF32 / MMA / cp.async helpers
// ---------------------------------------------------------------------------
__device__ __forceinline__ float f2tf32(float x) {
    uint32_t u;
    asm("cvt.rna.tf32.f32 %0, %1;" : "=r"(u) : "f"(x));
    return __uint_as_float(u);
}

__device__ __forceinline__ void mma_tf32(
    float& d0, float& d1, float& d2, float& d3,
    uint32_t a0, uint32_t a1, uint32_t a2, uint32_t a3,
    uint32_t b0, uint32_t b1)
{
    asm volatile(
        "mma.sync.aligned.m16n8k8.row.col.f32.tf32.tf32.f32 "
        "{%0,%1,%2,%3}, {%4,%5,%6,%7}, {%8,%9}, {%0,%1,%2,%3};"
        : "+f"(d0), "+f"(d1), "+f"(d2), "+f"(d3)
        : "r"(a0), "r"(a1), "r"(a2), "r"(a3), "r"(b0), "r"(b1));
}

__device__ __forceinline__ uint32_t smem_u32(const void* p) {
    uint32_t a;
    asm("{ .reg .u64 t; cvta.to.shared.u64 t, %1; cvt.u32.u64 %0, t; }"
        : "=r"(a) : "l"(p));
    return a;
}

__device__ __forceinline__ void cp_async16(uint32_t s, const void* g) {
    asm volatile("cp.async.cg.shared.global [%0], [%1], 16;\n"
                 :: "r"(s), "l"(g));
}
__device__ __forceinline__ void cp_commit() {
    asm volatile("cp.async.commit_group;\n");
}

// ---------------------------------------------------------------------------
// TF32 tensor-core GEMM (unchanged): C = A @ W^T + bias
// ---------------------------------------------------------------------------
#define GPAD 20

__global__ void __launch_bounds__(256) gemm_tf32_nt_bias(
    const float* __restrict__ A, const float* __restrict__ W,
    const float* __restrict__ bias, float* __restrict__ C,
    int M, int N, int K)
{
    __shared__ float As[2][128 * GPAD];
    __shared__ float Ws[2][128 * GPAD];

    const int tid  = threadIdx.x;
    const int m0   = blockIdx.y * 128;
    const int n0   = blockIdx.x * 128;
    const int warp = tid >> 5;
    const int lane = tid & 31;
    const int wm   = (warp >> 2) * 64;
    const int wn   = (warp & 3) * 32;
    const int g    = lane >> 2;
    const int t    = lane & 3;

    const int lrow = tid >> 2;
    const int lq   = (tid & 3) << 2;
    const float* Ag = A + (size_t)(m0 + lrow) * K + lq;
    const float* Wg = W + (size_t)(n0 + lrow) * K + lq;

    float acc[4][4][4];
#pragma unroll
    for (int i = 0; i < 4; i++)
#pragma unroll
        for (int j = 0; j < 4; j++)
#pragma unroll
            for (int r = 0; r < 4; r++) acc[i][j][r] = 0.f;

    const int NK = K >> 4;

    auto stage = [&](int buf, float4 a0v, float4 a1v, float4 w0v, float4 w1v) {
        float4 c0 = make_float4(f2tf32(a0v.x), f2tf32(a0v.y), f2tf32(a0v.z), f2tf32(a0v.w));
        float4 c1 = make_float4(f2tf32(a1v.x), f2tf32(a1v.y), f2tf32(a1v.z), f2tf32(a1v.w));
        float4 c2 = make_float4(f2tf32(w0v.x), f2tf32(w0v.y), f2tf32(w0v.z), f2tf32(w0v.w));
        float4 c3 = make_float4(f2tf32(w1v.x), f2tf32(w1v.y), f2tf32(w1v.z), f2tf32(w1v.w));
        *(float4*)&As[buf][lrow        * GPAD + lq] = c0;
        *(float4*)&As[buf][(lrow + 64) * GPAD + lq] = c1;
        *(float4*)&Ws[buf][lrow        * GPAD + lq] = c2;
        *(float4*)&Ws[buf][(lrow + 64) * GPAD + lq] = c3;
    };

    {
        float4 a0v = *(const float4*)(Ag);
        float4 a1v = *(const float4*)(Ag + (size_t)64 * K);
        float4 w0v = *(const float4*)(Wg);
        float4 w1v = *(const float4*)(Wg + (size_t)64 * K);
        stage(0, a0v, a1v, w0v, w1v);
    }
    __syncthreads();

    for (int kt = 0; kt < NK; kt++) {
        const int cur = kt & 1;

        float4 a0v, a1v, w0v, w1v;
        const bool more = (kt + 1) < NK;
        if (more) {
            const float* Ap = Ag + (size_t)(kt + 1) * 16;
            const float* Wp = Wg + (size_t)(kt + 1) * 16;
            a0v = *(const float4*)(Ap);
            a1v = *(const float4*)(Ap + (size_t)64 * K);
            w0v = *(const float4*)(Wp);
            w1v = *(const float4*)(Wp + (size_t)64 * K);
        }

        const uint32_t* Asb = (const uint32_t*)As[cur];
        const uint32_t* Wsb = (const uint32_t*)Ws[cur];

#pragma unroll
        for (int ks = 0; ks < 2; ks++) {
            const int kk = ks * 8;
            uint32_t af[4][4];
#pragma unroll
            for (int i = 0; i < 4; i++) {
                const int rb = wm + i * 16;
                af[i][0] = Asb[(rb + g    ) * GPAD + kk + t    ];
                af[i][1] = Asb[(rb + g + 8) * GPAD + kk + t    ];
                af[i][2] = Asb[(rb + g    ) * GPAD + kk + t + 4];
                af[i][3] = Asb[(rb + g + 8) * GPAD + kk + t + 4];
            }
#pragma unroll
            for (int j = 0; j < 4; j++) {
                const int cb = wn + j * 8 + g;
                uint32_t b0 = Wsb[cb * GPAD + kk + t    ];
                uint32_t b1 = Wsb[cb * GPAD + kk + t + 4];
#pragma unroll
                for (int i = 0; i < 4; i++)
                    mma_tf32(acc[i][j][0], acc[i][j][1], acc[i][j][2], acc[i][j][3],
                             af[i][0], af[i][1], af[i][2], af[i][3], b0, b1);
            }
        }

        if (more) stage(1 - cur, a0v, a1v, w0v, w1v);
        __syncthreads();
    }

#pragma unroll
    for (int i = 0; i < 4; i++) {
        const int r0 = m0 + wm + i * 16 + g;
        const int r1 = r0 + 8;
#pragma unroll
        for (int j = 0; j < 4; j++) {
            const int col = n0 + wn + j * 8 + 2 * t;
            float2 bv = *(const float2*)&bias[col];
            float2 o0 = make_float2(acc[i][j][0] + bv.x, acc[i][j][1] + bv.y);
            float2 o1 = make_float2(acc[i][j][2] + bv.x, acc[i][j][3] + bv.y);
            *(float2*)&C[(size_t)r0 * N + col] = o0;
            *(float2*)&C[(size_t)r1 * N + col] = o1;
        }
    }
}

// ---------------------------------------------------------------------------
// RoPE + TF32 rounding + fragment-order permutation of d within each 8-group
// for q and k (both permuted identically -> dot products unchanged).
// slot(p) = p<4 ? 2p : 2(p-4)+1, i.e. column order [0,4,1,5,2,6,3,7].
// q additionally scaled by DH^-0.5. v: tf32 rounding only, natural order.
// Pairs (d, d+32) always live in the same warp -> loads before stores, safe.
// ---------------------------------------------------------------------------
__global__ void __launch_bounds__(256) rope_tf32_perm_kernel(
    float* __restrict__ qkv, const int* __restrict__ p,
    const float* __restrict__ freqs)
{
    const int idx4 = blockIdx.x * blockDim.x + threadIdx.x;
    const int per_row = D3 / 4;                  // 768
    const int row = idx4 / per_row;
    const int c   = (idx4 - row * per_row) * 4;  // float col
    if (row >= NTOK) return;

    float* base = qkv + (size_t)row * D3 + c;
    float4 v = *(float4*)base;

    if (c < 2 * DD) {                            // q or k: RoPE + permute
        const float pos = (float)p[row];
        const int dh = c & 63;
        const int off = (dh < 32) ? 32 : -32;
        float4 o = *(const float4*)(base + off);
        float vv[4] = {v.x, v.y, v.z, v.w};
        float oo[4] = {o.x, o.y, o.z, o.w};
        const float qs = (c < DD) ? 0.125f : 1.0f;
#pragma unroll
        for (int j = 0; j < 4; j++) {
            float a = pos * freqs[dh + j];
            float sn, cs;
            __sincosf(a, &sn, &cs);
            vv[j] = f2tf32((vv[j] * cs + oo[j] * sn) * qs);
        }
        // scatter to permuted slots within this 8-group
        float* grp = qkv + (size_t)row * D3 + (c & ~7);
        const int p0 = c & 7;                    // 0 or 4
#pragma unroll
        for (int j = 0; j < 4; j++) {
            const int pp = p0 + j;
            const int slot = (pp < 4) ? (pp << 1) : (((pp - 4) << 1) + 1);
            grp[slot] = vv[j];
        }
    } else {                                     // v: tf32 only
        v = make_float4(f2tf32(v.x), f2tf32(v.y), f2tf32(v.z), f2tf32(v.w));
        *(float4*)base = v;
    }
}

// ---------------------------------------------------------------------------
// Flash attention, TF32 tensor cores, high-occupancy version.
// Block: 64 q-rows x 1 head, 4 warps (16 q each). 32-key tiles, cp.async
// double-buffered. Q fragments pre-loaded to registers; Q smem reused for P.
// Q/K in gmem are d-permuted -> QK fragments are float2 LDS.
// smem (floats): QP[64*72] (Q, then P per-warp 16x68), K[2][32*72], V[2][32*72]
// ---------------------------------------------------------------------------
#define AT_K    4608
#define AT_KSZ  2304
#define AT_V    (AT_K + 2*AT_KSZ)       // 9216
#define AT_VSZ  2304
#define AT_TOT  (AT_V + 2*AT_VSZ)       // 13824 floats
#define FA3_SMEM (AT_TOT * (int)sizeof(float))   // 55296 B

__global__ void __launch_bounds__(128, 4) flash_attn_tc2_kernel(
    const float* __restrict__ qkv, float* __restrict__ O)
{
    extern __shared__ float sm[];
    const int tid  = threadIdx.x;
    const int warp = tid >> 5;
    const int lane = tid & 31;
    const int g = lane >> 2;
    const int t = lane & 3;
    const int wq = warp * 16;

    const int qt = blockIdx.x, h = blockIdx.y, b = blockIdx.z;
    const int rowBase = b * SS + qt * 64;
    const int cq = h * DH;
    const int bS = b * SS;

    float* Qs  = sm;                       // 64 x 72 (permuted d)
    float* Psw = sm + warp * (16 * 68);    // overlays Q after frag extraction
    const uint32_t smb = smem_u32(sm);

    // ---- load Q tile to smem (raw copy; gmem already permuted/scaled/tf32)
    for (int i = tid; i < 64 * 16; i += 128) {
        int r = i >> 4, q4 = (i & 15) << 2;
        float4 v = *(const float4*)&qkv[(size_t)(rowBase + r) * D3 + cq + q4];
        *(float4*)&Qs[r * 72 + q4] = v;
    }

    // ---- prefetch K/V tile 0
    auto issue_tile = [&](int kt, int buf) {
        const float* gK = qkv + (size_t)(bS + kt * 32) * D3 + cq + DD;
        const uint32_t sK = smb + (AT_K + buf * AT_KSZ) * 4;
        const uint32_t sV = smb + (AT_V + buf * AT_VSZ) * 4;
#pragma unroll
        for (int it = 0; it < 4; it++) {
            int i = tid + it * 128;          // 0..511
            int r = i >> 4, q4 = (i & 15) << 2;
            const float* gp = gK + (size_t)r * D3 + q4;
            cp_async16(sK + (r * 72 + q4) * 4, gp);
            cp_async16(sV + (r * 72 + q4) * 4, gp + DD);
        }
        cp_commit();
    };
    issue_tile(0, 0);

    __syncthreads();

    // ---- extract Q fragments to registers (warp-local rows wq..wq+15)
    uint32_t qf[8][4];
#pragma unroll
    for (int kk8 = 0; kk8 < 8; kk8++) {
        const int kk = kk8 * 8;
        float2 q0 = *(const float2*)&Qs[(wq + g    ) * 72 + kk + 2 * t];
        float2 q1 = *(const float2*)&Qs[(wq + g + 8) * 72 + kk + 2 * t];
        qf[kk8][0] = __float_as_uint(q0.x);   // A[g][t]
        qf[kk8][1] = __float_as_uint(q1.x);   // A[g+8][t]
        qf[kk8][2] = __float_as_uint(q0.y);   // A[g][t+4]
        qf[kk8][3] = __float_as_uint(q1.y);   // A[g+8][t+4]
    }
    __syncwarp();    // Q rows of this warp now dead; Psw may be written

    float m_i[2] = {-1e30f, -1e30f};
    float l_i[2] = {0.f, 0.f};
    float acc[8][4];
#pragma unroll
    for (int d = 0; d < 8; d++)
#pragma unroll
        for (int r = 0; r < 4; r++) acc[d][r] = 0.f;

    const int NT = SS / 32;   // 64
    for (int kt = 0; kt < NT; kt++) {
        const int cur = kt & 1;
        if (kt + 1 < NT) {
            issue_tile(kt + 1, 1 - cur);
            asm volatile("cp.async.wait_group 1;\n");
        } else {
            asm volatile("cp.async.wait_group 0;\n");
        }
        __syncthreads();

        const float* Ks = sm + AT_K + cur * AT_KSZ;
        const float* Vs = sm + AT_V + cur * AT_VSZ;

        // ---- S = Q K^T (16 x 32 per warp) ----
        float s4[4][4];
#pragma unroll
        for (int n = 0; n < 4; n++)
#pragma unroll
            for (int r = 0; r < 4; r++) s4[n][r] = 0.f;

#pragma unroll
        for (int kk8 = 0; kk8 < 8; kk8++) {
            const int kk = kk8 * 8;
#pragma unroll
            for (int n = 0; n < 4; n++) {
                float2 bv = *(const float2*)&Ks[(n * 8 + g) * 72 + kk + 2 * t];
                mma_tf32(s4[n][0], s4[n][1], s4[n][2], s4[n][3],
                         qf[kk8][0], qf[kk8][1], qf[kk8][2], qf[kk8][3],
                         __float_as_uint(bv.x), __float_as_uint(bv.y));
            }
        }

        // ---- online softmax; rows r0 = wq+g, r1 = wq+g+8 ----
        float mx0 = -1e30f, mx1 = -1e30f;
#pragma unroll
        for (int n = 0; n < 4; n++) {
            mx0 = fmaxf(mx0, fmaxf(s4[n][0], s4[n][1]));
            mx1 = fmaxf(mx1, fmaxf(s4[n][2], s4[n][3]));
        }
        mx0 = fmaxf(mx0, __shfl_xor_sync(0xffffffffu, mx0, 1));
        mx0 = fmaxf(mx0, __shfl_xor_sync(0xffffffffu, mx0, 2));
        mx1 = fmaxf(mx1, __shfl_xor_sync(0xffffffffu, mx1, 1));
        mx1 = fmaxf(mx1, __shfl_xor_sync(0xffffffffu, mx1, 2));

        float mn0 = fmaxf(m_i[0], mx0);
        float mn1 = fmaxf(m_i[1], mx1);
        float cr0 = __expf(m_i[0] - mn0);
        float cr1 = __expf(m_i[1] - mn1);

        float sum0 = 0.f, sum1 = 0.f;
#pragma unroll
        for (int n = 0; n < 4; n++) {
            s4[n][0] = __expf(s4[n][0] - mn0);
            s4[n][1] = __expf(s4[n][1] - mn0);
            s4[n][2] = __expf(s4[n][2] - mn1);
            s4[n][3] = __expf(s4[n][3] - mn1);
            sum0 += s4[n][0] + s4[n][1];
            sum1 += s4[n][2] + s4[n][3];
        }
        sum0 += __shfl_xor_sync(0xffffffffu, sum0, 1);
        sum0 += __shfl_xor_sync(0xffffffffu, sum0, 2);
        sum1 += __shfl_xor_sync(0xffffffffu, sum1, 1);
        sum1 += __shfl_xor_sync(0xffffffffu, sum1, 2);

        l_i[0] = l_i[0] * cr0 + sum0;
        l_i[1] = l_i[1] * cr1 + sum1;
        m_i[0] = mn0; m_i[1] = mn1;

#pragma unroll
        for (int d = 0; d < 8; d++) {
            acc[d][0] *= cr0; acc[d][1] *= cr0;
            acc[d][2] *= cr1; acc[d][3] *= cr1;
        }

        // ---- store P (tf32, float2) ----
#pragma unroll
        for (int n = 0; n < 4; n++) {
            *(float2*)&Psw[ g      * 68 + n * 8 + 2 * t] =
                make_float2(f2tf32(s4[n][0]), f2tf32(s4[n][1]));
            *(float2*)&Psw[(g + 8) * 68 + n * 8 + 2 * t] =
                make_float2(f2tf32(s4[n][2]), f2tf32(s4[n][3]));
        }
        __syncwarp();

        // ---- acc += P @ V ----
#pragma unroll
        for (int kk8 = 0; kk8 < 4; kk8++) {
            const int kk = kk8 * 8;
            uint32_t a0 = __float_as_uint(Psw[ g      * 68 + kk + t    ]);
            uint32_t a1 = __float_as_uint(Psw[(g + 8) * 68 + kk + t    ]);
            uint32_t a2 = __float_as_uint(Psw[ g      * 68 + kk + t + 4]);
            uint32_t a3 = __float_as_uint(Psw[(g + 8) * 68 + kk + t + 4]);
#pragma unroll
            for (int d = 0; d < 8; d++) {
                uint32_t b0 = __float_as_uint(Vs[(kk + t    ) * 72 + d * 8 + g]);
                uint32_t b1 = __float_as_uint(Vs[(kk + t + 4) * 72 + d * 8 + g]);
                mma_tf32(acc[d][0], acc[d][1], acc[d][2], acc[d][3],
                         a0, a1, a2, a3, b0, b1);
            }
        }
        __syncthreads();   // all warps done with cur K/V before refill
    }

    // ---- write O (natural d order) ----
    const float inv0 = 1.0f / l_i[0];
    const float inv1 = 1.0f / l_i[1];
    const int r0 = rowBase + wq + g;
    const int r1 = r0 + 8;
#pragma unroll
    for (int d = 0; d < 8; d++) {
        const int col = cq + d * 8 + 2 * t;
        *(float2*)&O[(size_t)r0 * DD + col] =
            make_float2(acc[d][0] * inv0, acc[d][1] * inv0);
        *(float2*)&O[(size_t)r1 * DD + col] =
            make_float2(acc[d][2] * inv1, acc[d][3] * inv1);
    }
}

// ---------------------------------------------------------------------------
// Fused residual add + LayerNorm
// ---------------------------------------------------------------------------
__global__ void __launch_bounds__(256) add_ln_kernel(
    const float* __restrict__ A, const float* __restrict__ R,
    const float* __restrict__ g, const float* __restrict__ be,
    float* __restrict__ out)
{
    __shared__ float red[8];
    const int row = blockIdx.x, tid = threadIdx.x;
    const int lane = tid & 31, wid = tid >> 5;

    float4 a = ((const float4*)(A + (size_t)row * DD))[tid];
    float4 r = ((const float4*)(R + (size_t)row * DD))[tid];
    float4 t = make_float4(a.x + r.x, a.y + r.y, a.z + r.z, a.w + r.w);

    float ssum = t.x + t.y + t.z + t.w;
#pragma unroll
    for (int o = 16; o; o >>= 1) ssum += __shfl_xor_sync(0xffffffffu, ssum, o);
    if (lane == 0) red[wid] = ssum;
    __syncthreads();
    float mean = (red[0] + red[1] + red[2] + red[3] +
                  red[4] + red[5] + red[6] + red[7]) * (1.0f / DD);
    __syncthreads();

    float4 d = make_float4(t.x - mean, t.y - mean, t.z - mean, t.w - mean);
    float sq = d.x * d.x + d.y * d.y + d.z * d.z + d.w * d.w;
#pragma unroll
    for (int o = 16; o; o >>= 1) sq += __shfl_xor_sync(0xffffffffu, sq, o);
    if (lane == 0) red[wid] = sq;
    __syncthreads();
    float var = (red[0] + red[1] + red[2] + red[3] +
                 red[4] + red[5] + red[6] + red[7]) * (1.0f / DD);
    float rs = rsqrtf(var + 1e-5f);

    float4 gv = ((const float4*)g)[tid];
    float4 bv = ((const float4*)be)[tid];
    float4 o4 = make_float4(d.x * rs * gv.x + bv.x,
                            d.y * rs * gv.y + bv.y,
                            d.z * rs * gv.z + bv.z,
                            d.w * rs * gv.w + bv.w);
    ((float4*)(out + (size_t)row * DD))[tid] = o4;
}

// ---------------------------------------------------------------------------
// GELU(exact) * gate
// ---------------------------------------------------------------------------
__global__ void __launch_bounds__(256) gelu_gate_kernel(
    const float* __restrict__ u, float* __restrict__ m)
{
    int gid = blockIdx.x * blockDim.x + threadIdx.x;
    const int f4_per_row = FF / 4;
    int row  = gid / f4_per_row;
    int col4 = gid - row * f4_per_row;
    if (row >= NTOK) return;

    const float4* U4 = (const float4*)(u + (size_t)row * 2 * FF);
    float4 a = U4[col4];
    float4 gt = U4[f4_per_row + col4];

    const float inv_sqrt2 = 0.70710678118654752f;
    float4 o;
    o.x = 0.5f * a.x * (1.0f + erff(a.x * inv_sqrt2)) * gt.x;
    o.y = 0.5f * a.y * (1.0f + erff(a.y * inv_sqrt2)) * gt.y;
    o.z = 0.5f * a.z * (1.0f + erff(a.z * inv_sqrt2)) * gt.z;
    o.w = 0.5f * a.w * (1.0f + erff(a.w * inv_sqrt2)) * gt.w;
    ((float4*)(m + (size_t)row * FF))[col4] = o;
}

// ---------------------------------------------------------------------------
// kernel_launch
// ---------------------------------------------------------------------------
extern "C" void kernel_launch(void* const* d_in, const int* in_sizes, int n_in,
                              void* d_out, int out_size)
{
    const float* x      = (const float*)d_in[0];
    const int*   p      = (const int*)  d_in[1];
    const float* Wqkv   = (const float*)d_in[2];
    const float* bqkv   = (const float*)d_in[3];
    const float* Wo     = (const float*)d_in[4];
    const float* bo     = (const float*)d_in[5];
    const float* gattn  = (const float*)d_in[6];
    const float* battn  = (const float*)d_in[7];
    const float* W1     = (const float*)d_in[8];
    const float* b1     = (const float*)d_in[9];
    const float* W2     = (const float*)d_in[10];
    const float* b2     = (const float*)d_in[11];
    const float* gmlp   = (const float*)d_in[12];
    const float* bmlp   = (const float*)d_in[13];
    const float* freqs  = (const float*)d_in[14];
    float* out = (float*)d_out;

    float *qkv, *attn, *proj, *hbuf, *u, *mbuf, *m2;
    cudaGetSymbolAddress((void**)&qkv,  g_qkv);
    cudaGetSymbolAddress((void**)&attn, g_attn);
    cudaGetSymbolAddress((void**)&proj, g_proj);
    cudaGetSymbolAddress((void**)&hbuf, g_hbuf);
    cudaGetSymbolAddress((void**)&u,    g_u);
    cudaGetSymbolAddress((void**)&mbuf, g_mbuf);
    cudaGetSymbolAddress((void**)&m2,   g_m2);

    cudaFuncSetAttribute(flash_attn_tc2_kernel,
                         cudaFuncAttributeMaxDynamicSharedMemorySize, FA3_SMEM);

    // 1) QKV projection
    gemm_tf32_nt_bias<<<dim3(D3 / 128, NTOK / 128), 256>>>(
        x, Wqkv, bqkv, qkv, NTOK, D3, DD);

    // 2) RoPE + tf32 rounding + fragment permutation of q,k
    rope_tf32_perm_kernel<<<(NTOK * D3 / 4) / 256, 256>>>(qkv, p, freqs);

    // 3) Flash attention (tensor cores, 4 CTA/SM)
    flash_attn_tc2_kernel<<<dim3(SS / 64, HH, BB), 128, FA3_SMEM>>>(qkv, attn);

    // 4) Output projection
    gemm_tf32_nt_bias<<<dim3(DD / 128, NTOK / 128), 256>>>(
        attn, Wo, bo, proj, NTOK, DD, DD);

    // 5) h = LN(proj + x)
    add_ln_kernel<<<NTOK, 256>>>(proj, x, gattn, battn, hbuf);

    // 6) u = h @ W1^T + b1
    gemm_tf32_nt_bias<<<dim3(2 * FF / 128, NTOK / 128), 256>>>(
        hbuf, W1, b1, u, NTOK, 2 * FF, DD);

    // 7) m = gelu(a) * gate
    gelu_gate_kernel<<<(NTOK * FF / 4) / 256, 256>>>(u, mbuf);

    // 8) m2 = m @ W2^T + b2
    gemm_tf32_nt_bias<<<dim3(DD / 128, NTOK / 128), 256>>>(
        mbuf, W2, b2, m2, NTOK, DD, FF);

    // 9) out = LN(m2 + h)
    add_ln_kernel<<<NTOK, 256>>>(m2, hbuf, gmlp, bmlp, out);
}

// round 5
// speedup vs baseline: 3.4182x; 1.0960x over previous
#include <cuda_runtime.h>
#include <math.h>
#include <stdint.h>

// Problem constants
#define BB   2
#define SS   2048
#define DD   1024
#define HH   16
#define DH   64
#define FF   4096
#define NTOK (BB*SS)          // 4096 rows
#define D3   (3*DD)           // 3072

// ---------------------------------------------------------------------------
// Scratch (static device globals — no runtime allocation allowed)
// ---------------------------------------------------------------------------
__device__ float g_qkv [NTOK * D3];
__device__ float g_attn[NTOK * DD];
__device__ float g_proj[NTOK * DD];
__device__ float g_hbuf[NTOK * DD];
__device__ float g_u   [NTOK * 2 * FF];
__device__ float g_mbuf[NTOK * FF];
__device__ float g_m2  [NTOK * DD];
// tf32 pre-converted GEMM inputs
__device__ float g_xt  [NTOK * DD];
__device__ float g_ht  [NTOK * DD];
__device__ float g_wqkvt[D3 * DD];
__device__ float g_wot [DD * DD];
__device__ float g_w1t [2 * FF * DD];
__device__ float g_w2t [DD * FF];

// ---------------------------------------------------------------------------
// TF32 / MMA / cp.async helpers
// ---------------------------------------------------------------------------
__device__ __forceinline__ float f2tf32(float x) {
    uint32_t u;
    asm("cvt.rna.tf32.f32 %0, %1;" : "=r"(u) : "f"(x));
    return __uint_as_float(u);
}

__device__ __forceinline__ void mma_tf32(
    float& d0, float& d1, float& d2, float& d3,
    uint32_t a0, uint32_t a1, uint32_t a2, uint32_t a3,
    uint32_t b0, uint32_t b1)
{
    asm volatile(
        "mma.sync.aligned.m16n8k8.row.col.f32.tf32.tf32.f32 "
        "{%0,%1,%2,%3}, {%4,%5,%6,%7}, {%8,%9}, {%0,%1,%2,%3};"
        : "+f"(d0), "+f"(d1), "+f"(d2), "+f"(d3)
        : "r"(a0), "r"(a1), "r"(a2), "r"(a3), "r"(b0), "r"(b1));
}

__device__ __forceinline__ uint32_t smem_u32(const void* p) {
    uint32_t a;
    asm("{ .reg .u64 t; cvta.to.shared.u64 t, %1; cvt.u32.u64 %0, t; }"
        : "=r"(a) : "l"(p));
    return a;
}

__device__ __forceinline__ void cp_async16(uint32_t s, const void* g) {
    asm volatile("cp.async.cg.shared.global [%0], [%1], 16;\n"
                 :: "r"(s), "l"(g));
}
__device__ __forceinline__ void cp_commit() {
    asm volatile("cp.async.commit_group;\n");
}

// ---------------------------------------------------------------------------
// tf32 copy (RNA rounding), float4 vectorized
// ---------------------------------------------------------------------------
__global__ void __launch_bounds__(256) tf32_copy_kernel(
    const float* __restrict__ s, float* __restrict__ d, int n4)
{
    int i = blockIdx.x * blockDim.x + threadIdx.x;
    if (i < n4) {
        float4 v = ((const float4*)s)[i];
        ((float4*)d)[i] = make_float4(f2tf32(v.x), f2tf32(v.y),
                                      f2tf32(v.z), f2tf32(v.w));
    }
}

// ---------------------------------------------------------------------------
// GEMM v3: inputs pre-rounded to tf32. C = A @ W^T + bias.
// CTA tile 128x128, BK=16, 8 warps (2x4), warp tile 64x32.
// 3-stage cp.async pipeline, stride-28 smem rows (conflict-free frag LDS),
// fragment double-buffering across the two k-steps.
// ---------------------------------------------------------------------------
#define SSTR    28
#define STAGE_F (2 * 128 * SSTR)                 // floats per stage (A+B)
#define G3_SMEM (3 * STAGE_F * (int)sizeof(float))   // 86016 bytes

__global__ void __launch_bounds__(256) gemm_pre_nt_bias(
    const float* __restrict__ A, const float* __restrict__ W,
    const float* __restrict__ bias, float* __restrict__ C,
    int M, int N, int K)
{
    extern __shared__ float sm[];
    const int tid  = threadIdx.x;
    const int m0   = blockIdx.y * 128;
    const int n0   = blockIdx.x * 128;
    const int warp = tid >> 5;
    const int lane = tid & 31;
    const int g    = lane >> 2;
    const int t    = lane & 3;
    const int wm   = (warp >> 2) * 64;
    const int wn   = (warp & 3) * 32;

    const int lrow = tid >> 1;          // 0..127
    const int lc   = (tid & 1) * 8;     // 0 or 8
    const float* Ag = A + (size_t)(m0 + lrow) * K + lc;
    const float* Wg = W + (size_t)(n0 + lrow) * K + lc;
    const uint32_t smb = smem_u32(sm);

    const int NK = K >> 4;

    auto issue = [&](int kt) {
        const int buf = kt % 3;
        uint32_t dA = smb + (uint32_t)(buf * STAGE_F + lrow * SSTR + lc) * 4;
        uint32_t dB = dA + 128 * SSTR * 4;
        const float* a = Ag + (size_t)kt * 16;
        const float* w = Wg + (size_t)kt * 16;
        cp_async16(dA,      a);
        cp_async16(dA + 16, a + 4);
        cp_async16(dB,      w);
        cp_async16(dB + 16, w + 4);
        cp_commit();
    };

    uint32_t af0[4][4], bf0[4][2], af1[4][4], bf1[4][2];

    auto ldfrag = [&](int buf, int ks, uint32_t af[4][4], uint32_t bf[4][2]) {
        const float* As = sm + buf * STAGE_F;
        const float* Bs = As + 128 * SSTR;
        const int kk = ks * 8;
#pragma unroll
        for (int i = 0; i < 4; i++) {
            const int rb = wm + i * 16;
            af[i][0] = __float_as_uint(As[(rb + g    ) * SSTR + kk + t    ]);
            af[i][1] = __float_as_uint(As[(rb + g + 8) * SSTR + kk + t    ]);
            af[i][2] = __float_as_uint(As[(rb + g    ) * SSTR + kk + t + 4]);
            af[i][3] = __float_as_uint(As[(rb + g + 8) * SSTR + kk + t + 4]);
        }
#pragma unroll
        for (int j = 0; j < 4; j++) {
            const int cb = wn + j * 8 + g;
            bf[j][0] = __float_as_uint(Bs[cb * SSTR + kk + t    ]);
            bf[j][1] = __float_as_uint(Bs[cb * SSTR + kk + t + 4]);
        }
    };

    float acc[4][4][4];
#pragma unroll
    for (int i = 0; i < 4; i++)
#pragma unroll
        for (int j = 0; j < 4; j++)
#pragma unroll
            for (int r = 0; r < 4; r++) acc[i][j][r] = 0.f;

    auto mma16 = [&](uint32_t af[4][4], uint32_t bf[4][2]) {
#pragma unroll
        for (int j = 0; j < 4; j++)
#pragma unroll
            for (int i = 0; i < 4; i++)
                mma_tf32(acc[i][j][0], acc[i][j][1], acc[i][j][2], acc[i][j][3],
                         af[i][0], af[i][1], af[i][2], af[i][3],
                         bf[j][0], bf[j][1]);
    };

    // prologue: two stages in flight
    issue(0);
    issue(1);
    asm volatile("cp.async.wait_group 1;\n");
    __syncthreads();
    ldfrag(0, 0, af0, bf0);

    for (int kt = 0; kt < NK; kt++) {
        const int buf = kt % 3;
        ldfrag(buf, 1, af1, bf1);
        mma16(af0, bf0);
        const bool more2 = (kt + 2) < NK;
        if (more2) issue(kt + 2);
        mma16(af1, bf1);
        if (kt + 1 < NK) {
            if (more2) asm volatile("cp.async.wait_group 1;\n");
            else       asm volatile("cp.async.wait_group 0;\n");
            __syncthreads();
            ldfrag((kt + 1) % 3, 0, af0, bf0);
        }
    }

    // epilogue: bias add, float2 stores
#pragma unroll
    for (int i = 0; i < 4; i++) {
        const int r0 = m0 + wm + i * 16 + g;
        const int r1 = r0 + 8;
#pragma unroll
        for (int j = 0; j < 4; j++) {
            const int col = n0 + wn + j * 8 + 2 * t;
            float2 bv = *(const float2*)&bias[col];
            float2 o0 = make_float2(acc[i][j][0] + bv.x, acc[i][j][1] + bv.y);
            float2 o1 = make_float2(acc[i][j][2] + bv.x, acc[i][j][3] + bv.y);
            *(float2*)&C[(size_t)r0 * N + col] = o0;
            *(float2*)&C[(size_t)r1 * N + col] = o1;
        }
    }
}

// ---------------------------------------------------------------------------
// RoPE + TF32 rounding + fragment-order permutation of d within each 8-group
// for q and k (both permuted identically -> dot products unchanged).
// q additionally scaled by DH^-0.5. v: tf32 rounding only, natural order.
// ---------------------------------------------------------------------------
__global__ void __launch_bounds__(256) rope_tf32_perm_kernel(
    float* __restrict__ qkv, const int* __restrict__ p,
    const float* __restrict__ freqs)
{
    const int idx4 = blockIdx.x * blockDim.x + threadIdx.x;
    const int per_row = D3 / 4;                  // 768
    const int row = idx4 / per_row;
    const int c   = (idx4 - row * per_row) * 4;  // float col
    if (row >= NTOK) return;

    float* base = qkv + (size_t)row * D3 + c;
    float4 v = *(float4*)base;

    if (c < 2 * DD) {                            // q or k: RoPE + permute
        const float pos = (float)p[row];
        const int dh = c & 63;
        const int off = (dh < 32) ? 32 : -32;
        float4 o = *(const float4*)(base + off);
        float vv[4] = {v.x, v.y, v.z, v.w};
        float oo[4] = {o.x, o.y, o.z, o.w};
        const float qs = (c < DD) ? 0.125f : 1.0f;
#pragma unroll
        for (int j = 0; j < 4; j++) {
            float a = pos * freqs[dh + j];
            float sn, cs;
            __sincosf(a, &sn, &cs);
            vv[j] = f2tf32((vv[j] * cs + oo[j] * sn) * qs);
        }
        float* grp = qkv + (size_t)row * D3 + (c & ~7);
        const int p0 = c & 7;                    // 0 or 4
#pragma unroll
        for (int j = 0; j < 4; j++) {
            const int pp = p0 + j;
            const int slot = (pp < 4) ? (pp << 1) : (((pp - 4) << 1) + 1);
            grp[slot] = vv[j];
        }
    } else {                                     // v: tf32 only
        v = make_float4(f2tf32(v.x), f2tf32(v.y), f2tf32(v.z), f2tf32(v.w));
        *(float4*)base = v;
    }
}

// ---------------------------------------------------------------------------
// Flash attention, TF32 tensor cores (as R4), output tf32-rounded (feeds
// only the O-projection GEMM).
// ---------------------------------------------------------------------------
#define AT_K    4608
#define AT_KSZ  2304
#define AT_V    (AT_K + 2*AT_KSZ)       // 9216
#define AT_VSZ  2304
#define AT_TOT  (AT_V + 2*AT_VSZ)       // 13824 floats
#define FA3_SMEM (AT_TOT * (int)sizeof(float))   // 55296 B

__global__ void __launch_bounds__(128, 4) flash_attn_tc2_kernel(
    const float* __restrict__ qkv, float* __restrict__ O)
{
    extern __shared__ float sm[];
    const int tid  = threadIdx.x;
    const int warp = tid >> 5;
    const int lane = tid & 31;
    const int g = lane >> 2;
    const int t = lane & 3;
    const int wq = warp * 16;

    const int qt = blockIdx.x, h = blockIdx.y, b = blockIdx.z;
    const int rowBase = b * SS + qt * 64;
    const int cq = h * DH;
    const int bS = b * SS;

    float* Qs  = sm;
    float* Psw = sm + warp * (16 * 68);
    const uint32_t smb = smem_u32(sm);

    for (int i = tid; i < 64 * 16; i += 128) {
        int r = i >> 4, q4 = (i & 15) << 2;
        float4 v = *(const float4*)&qkv[(size_t)(rowBase + r) * D3 + cq + q4];
        *(float4*)&Qs[r * 72 + q4] = v;
    }

    auto issue_tile = [&](int kt, int buf) {
        const float* gK = qkv + (size_t)(bS + kt * 32) * D3 + cq + DD;
        const uint32_t sK = smb + (AT_K + buf * AT_KSZ) * 4;
        const uint32_t sV = smb + (AT_V + buf * AT_VSZ) * 4;
#pragma unroll
        for (int it = 0; it < 4; it++) {
            int i = tid + it * 128;
            int r = i >> 4, q4 = (i & 15) << 2;
            const float* gp = gK + (size_t)r * D3 + q4;
            cp_async16(sK + (r * 72 + q4) * 4, gp);
            cp_async16(sV + (r * 72 + q4) * 4, gp + DD);
        }
        cp_commit();
    };
    issue_tile(0, 0);

    __syncthreads();

    uint32_t qf[8][4];
#pragma unroll
    for (int kk8 = 0; kk8 < 8; kk8++) {
        const int kk = kk8 * 8;
        float2 q0 = *(const float2*)&Qs[(wq + g    ) * 72 + kk + 2 * t];
        float2 q1 = *(const float2*)&Qs[(wq + g + 8) * 72 + kk + 2 * t];
        qf[kk8][0] = __float_as_uint(q0.x);
        qf[kk8][1] = __float_as_uint(q1.x);
        qf[kk8][2] = __float_as_uint(q0.y);
        qf[kk8][3] = __float_as_uint(q1.y);
    }
    __syncwarp();

    float m_i[2] = {-1e30f, -1e30f};
    float l_i[2] = {0.f, 0.f};
    float acc[8][4];
#pragma unroll
    for (int d = 0; d < 8; d++)
#pragma unroll
        for (int r = 0; r < 4; r++) acc[d][r] = 0.f;

    const int NT = SS / 32;
    for (int kt = 0; kt < NT; kt++) {
        const int cur = kt & 1;
        if (kt + 1 < NT) {
            issue_tile(kt + 1, 1 - cur);
            asm volatile("cp.async.wait_group 1;\n");
        } else {
            asm volatile("cp.async.wait_group 0;\n");
        }
        __syncthreads();

        const float* Ks = sm + AT_K + cur * AT_KSZ;
        const float* Vs = sm + AT_V + cur * AT_VSZ;

        float s4[4][4];
#pragma unroll
        for (int n = 0; n < 4; n++)
#pragma unroll
            for (int r = 0; r < 4; r++) s4[n][r] = 0.f;

#pragma unroll
        for (int kk8 = 0; kk8 < 8; kk8++) {
            const int kk = kk8 * 8;
#pragma unroll
            for (int n = 0; n < 4; n++) {
                float2 bv = *(const float2*)&Ks[(n * 8 + g) * 72 + kk + 2 * t];
                mma_tf32(s4[n][0], s4[n][1], s4[n][2], s4[n][3],
                         qf[kk8][0], qf[kk8][1], qf[kk8][2], qf[kk8][3],
                         __float_as_uint(bv.x), __float_as_uint(bv.y));
            }
        }

        float mx0 = -1e30f, mx1 = -1e30f;
#pragma unroll
        for (int n = 0; n < 4; n++) {
            mx0 = fmaxf(mx0, fmaxf(s4[n][0], s4[n][1]));
            mx1 = fmaxf(mx1, fmaxf(s4[n][2], s4[n][3]));
        }
        mx0 = fmaxf(mx0, __shfl_xor_sync(0xffffffffu, mx0, 1));
        mx0 = fmaxf(mx0, __shfl_xor_sync(0xffffffffu, mx0, 2));
        mx1 = fmaxf(mx1, __shfl_xor_sync(0xffffffffu, mx1, 1));
        mx1 = fmaxf(mx1, __shfl_xor_sync(0xffffffffu, mx1, 2));

        float mn0 = fmaxf(m_i[0], mx0);
        float mn1 = fmaxf(m_i[1], mx1);
        float cr0 = __expf(m_i[0] - mn0);
        float cr1 = __expf(m_i[1] - mn1);

        float sum0 = 0.f, sum1 = 0.f;
#pragma unroll
        for (int n = 0; n < 4; n++) {
            s4[n][0] = __expf(s4[n][0] - mn0);
            s4[n][1] = __expf(s4[n][1] - mn0);
            s4[n][2] = __expf(s4[n][2] - mn1);
            s4[n][3] = __expf(s4[n][3] - mn1);
            sum0 += s4[n][0] + s4[n][1];
            sum1 += s4[n][2] + s4[n][3];
        }
        sum0 += __shfl_xor_sync(0xffffffffu, sum0, 1);
        sum0 += __shfl_xor_sync(0xffffffffu, sum0, 2);
        sum1 += __shfl_xor_sync(0xffffffffu, sum1, 1);
        sum1 += __shfl_xor_sync(0xffffffffu, sum1, 2);

        l_i[0] = l_i[0] * cr0 + sum0;
        l_i[1] = l_i[1] * cr1 + sum1;
        m_i[0] = mn0; m_i[1] = mn1;

#pragma unroll
        for (int d = 0; d < 8; d++) {
            acc[d][0] *= cr0; acc[d][1] *= cr0;
            acc[d][2] *= cr1; acc[d][3] *= cr1;
        }

#pragma unroll
        for (int n = 0; n < 4; n++) {
            *(float2*)&Psw[ g      * 68 + n * 8 + 2 * t] =
                make_float2(f2tf32(s4[n][0]), f2tf32(s4[n][1]));
            *(float2*)&Psw[(g + 8) * 68 + n * 8 + 2 * t] =
                make_float2(f2tf32(s4[n][2]), f2tf32(s4[n][3]));
        }
        __syncwarp();

#pragma unroll
        for (int kk8 = 0; kk8 < 4; kk8++) {
            const int kk = kk8 * 8;
            uint32_t a0 = __float_as_uint(Psw[ g      * 68 + kk + t    ]);
            uint32_t a1 = __float_as_uint(Psw[(g + 8) * 68 + kk + t    ]);
            uint32_t a2 = __float_as_uint(Psw[ g      * 68 + kk + t + 4]);
            uint32_t a3 = __float_as_uint(Psw[(g + 8) * 68 + kk + t + 4]);
#pragma unroll
            for (int d = 0; d < 8; d++) {
                uint32_t b0 = __float_as_uint(Vs[(kk + t    ) * 72 + d * 8 + g]);
                uint32_t b1 = __float_as_uint(Vs[(kk + t + 4) * 72 + d * 8 + g]);
                mma_tf32(acc[d][0], acc[d][1], acc[d][2], acc[d][3],
                         a0, a1, a2, a3, b0, b1);
            }
        }
        __syncthreads();
    }

    const float inv0 = 1.0f / l_i[0];
    const float inv1 = 1.0f / l_i[1];
    const int r0 = rowBase + wq + g;
    const int r1 = r0 + 8;
#pragma unroll
    for (int d = 0; d < 8; d++) {
        const int col = cq + d * 8 + 2 * t;
        *(float2*)&O[(size_t)r0 * DD + col] =
            make_float2(f2tf32(acc[d][0] * inv0), f2tf32(acc[d][1] * inv0));
        *(float2*)&O[(size_t)r1 * DD + col] =
            make_float2(f2tf32(acc[d][2] * inv1), f2tf32(acc[d][3] * inv1));
    }
}

// ---------------------------------------------------------------------------
// Fused residual add + LayerNorm. Optionally also writes a tf32-rounded copy
// (for feeding the next GEMM) while keeping the fp32 result exact.
// ---------------------------------------------------------------------------
__global__ void __launch_bounds__(256) add_ln_kernel(
    const float* __restrict__ A, const float* __restrict__ R,
    const float* __restrict__ g, const float* __restrict__ be,
    float* __restrict__ out, float* __restrict__ out_t)
{
    __shared__ float red[8];
    const int row = blockIdx.x, tid = threadIdx.x;
    const int lane = tid & 31, wid = tid >> 5;

    float4 a = ((const float4*)(A + (size_t)row * DD))[tid];
    float4 r = ((const float4*)(R + (size_t)row * DD))[tid];
    float4 t = make_float4(a.x + r.x, a.y + r.y, a.z + r.z, a.w + r.w);

    float ssum = t.x + t.y + t.z + t.w;
#pragma unroll
    for (int o = 16; o; o >>= 1) ssum += __shfl_xor_sync(0xffffffffu, ssum, o);
    if (lane == 0) red[wid] = ssum;
    __syncthreads();
    float mean = (red[0] + red[1] + red[2] + red[3] +
                  red[4] + red[5] + red[6] + red[7]) * (1.0f / DD);
    __syncthreads();

    float4 d = make_float4(t.x - mean, t.y - mean, t.z - mean, t.w - mean);
    float sq = d.x * d.x + d.y * d.y + d.z * d.z + d.w * d.w;
#pragma unroll
    for (int o = 16; o; o >>= 1) sq += __shfl_xor_sync(0xffffffffu, sq, o);
    if (lane == 0) red[wid] = sq;
    __syncthreads();
    float var = (red[0] + red[1] + red[2] + red[3] +
                 red[4] + red[5] + red[6] + red[7]) * (1.0f / DD);
    float rs = rsqrtf(var + 1e-5f);

    float4 gv = ((const float4*)g)[tid];
    float4 bv = ((const float4*)be)[tid];
    float4 o4 = make_float4(d.x * rs * gv.x + bv.x,
                            d.y * rs * gv.y + bv.y,
                            d.z * rs * gv.z + bv.z,
                            d.w * rs * gv.w + bv.w);
    ((float4*)(out + (size_t)row * DD))[tid] = o4;
    if (out_t) {
        float4 o4t = make_float4(f2tf32(o4.x), f2tf32(o4.y),
                                 f2tf32(o4.z), f2tf32(o4.w));
        ((float4*)(out_t + (size_t)row * DD))[tid] = o4t;
    }
}

// ---------------------------------------------------------------------------
// GELU(exact) * gate, output tf32-rounded (feeds only the W2 GEMM)
// ---------------------------------------------------------------------------
__global__ void __launch_bounds__(256) gelu_gate_kernel(
    const float* __restrict__ u, float* __restrict__ m)
{
    int gid = blockIdx.x * blockDim.x + threadIdx.x;
    const int f4_per_row = FF / 4;
    int row  = gid / f4_per_row;
    int col4 = gid - row * f4_per_row;
    if (row >= NTOK) return;

    const float4* U4 = (const float4*)(u + (size_t)row * 2 * FF);
    float4 a = U4[col4];
    float4 gt = U4[f4_per_row + col4];

    const float inv_sqrt2 = 0.70710678118654752f;
    float4 o;
    o.x = f2tf32(0.5f * a.x * (1.0f + erff(a.x * inv_sqrt2)) * gt.x);
    o.y = f2tf32(0.5f * a.y * (1.0f + erff(a.y * inv_sqrt2)) * gt.y);
    o.z = f2tf32(0.5f * a.z * (1.0f + erff(a.z * inv_sqrt2)) * gt.z);
    o.w = f2tf32(0.5f * a.w * (1.0f + erff(a.w * inv_sqrt2)) * gt.w);
    ((float4*)(m + (size_t)row * FF))[col4] = o;
}

// ---------------------------------------------------------------------------
// kernel_launch
// ---------------------------------------------------------------------------
extern "C" void kernel_launch(void* const* d_in, const int* in_sizes, int n_in,
                              void* d_out, int out_size)
{
    const float* x      = (const float*)d_in[0];
    const int*   p      = (const int*)  d_in[1];
    const float* Wqkv   = (const float*)d_in[2];
    const float* bqkv   = (const float*)d_in[3];
    const float* Wo     = (const float*)d_in[4];
    const float* bo     = (const float*)d_in[5];
    const float* gattn  = (const float*)d_in[6];
    const float* battn  = (const float*)d_in[7];
    const float* W1     = (const float*)d_in[8];
    const float* b1     = (const float*)d_in[9];
    const float* W2     = (const float*)d_in[10];
    const float* b2     = (const float*)d_in[11];
    const float* gmlp   = (const float*)d_in[12];
    const float* bmlp   = (const float*)d_in[13];
    const float* freqs  = (const float*)d_in[14];
    float* out = (float*)d_out;

    float *qkv, *attn, *proj, *hbuf, *u, *mbuf, *m2;
    float *xt, *ht, *wqkvt, *wot, *w1t, *w2t;
    cudaGetSymbolAddress((void**)&qkv,  g_qkv);
    cudaGetSymbolAddress((void**)&attn, g_attn);
    cudaGetSymbolAddress((void**)&proj, g_proj);
    cudaGetSymbolAddress((void**)&hbuf, g_hbuf);
    cudaGetSymbolAddress((void**)&u,    g_u);
    cudaGetSymbolAddress((void**)&mbuf, g_mbuf);
    cudaGetSymbolAddress((void**)&m2,   g_m2);
    cudaGetSymbolAddress((void**)&xt,   g_xt);
    cudaGetSymbolAddress((void**)&ht,   g_ht);
    cudaGetSymbolAddress((void**)&wqkvt,g_wqkvt);
    cudaGetSymbolAddress((void**)&wot,  g_wot);
    cudaGetSymbolAddress((void**)&w1t,  g_w1t);
    cudaGetSymbolAddress((void**)&w2t,  g_w2t);

    cudaFuncSetAttribute(flash_attn_tc2_kernel,
                         cudaFuncAttributeMaxDynamicSharedMemorySize, FA3_SMEM);
    cudaFuncSetAttribute(gemm_pre_nt_bias,
                         cudaFuncAttributeMaxDynamicSharedMemorySize, G3_SMEM);

    // 0) tf32 pre-conversion of GEMM inputs (weights + x)
    tf32_copy_kernel<<<(NTOK * DD / 4 + 255) / 256, 256>>>(x,    xt,    NTOK * DD / 4);
    tf32_copy_kernel<<<(D3 * DD / 4 + 255) / 256, 256>>>(Wqkv, wqkvt, D3 * DD / 4);
    tf32_copy_kernel<<<(DD * DD / 4 + 255) / 256, 256>>>(Wo,   wot,   DD * DD / 4);
    tf32_copy_kernel<<<(2 * FF * DD / 4 + 255) / 256, 256>>>(W1, w1t,  2 * FF * DD / 4);
    tf32_copy_kernel<<<(DD * FF / 4 + 255) / 256, 256>>>(W2,   w2t,   DD * FF / 4);

    // 1) QKV projection
    gemm_pre_nt_bias<<<dim3(D3 / 128, NTOK / 128), 256, G3_SMEM>>>(
        xt, wqkvt, bqkv, qkv, NTOK, D3, DD);

    // 2) RoPE + tf32 rounding + fragment permutation of q,k
    rope_tf32_perm_kernel<<<(NTOK * D3 / 4) / 256, 256>>>(qkv, p, freqs);

    // 3) Flash attention (tensor cores), tf32 output
    flash_attn_tc2_kernel<<<dim3(SS / 64, HH, BB), 128, FA3_SMEM>>>(qkv, attn);

    // 4) Output projection
    gemm_pre_nt_bias<<<dim3(DD / 128, NTOK / 128), 256, G3_SMEM>>>(
        attn, wot, bo, proj, NTOK, DD, DD);

    // 5) h = LN(proj + x); also tf32 copy for W1 GEMM
    add_ln_kernel<<<NTOK, 256>>>(proj, x, gattn, battn, hbuf, ht);

    // 6) u = h @ W1^T + b1
    gemm_pre_nt_bias<<<dim3(2 * FF / 128, NTOK / 128), 256, G3_SMEM>>>(
        ht, w1t, b1, u, NTOK, 2 * FF, DD);

    // 7) m = gelu(a) * gate (tf32 output)
    gelu_gate_kernel<<<(NTOK * FF / 4) / 256, 256>>>(u, mbuf);

    // 8) m2 = m @ W2^T + b2
    gemm_pre_nt_bias<<<dim3(DD / 128, NTOK / 128), 256, G3_SMEM>>>(
        mbuf, w2t, b2, m2, NTOK, DD, FF);

    // 9) out = LN(m2 + h)
    add_ln_kernel<<<NTOK, 256>>>(m2, hbuf, gmlp, bmlp, out, nullptr);
}

// round 6
// speedup vs baseline: 5.4110x; 1.5830x over previous
#include <cuda_runtime.h>
#include <cuda_fp16.h>
#include <math.h>
#include <stdint.h>

// Problem constants
#define BB   2
#define SS   2048
#define DD   1024
#define HH   16
#define DH   64
#define FF   4096
#define NTOK (BB*SS)          // 4096 rows
#define D3   (3*DD)           // 3072

// ---------------------------------------------------------------------------
// Scratch (static device globals)
// ---------------------------------------------------------------------------
__device__ float  g_qkv [NTOK * D3];     // fp32, rope->tf32 in place
__device__ float  g_proj[NTOK * DD];
__device__ float  g_hbuf[NTOK * DD];
__device__ float  g_m2  [NTOK * DD];
// fp16 GEMM operands
__device__ __half g_xh   [NTOK * DD];
__device__ __half g_wqkvh[D3 * DD];
__device__ __half g_woh  [DD * DD];
__device__ __half g_w1h  [2 * FF * DD];
__device__ __half g_w2h  [DD * FF];
__device__ __half g_attnh[NTOK * DD];
__device__ __half g_hh   [NTOK * DD];
__device__ __half g_uh   [NTOK * 2 * FF];
__device__ __half g_mh   [NTOK * FF];

// ---------------------------------------------------------------------------
// helpers
// ---------------------------------------------------------------------------
__device__ __forceinline__ float f2tf32(float x) {
    uint32_t u;
    asm("cvt.rna.tf32.f32 %0, %1;" : "=r"(u) : "f"(x));
    return __uint_as_float(u);
}

__device__ __forceinline__ void mma_tf32(
    float& d0, float& d1, float& d2, float& d3,
    uint32_t a0, uint32_t a1, uint32_t a2, uint32_t a3,
    uint32_t b0, uint32_t b1)
{
    asm volatile(
        "mma.sync.aligned.m16n8k8.row.col.f32.tf32.tf32.f32 "
        "{%0,%1,%2,%3}, {%4,%5,%6,%7}, {%8,%9}, {%0,%1,%2,%3};"
        : "+f"(d0), "+f"(d1), "+f"(d2), "+f"(d3)
        : "r"(a0), "r"(a1), "r"(a2), "r"(a3), "r"(b0), "r"(b1));
}

__device__ __forceinline__ void mma_f16(
    float& d0, float& d1, float& d2, float& d3,
    uint32_t a0, uint32_t a1, uint32_t a2, uint32_t a3,
    uint32_t b0, uint32_t b1)
{
    asm volatile(
        "mma.sync.aligned.m16n8k16.row.col.f32.f16.f16.f32 "
        "{%0,%1,%2,%3}, {%4,%5,%6,%7}, {%8,%9}, {%0,%1,%2,%3};"
        : "+f"(d0), "+f"(d1), "+f"(d2), "+f"(d3)
        : "r"(a0), "r"(a1), "r"(a2), "r"(a3), "r"(b0), "r"(b1));
}

__device__ __forceinline__ uint32_t smem_u32(const void* p) {
    uint32_t a;
    asm("{ .reg .u64 t; cvta.to.shared.u64 t, %1; cvt.u32.u64 %0, t; }"
        : "=r"(a) : "l"(p));
    return a;
}

__device__ __forceinline__ void cp_async16(uint32_t s, const void* g) {
    asm volatile("cp.async.cg.shared.global [%0], [%1], 16;\n"
                 :: "r"(s), "l"(g));
}
__device__ __forceinline__ void cp_commit() {
    asm volatile("cp.async.commit_group;\n");
}

__device__ __forceinline__ void store2(float* C, size_t idx, float a, float b) {
    *(float2*)&C[idx] = make_float2(a, b);
}
__device__ __forceinline__ void store2(__half* C, size_t idx, float a, float b) {
    *(__half2*)&C[idx] = __floats2half2_rn(a, b);
}

// ---------------------------------------------------------------------------
// fp32 -> fp16 copy (RN), float4-read / 8B-write
// ---------------------------------------------------------------------------
__global__ void __launch_bounds__(256) h_copy_kernel(
    const float* __restrict__ s, __half* __restrict__ d, int n4)
{
    int i = blockIdx.x * blockDim.x + threadIdx.x;
    if (i < n4) {
        float4 v = ((const float4*)s)[i];
        __half2 h0 = __floats2half2_rn(v.x, v.y);
        __half2 h1 = __floats2half2_rn(v.z, v.w);
        ((__half2*)d)[2 * i]     = h0;
        ((__half2*)d)[2 * i + 1] = h1;
    }
}

// ---------------------------------------------------------------------------
// FP16 tensor-core GEMM: C = A @ W^T + bias.
// A:[M,K] half, W:[N,K] half. CTA 128x128, BK=32, 8 warps (2x4), warp 64x32.
// 3-stage cp.async pipeline; rows padded to 40 halves (conflict-free LDS).
// OutT = float or __half.
// ---------------------------------------------------------------------------
#define HSTR    40                        // halves per smem row
#define STAGE_H (2 * 128 * HSTR)          // halves per stage (A+B) = 10240
#define GH_SMEM (3 * STAGE_H * 2)         // bytes = 61440

template<typename OutT>
__global__ void __launch_bounds__(256) gemm_f16_nt_bias(
    const __half* __restrict__ A, const __half* __restrict__ W,
    const float* __restrict__ bias, OutT* __restrict__ C,
    int M, int N, int K)
{
    extern __shared__ __align__(16) char smc[];
    __half* smh = (__half*)smc;

    const int tid  = threadIdx.x;
    const int m0   = blockIdx.y * 128;
    const int n0   = blockIdx.x * 128;
    const int warp = tid >> 5;
    const int lane = tid & 31;
    const int g    = lane >> 2;
    const int t    = lane & 3;
    const int wm   = (warp >> 2) * 64;
    const int wn   = (warp & 3) * 32;

    const int lrow = tid >> 1;            // 0..127
    const int lc   = (tid & 1) * 16;      // 0 or 16 halves (32B)
    const __half* Ag = A + (size_t)(m0 + lrow) * K + lc;
    const __half* Wg = W + (size_t)(n0 + lrow) * K + lc;
    const uint32_t smb = smem_u32(smh);

    const int NK = K >> 5;                // BK = 32

    auto issue = [&](int kt) {
        const int buf = kt % 3;
        uint32_t dA = smb + (uint32_t)(buf * STAGE_H + lrow * HSTR + lc) * 2;
        uint32_t dB = dA + 128 * HSTR * 2;
        const __half* a = Ag + (size_t)kt * 32;
        const __half* w = Wg + (size_t)kt * 32;
        cp_async16(dA,      a);
        cp_async16(dA + 16, a + 8);
        cp_async16(dB,      w);
        cp_async16(dB + 16, w + 8);
        cp_commit();
    };

    uint32_t af0[4][4], bf0[4][2], af1[4][4], bf1[4][2];

    // fragment load for k-step ks (0/1) of stage buf; word stride = 20/row
    auto ldfrag = [&](int buf, int ks, uint32_t af[4][4], uint32_t bf[4][2]) {
        const uint32_t* Aw = (const uint32_t*)(smh + buf * STAGE_H);
        const uint32_t* Bw = Aw + 128 * (HSTR / 2);
        const int kb = ks * 8;            // word base within row
#pragma unroll
        for (int i = 0; i < 4; i++) {
            const int rb = wm + i * 16;
            af[i][0] = Aw[(rb + g    ) * 20 + kb + t    ];
            af[i][1] = Aw[(rb + g + 8) * 20 + kb + t    ];
            af[i][2] = Aw[(rb + g    ) * 20 + kb + t + 4];
            af[i][3] = Aw[(rb + g + 8) * 20 + kb + t + 4];
        }
#pragma unroll
        for (int j = 0; j < 4; j++) {
            const int cb = wn + j * 8 + g;
            bf[j][0] = Bw[cb * 20 + kb + t    ];
            bf[j][1] = Bw[cb * 20 + kb + t + 4];
        }
    };

    float acc[4][4][4];
#pragma unroll
    for (int i = 0; i < 4; i++)
#pragma unroll
        for (int j = 0; j < 4; j++)
#pragma unroll
            for (int r = 0; r < 4; r++) acc[i][j][r] = 0.f;

    auto mma16 = [&](uint32_t af[4][4], uint32_t bf[4][2]) {
#pragma unroll
        for (int j = 0; j < 4; j++)
#pragma unroll
            for (int i = 0; i < 4; i++)
                mma_f16(acc[i][j][0], acc[i][j][1], acc[i][j][2], acc[i][j][3],
                        af[i][0], af[i][1], af[i][2], af[i][3],
                        bf[j][0], bf[j][1]);
    };

    issue(0);
    issue(1);
    asm volatile("cp.async.wait_group 1;\n");
    __syncthreads();
    ldfrag(0, 0, af0, bf0);

    for (int kt = 0; kt < NK; kt++) {
        const int buf = kt % 3;
        ldfrag(buf, 1, af1, bf1);
        mma16(af0, bf0);
        const bool more2 = (kt + 2) < NK;
        if (more2) issue(kt + 2);
        mma16(af1, bf1);
        if (kt + 1 < NK) {
            if (more2) asm volatile("cp.async.wait_group 1;\n");
            else       asm volatile("cp.async.wait_group 0;\n");
            __syncthreads();
            ldfrag((kt + 1) % 3, 0, af0, bf0);
        }
    }

#pragma unroll
    for (int i = 0; i < 4; i++) {
        const int r0 = m0 + wm + i * 16 + g;
        const int r1 = r0 + 8;
#pragma unroll
        for (int j = 0; j < 4; j++) {
            const int col = n0 + wn + j * 8 + 2 * t;
            float2 bv = *(const float2*)&bias[col];
            store2(C, (size_t)r0 * N + col, acc[i][j][0] + bv.x, acc[i][j][1] + bv.y);
            store2(C, (size_t)r1 * N + col, acc[i][j][2] + bv.x, acc[i][j][3] + bv.y);
        }
    }
}

// ---------------------------------------------------------------------------
// RoPE + TF32 rounding + fragment-order permutation (q,k), unchanged from R5
// ---------------------------------------------------------------------------
__global__ void __launch_bounds__(256) rope_tf32_perm_kernel(
    float* __restrict__ qkv, const int* __restrict__ p,
    const float* __restrict__ freqs)
{
    const int idx4 = blockIdx.x * blockDim.x + threadIdx.x;
    const int per_row = D3 / 4;
    const int row = idx4 / per_row;
    const int c   = (idx4 - row * per_row) * 4;
    if (row >= NTOK) return;

    float* base = qkv + (size_t)row * D3 + c;
    float4 v = *(float4*)base;

    if (c < 2 * DD) {
        const float pos = (float)p[row];
        const int dh = c & 63;
        const int off = (dh < 32) ? 32 : -32;
        float4 o = *(const float4*)(base + off);
        float vv[4] = {v.x, v.y, v.z, v.w};
        float oo[4] = {o.x, o.y, o.z, o.w};
        const float qs = (c < DD) ? 0.125f : 1.0f;
#pragma unroll
        for (int j = 0; j < 4; j++) {
            float a = pos * freqs[dh + j];
            float sn, cs;
            __sincosf(a, &sn, &cs);
            vv[j] = f2tf32((vv[j] * cs + oo[j] * sn) * qs);
        }
        float* grp = qkv + (size_t)row * D3 + (c & ~7);
        const int p0 = c & 7;
#pragma unroll
        for (int j = 0; j < 4; j++) {
            const int pp = p0 + j;
            const int slot = (pp < 4) ? (pp << 1) : (((pp - 4) << 1) + 1);
            grp[slot] = vv[j];
        }
    } else {
        v = make_float4(f2tf32(v.x), f2tf32(v.y), f2tf32(v.z), f2tf32(v.w));
        *(float4*)base = v;
    }
}

// ---------------------------------------------------------------------------
// Flash attention (tf32 MMA), output fp16 (feeds Wo GEMM)
// ---------------------------------------------------------------------------
#define AT_K    4608
#define AT_KSZ  2304
#define AT_V    (AT_K + 2*AT_KSZ)
#define AT_VSZ  2304
#define AT_TOT  (AT_V + 2*AT_VSZ)
#define FA3_SMEM (AT_TOT * (int)sizeof(float))

__global__ void __launch_bounds__(128, 4) flash_attn_tc2_kernel(
    const float* __restrict__ qkv, __half* __restrict__ O)
{
    extern __shared__ float sm[];
    const int tid  = threadIdx.x;
    const int warp = tid >> 5;
    const int lane = tid & 31;
    const int g = lane >> 2;
    const int t = lane & 3;
    const int wq = warp * 16;

    const int qt = blockIdx.x, h = blockIdx.y, b = blockIdx.z;
    const int rowBase = b * SS + qt * 64;
    const int cq = h * DH;
    const int bS = b * SS;

    float* Qs  = sm;
    float* Psw = sm + warp * (16 * 68);
    const uint32_t smb = smem_u32(sm);

    for (int i = tid; i < 64 * 16; i += 128) {
        int r = i >> 4, q4 = (i & 15) << 2;
        float4 v = *(const float4*)&qkv[(size_t)(rowBase + r) * D3 + cq + q4];
        *(float4*)&Qs[r * 72 + q4] = v;
    }

    auto issue_tile = [&](int kt, int buf) {
        const float* gK = qkv + (size_t)(bS + kt * 32) * D3 + cq + DD;
        const uint32_t sK = smb + (AT_K + buf * AT_KSZ) * 4;
        const uint32_t sV = smb + (AT_V + buf * AT_VSZ) * 4;
#pragma unroll
        for (int it = 0; it < 4; it++) {
            int i = tid + it * 128;
            int r = i >> 4, q4 = (i & 15) << 2;
            const float* gp = gK + (size_t)r * D3 + q4;
            cp_async16(sK + (r * 72 + q4) * 4, gp);
            cp_async16(sV + (r * 72 + q4) * 4, gp + DD);
        }
        cp_commit();
    };
    issue_tile(0, 0);

    __syncthreads();

    uint32_t qf[8][4];
#pragma unroll
    for (int kk8 = 0; kk8 < 8; kk8++) {
        const int kk = kk8 * 8;
        float2 q0 = *(const float2*)&Qs[(wq + g    ) * 72 + kk + 2 * t];
        float2 q1 = *(const float2*)&Qs[(wq + g + 8) * 72 + kk + 2 * t];
        qf[kk8][0] = __float_as_uint(q0.x);
        qf[kk8][1] = __float_as_uint(q1.x);
        qf[kk8][2] = __float_as_uint(q0.y);
        qf[kk8][3] = __float_as_uint(q1.y);
    }
    __syncwarp();

    float m_i[2] = {-1e30f, -1e30f};
    float l_i[2] = {0.f, 0.f};
    float acc[8][4];
#pragma unroll
    for (int d = 0; d < 8; d++)
#pragma unroll
        for (int r = 0; r < 4; r++) acc[d][r] = 0.f;

    const int NT = SS / 32;
    for (int kt = 0; kt < NT; kt++) {
        const int cur = kt & 1;
        if (kt + 1 < NT) {
            issue_tile(kt + 1, 1 - cur);
            asm volatile("cp.async.wait_group 1;\n");
        } else {
            asm volatile("cp.async.wait_group 0;\n");
        }
        __syncthreads();

        const float* Ks = sm + AT_K + cur * AT_KSZ;
        const float* Vs = sm + AT_V + cur * AT_VSZ;

        float s4[4][4];
#pragma unroll
        for (int n = 0; n < 4; n++)
#pragma unroll
            for (int r = 0; r < 4; r++) s4[n][r] = 0.f;

#pragma unroll
        for (int kk8 = 0; kk8 < 8; kk8++) {
            const int kk = kk8 * 8;
#pragma unroll
            for (int n = 0; n < 4; n++) {
                float2 bv = *(const float2*)&Ks[(n * 8 + g) * 72 + kk + 2 * t];
                mma_tf32(s4[n][0], s4[n][1], s4[n][2], s4[n][3],
                         qf[kk8][0], qf[kk8][1], qf[kk8][2], qf[kk8][3],
                         __float_as_uint(bv.x), __float_as_uint(bv.y));
            }
        }

        float mx0 = -1e30f, mx1 = -1e30f;
#pragma unroll
        for (int n = 0; n < 4; n++) {
            mx0 = fmaxf(mx0, fmaxf(s4[n][0], s4[n][1]));
            mx1 = fmaxf(mx1, fmaxf(s4[n][2], s4[n][3]));
        }
        mx0 = fmaxf(mx0, __shfl_xor_sync(0xffffffffu, mx0, 1));
        mx0 = fmaxf(mx0, __shfl_xor_sync(0xffffffffu, mx0, 2));
        mx1 = fmaxf(mx1, __shfl_xor_sync(0xffffffffu, mx1, 1));
        mx1 = fmaxf(mx1, __shfl_xor_sync(0xffffffffu, mx1, 2));

        float mn0 = fmaxf(m_i[0], mx0);
        float mn1 = fmaxf(m_i[1], mx1);
        float cr0 = __expf(m_i[0] - mn0);
        float cr1 = __expf(m_i[1] - mn1);

        float sum0 = 0.f, sum1 = 0.f;
#pragma unroll
        for (int n = 0; n < 4; n++) {
            s4[n][0] = __expf(s4[n][0] - mn0);
            s4[n][1] = __expf(s4[n][1] - mn0);
            s4[n][2] = __expf(s4[n][2] - mn1);
            s4[n][3] = __expf(s4[n][3] - mn1);
            sum0 += s4[n][0] + s4[n][1];
            sum1 += s4[n][2] + s4[n][3];
        }
        sum0 += __shfl_xor_sync(0xffffffffu, sum0, 1);
        sum0 += __shfl_xor_sync(0xffffffffu, sum0, 2);
        sum1 += __shfl_xor_sync(0xffffffffu, sum1, 1);
        sum1 += __shfl_xor_sync(0xffffffffu, sum1, 2);

        l_i[0] = l_i[0] * cr0 + sum0;
        l_i[1] = l_i[1] * cr1 + sum1;
        m_i[0] = mn0; m_i[1] = mn1;

#pragma unroll
        for (int d = 0; d < 8; d++) {
            acc[d][0] *= cr0; acc[d][1] *= cr0;
            acc[d][2] *= cr1; acc[d][3] *= cr1;
        }

#pragma unroll
        for (int n = 0; n < 4; n++) {
            *(float2*)&Psw[ g      * 68 + n * 8 + 2 * t] =
                make_float2(f2tf32(s4[n][0]), f2tf32(s4[n][1]));
            *(float2*)&Psw[(g + 8) * 68 + n * 8 + 2 * t] =
                make_float2(f2tf32(s4[n][2]), f2tf32(s4[n][3]));
        }
        __syncwarp();

#pragma unroll
        for (int kk8 = 0; kk8 < 4; kk8++) {
            const int kk = kk8 * 8;
            uint32_t a0 = __float_as_uint(Psw[ g      * 68 + kk + t    ]);
            uint32_t a1 = __float_as_uint(Psw[(g + 8) * 68 + kk + t    ]);
            uint32_t a2 = __float_as_uint(Psw[ g      * 68 + kk + t + 4]);
            uint32_t a3 = __float_as_uint(Psw[(g + 8) * 68 + kk + t + 4]);
#pragma unroll
            for (int d = 0; d < 8; d++) {
                uint32_t b0 = __float_as_uint(Vs[(kk + t    ) * 72 + d * 8 + g]);
                uint32_t b1 = __float_as_uint(Vs[(kk + t + 4) * 72 + d * 8 + g]);
                mma_tf32(acc[d][0], acc[d][1], acc[d][2], acc[d][3],
                         a0, a1, a2, a3, b0, b1);
            }
        }
        __syncthreads();
    }

    const float inv0 = 1.0f / l_i[0];
    const float inv1 = 1.0f / l_i[1];
    const int r0 = rowBase + wq + g;
    const int r1 = r0 + 8;
#pragma unroll
    for (int d = 0; d < 8; d++) {
        const int col = cq + d * 8 + 2 * t;
        *(__half2*)&O[(size_t)r0 * DD + col] =
            __floats2half2_rn(acc[d][0] * inv0, acc[d][1] * inv0);
        *(__half2*)&O[(size_t)r1 * DD + col] =
            __floats2half2_rn(acc[d][2] * inv1, acc[d][3] * inv1);
    }
}

// ---------------------------------------------------------------------------
// Fused residual add + LayerNorm (+ optional fp16 copy for next GEMM)
// ---------------------------------------------------------------------------
__global__ void __launch_bounds__(256) add_ln_kernel(
    const float* __restrict__ A, const float* __restrict__ R,
    const float* __restrict__ g, const float* __restrict__ be,
    float* __restrict__ out, __half* __restrict__ out_h)
{
    __shared__ float red[8];
    const int row = blockIdx.x, tid = threadIdx.x;
    const int lane = tid & 31, wid = tid >> 5;

    float4 a = ((const float4*)(A + (size_t)row * DD))[tid];
    float4 r = ((const float4*)(R + (size_t)row * DD))[tid];
    float4 t = make_float4(a.x + r.x, a.y + r.y, a.z + r.z, a.w + r.w);

    float ssum = t.x + t.y + t.z + t.w;
#pragma unroll
    for (int o = 16; o; o >>= 1) ssum += __shfl_xor_sync(0xffffffffu, ssum, o);
    if (lane == 0) red[wid] = ssum;
    __syncthreads();
    float mean = (red[0] + red[1] + red[2] + red[3] +
                  red[4] + red[5] + red[6] + red[7]) * (1.0f / DD);
    __syncthreads();

    float4 d = make_float4(t.x - mean, t.y - mean, t.z - mean, t.w - mean);
    float sq = d.x * d.x + d.y * d.y + d.z * d.z + d.w * d.w;
#pragma unroll
    for (int o = 16; o; o >>= 1) sq += __shfl_xor_sync(0xffffffffu, sq, o);
    if (lane == 0) red[wid] = sq;
    __syncthreads();
    float var = (red[0] + red[1] + red[2] + red[3] +
                 red[4] + red[5] + red[6] + red[7]) * (1.0f / DD);
    float rs = rsqrtf(var + 1e-5f);

    float4 gv = ((const float4*)g)[tid];
    float4 bv = ((const float4*)be)[tid];
    float4 o4 = make_float4(d.x * rs * gv.x + bv.x,
                            d.y * rs * gv.y + bv.y,
                            d.z * rs * gv.z + bv.z,
                            d.w * rs * gv.w + bv.w);
    ((float4*)(out + (size_t)row * DD))[tid] = o4;
    if (out_h) {
        __half2* oh = (__half2*)(out_h + (size_t)row * DD);
        oh[2 * tid]     = __floats2half2_rn(o4.x, o4.y);
        oh[2 * tid + 1] = __floats2half2_rn(o4.z, o4.w);
    }
}

// ---------------------------------------------------------------------------
// GELU(exact) * gate, fp16 in / fp16 out
// ---------------------------------------------------------------------------
__global__ void __launch_bounds__(256) gelu_gate_kernel(
    const __half* __restrict__ u, __half* __restrict__ m)
{
    int gid = blockIdx.x * blockDim.x + threadIdx.x;
    const int f4_per_row = FF / 4;
    int row  = gid / f4_per_row;
    int col4 = gid - row * f4_per_row;
    if (row >= NTOK) return;

    const __half* base = u + (size_t)row * 2 * FF;
    __half2 a01 = ((const __half2*)base)[2 * col4];
    __half2 a23 = ((const __half2*)base)[2 * col4 + 1];
    __half2 g01 = ((const __half2*)(base + FF))[2 * col4];
    __half2 g23 = ((const __half2*)(base + FF))[2 * col4 + 1];

    float2 af0 = __half22float2(a01), af1 = __half22float2(a23);
    float2 gf0 = __half22float2(g01), gf1 = __half22float2(g23);

    const float is2 = 0.70710678118654752f;
    float o0 = 0.5f * af0.x * (1.0f + erff(af0.x * is2)) * gf0.x;
    float o1 = 0.5f * af0.y * (1.0f + erff(af0.y * is2)) * gf0.y;
    float o2 = 0.5f * af1.x * (1.0f + erff(af1.x * is2)) * gf1.x;
    float o3 = 0.5f * af1.y * (1.0f + erff(af1.y * is2)) * gf1.y;

    __half2* mo = (__half2*)(m + (size_t)row * FF);
    mo[2 * col4]     = __floats2half2_rn(o0, o1);
    mo[2 * col4 + 1] = __floats2half2_rn(o2, o3);
}

// ---------------------------------------------------------------------------
// kernel_launch
// ---------------------------------------------------------------------------
extern "C" void kernel_launch(void* const* d_in, const int* in_sizes, int n_in,
                              void* d_out, int out_size)
{
    const float* x      = (const float*)d_in[0];
    const int*   p      = (const int*)  d_in[1];
    const float* Wqkv   = (const float*)d_in[2];
    const float* bqkv   = (const float*)d_in[3];
    const float* Wo     = (const float*)d_in[4];
    const float* bo     = (const float*)d_in[5];
    const float* gattn  = (const float*)d_in[6];
    const float* battn  = (const float*)d_in[7];
    const float* W1     = (const float*)d_in[8];
    const float* b1     = (const float*)d_in[9];
    const float* W2     = (const float*)d_in[10];
    const float* b2     = (const float*)d_in[11];
    const float* gmlp   = (const float*)d_in[12];
    const float* bmlp   = (const float*)d_in[13];
    const float* freqs  = (const float*)d_in[14];
    float* out = (float*)d_out;

    float *qkv, *proj, *hbuf, *m2;
    __half *xh, *wqkvh, *woh, *w1h, *w2h, *attnh, *hh, *uh, *mh;
    cudaGetSymbolAddress((void**)&qkv,  g_qkv);
    cudaGetSymbolAddress((void**)&proj, g_proj);
    cudaGetSymbolAddress((void**)&hbuf, g_hbuf);
    cudaGetSymbolAddress((void**)&m2,   g_m2);
    cudaGetSymbolAddress((void**)&xh,    g_xh);
    cudaGetSymbolAddress((void**)&wqkvh, g_wqkvh);
    cudaGetSymbolAddress((void**)&woh,   g_woh);
    cudaGetSymbolAddress((void**)&w1h,   g_w1h);
    cudaGetSymbolAddress((void**)&w2h,   g_w2h);
    cudaGetSymbolAddress((void**)&attnh, g_attnh);
    cudaGetSymbolAddress((void**)&hh,    g_hh);
    cudaGetSymbolAddress((void**)&uh,    g_uh);
    cudaGetSymbolAddress((void**)&mh,    g_mh);

    cudaFuncSetAttribute(flash_attn_tc2_kernel,
                         cudaFuncAttributeMaxDynamicSharedMemorySize, FA3_SMEM);
    cudaFuncSetAttribute(gemm_f16_nt_bias<float>,
                         cudaFuncAttributeMaxDynamicSharedMemorySize, GH_SMEM);
    cudaFuncSetAttribute(gemm_f16_nt_bias<__half>,
                         cudaFuncAttributeMaxDynamicSharedMemorySize, GH_SMEM);

    // 0) fp16 pre-conversion of GEMM inputs
    h_copy_kernel<<<(NTOK * DD / 4 + 255) / 256, 256>>>(x,    xh,    NTOK * DD / 4);
    h_copy_kernel<<<(D3 * DD / 4 + 255) / 256, 256>>>(Wqkv, wqkvh, D3 * DD / 4);
    h_copy_kernel<<<(DD * DD / 4 + 255) / 256, 256>>>(Wo,   woh,   DD * DD / 4);
    h_copy_kernel<<<(2 * FF * DD / 4 + 255) / 256, 256>>>(W1, w1h,  2 * FF * DD / 4);
    h_copy_kernel<<<(DD * FF / 4 + 255) / 256, 256>>>(W2,   w2h,   DD * FF / 4);

    // 1) QKV projection (fp16 TC)
    gemm_f16_nt_bias<float><<<dim3(D3 / 128, NTOK / 128), 256, GH_SMEM>>>(
        xh, wqkvh, bqkv, qkv, NTOK, D3, DD);

    // 2) RoPE + tf32 rounding + fragment permutation of q,k
    rope_tf32_perm_kernel<<<(NTOK * D3 / 4) / 256, 256>>>(qkv, p, freqs);

    // 3) Flash attention (tf32 TC), fp16 output
    flash_attn_tc2_kernel<<<dim3(SS / 64, HH, BB), 128, FA3_SMEM>>>(qkv, attnh);

    // 4) Output projection
    gemm_f16_nt_bias<float><<<dim3(DD / 128, NTOK / 128), 256, GH_SMEM>>>(
        attnh, woh, bo, proj, NTOK, DD, DD);

    // 5) h = LN(proj + x); fp16 copy for W1 GEMM
    add_ln_kernel<<<NTOK, 256>>>(proj, x, gattn, battn, hbuf, hh);

    // 6) u = h @ W1^T + b1 (fp16 output)
    gemm_f16_nt_bias<__half><<<dim3(2 * FF / 128, NTOK / 128), 256, GH_SMEM>>>(
        hh, w1h, b1, uh, NTOK, 2 * FF, DD);

    // 7) m = gelu(a) * gate (fp16 in/out)
    gelu_gate_kernel<<<(NTOK * FF / 4) / 256, 256>>>(uh, mh);

    // 8) m2 = m @ W2^T + b2
    gemm_f16_nt_bias<float><<<dim3(DD / 128, NTOK / 128), 256, GH_SMEM>>>(
        mh, w2h, b2, m2, NTOK, DD, FF);

    // 9) out = LN(m2 + h)
    add_ln_kernel<<<NTOK, 256>>>(m2, hbuf, gmlp, bmlp, out, nullptr);
}

// round 8
// speedup vs baseline: 5.7384x; 1.0605x over previous
#include <cuda_runtime.h>
#include <cuda_fp16.h>
#include <math.h>
#include <stdint.h>
#include <string.h>

// Problem constants
#define BB   2
#define SS   2048
#define DD   1024
#define HH   16
#define DH   64
#define FF   4096
#define NTOK (BB*SS)          // 4096 rows
#define D3   (3*DD)           // 3072

// ---------------------------------------------------------------------------
// Scratch (static device globals)
// ---------------------------------------------------------------------------
__device__ float  g_qkv [NTOK * D3];     // fp32 QKV GEMM output
__device__ float  g_proj[NTOK * DD];
__device__ float  g_hbuf[NTOK * DD];
__device__ float  g_m2  [NTOK * DD];
// fp16 operands
__device__ __half g_xh   [NTOK * DD];
__device__ __half g_wqkvh[D3 * DD];
__device__ __half g_woh  [DD * DD];
__device__ __half g_w1h  [2 * FF * DD];
__device__ __half g_w2h  [DD * FF];
__device__ __half g_attnh[NTOK * DD];
__device__ __half g_hh   [NTOK * DD];
__device__ __half g_uh   [NTOK * 2 * FF];
__device__ __half g_mh   [NTOK * FF];
// fp16 attention inputs
__device__ __half g_qh   [NTOK * DD];            // RoPE'd, scaled q
__device__ __half g_kh   [NTOK * DD];            // RoPE'd k
__device__ __half g_vth  [BB * HH * DH * SS];    // V transposed per (b,h): [d][s]

// ---------------------------------------------------------------------------
// helpers
// ---------------------------------------------------------------------------
__device__ __forceinline__ uint32_t h2_as_u32(__half2 h) {
    uint32_t u;
    memcpy(&u, &h, 4);
    return u;
}

__device__ __forceinline__ void mma_f16(
    float& d0, float& d1, float& d2, float& d3,
    uint32_t a0, uint32_t a1, uint32_t a2, uint32_t a3,
    uint32_t b0, uint32_t b1)
{
    asm volatile(
        "mma.sync.aligned.m16n8k16.row.col.f32.f16.f16.f32 "
        "{%0,%1,%2,%3}, {%4,%5,%6,%7}, {%8,%9}, {%0,%1,%2,%3};"
        : "+f"(d0), "+f"(d1), "+f"(d2), "+f"(d3)
        : "r"(a0), "r"(a1), "r"(a2), "r"(a3), "r"(b0), "r"(b1));
}

__device__ __forceinline__ uint32_t smem_u32(const void* p) {
    uint32_t a;
    asm("{ .reg .u64 t; cvta.to.shared.u64 t, %1; cvt.u32.u64 %0, t; }"
        : "=r"(a) : "l"(p));
    return a;
}

__device__ __forceinline__ void cp_async16(uint32_t s, const void* g) {
    asm volatile("cp.async.cg.shared.global [%0], [%1], 16;\n"
                 :: "r"(s), "l"(g));
}
__device__ __forceinline__ void cp_commit() {
    asm volatile("cp.async.commit_group;\n");
}

__device__ __forceinline__ void store2(float* C, size_t idx, float a, float b) {
    *(float2*)&C[idx] = make_float2(a, b);
}
__device__ __forceinline__ void store2(__half* C, size_t idx, float a, float b) {
    *(__half2*)&C[idx] = __floats2half2_rn(a, b);
}

// ---------------------------------------------------------------------------
// fp32 -> fp16 copy
// ---------------------------------------------------------------------------
__global__ void __launch_bounds__(256) h_copy_kernel(
    const float* __restrict__ s, __half* __restrict__ d, int n4)
{
    int i = blockIdx.x * blockDim.x + threadIdx.x;
    if (i < n4) {
        float4 v = ((const float4*)s)[i];
        ((__half2*)d)[2 * i]     = __floats2half2_rn(v.x, v.y);
        ((__half2*)d)[2 * i + 1] = __floats2half2_rn(v.z, v.w);
    }
}

// ---------------------------------------------------------------------------
// FP16 tensor-core GEMM: C = A @ W^T + bias
// ---------------------------------------------------------------------------
#define HSTR    40
#define STAGE_H (2 * 128 * HSTR)
#define GH_SMEM (3 * STAGE_H * 2)

template<typename OutT>
__global__ void __launch_bounds__(256) gemm_f16_nt_bias(
    const __half* __restrict__ A, const __half* __restrict__ W,
    const float* __restrict__ bias, OutT* __restrict__ C,
    int M, int N, int K)
{
    extern __shared__ __align__(16) char smc[];
    __half* smh = (__half*)smc;

    const int tid  = threadIdx.x;
    const int m0   = blockIdx.y * 128;
    const int n0   = blockIdx.x * 128;
    const int warp = tid >> 5;
    const int lane = tid & 31;
    const int g    = lane >> 2;
    const int t    = lane & 3;
    const int wm   = (warp >> 2) * 64;
    const int wn   = (warp & 3) * 32;

    const int lrow = tid >> 1;
    const int lc   = (tid & 1) * 16;
    const __half* Ag = A + (size_t)(m0 + lrow) * K + lc;
    const __half* Wg = W + (size_t)(n0 + lrow) * K + lc;
    const uint32_t smb = smem_u32(smh);

    const int NK = K >> 5;

    auto issue = [&](int kt) {
        const int buf = kt % 3;
        uint32_t dA = smb + (uint32_t)(buf * STAGE_H + lrow * HSTR + lc) * 2;
        uint32_t dB = dA + 128 * HSTR * 2;
        const __half* a = Ag + (size_t)kt * 32;
        const __half* w = Wg + (size_t)kt * 32;
        cp_async16(dA,      a);
        cp_async16(dA + 16, a + 8);
        cp_async16(dB,      w);
        cp_async16(dB + 16, w + 8);
        cp_commit();
    };

    uint32_t af0[4][4], bf0[4][2], af1[4][4], bf1[4][2];

    auto ldfrag = [&](int buf, int ks, uint32_t af[4][4], uint32_t bf[4][2]) {
        const uint32_t* Aw = (const uint32_t*)(smh + buf * STAGE_H);
        const uint32_t* Bw = Aw + 128 * (HSTR / 2);
        const int kb = ks * 8;
#pragma unroll
        for (int i = 0; i < 4; i++) {
            const int rb = wm + i * 16;
            af[i][0] = Aw[(rb + g    ) * 20 + kb + t    ];
            af[i][1] = Aw[(rb + g + 8) * 20 + kb + t    ];
            af[i][2] = Aw[(rb + g    ) * 20 + kb + t + 4];
            af[i][3] = Aw[(rb + g + 8) * 20 + kb + t + 4];
        }
#pragma unroll
        for (int j = 0; j < 4; j++) {
            const int cb = wn + j * 8 + g;
            bf[j][0] = Bw[cb * 20 + kb + t    ];
            bf[j][1] = Bw[cb * 20 + kb + t + 4];
        }
    };

    float acc[4][4][4];
#pragma unroll
    for (int i = 0; i < 4; i++)
#pragma unroll
        for (int j = 0; j < 4; j++)
#pragma unroll
            for (int r = 0; r < 4; r++) acc[i][j][r] = 0.f;

    auto mma16 = [&](uint32_t af[4][4], uint32_t bf[4][2]) {
#pragma unroll
        for (int j = 0; j < 4; j++)
#pragma unroll
            for (int i = 0; i < 4; i++)
                mma_f16(acc[i][j][0], acc[i][j][1], acc[i][j][2], acc[i][j][3],
                        af[i][0], af[i][1], af[i][2], af[i][3],
                        bf[j][0], bf[j][1]);
    };

    issue(0);
    issue(1);
    asm volatile("cp.async.wait_group 1;\n");
    __syncthreads();
    ldfrag(0, 0, af0, bf0);

    for (int kt = 0; kt < NK; kt++) {
        const int buf = kt % 3;
        ldfrag(buf, 1, af1, bf1);
        mma16(af0, bf0);
        const bool more2 = (kt + 2) < NK;
        if (more2) issue(kt + 2);
        mma16(af1, bf1);
        if (kt + 1 < NK) {
            if (more2) asm volatile("cp.async.wait_group 1;\n");
            else       asm volatile("cp.async.wait_group 0;\n");
            __syncthreads();
            ldfrag((kt + 1) % 3, 0, af0, bf0);
        }
    }

#pragma unroll
    for (int i = 0; i < 4; i++) {
        const int r0 = m0 + wm + i * 16 + g;
        const int r1 = r0 + 8;
#pragma unroll
        for (int j = 0; j < 4; j++) {
            const int col = n0 + wn + j * 8 + 2 * t;
            float2 bv = *(const float2*)&bias[col];
            store2(C, (size_t)r0 * N + col, acc[i][j][0] + bv.x, acc[i][j][1] + bv.y);
            store2(C, (size_t)r1 * N + col, acc[i][j][2] + bv.x, acc[i][j][3] + bv.y);
        }
    }
}

// ---------------------------------------------------------------------------
// RoPE -> fp16 attention operands.
// Reads fp32 qkv; writes qh (rotated, scaled), kh (rotated), vth (transposed).
// ---------------------------------------------------------------------------
__global__ void __launch_bounds__(256) rope_f16_kernel(
    const float* __restrict__ qkv, const int* __restrict__ p,
    const float* __restrict__ freqs,
    __half* __restrict__ qh, __half* __restrict__ kh,
    __half* __restrict__ vth)
{
    const int idx4 = blockIdx.x * blockDim.x + threadIdx.x;
    const int per_row = D3 / 4;                  // 768
    const int row = idx4 / per_row;
    const int c   = (idx4 - row * per_row) * 4;
    if (row >= NTOK) return;

    const float* base = qkv + (size_t)row * D3 + c;
    float4 v = *(const float4*)base;

    if (c < 2 * DD) {                            // q or k: RoPE
        const float pos = (float)p[row];
        const int dh = c & 63;
        const int off = (dh < 32) ? 32 : -32;
        float4 o = *(const float4*)(base + off);
        float vv[4] = {v.x, v.y, v.z, v.w};
        float oo[4] = {o.x, o.y, o.z, o.w};
        const bool isq = (c < DD);
        const float qs = isq ? 0.125f : 1.0f;
#pragma unroll
        for (int j = 0; j < 4; j++) {
            float a = pos * freqs[dh + j];
            float sn, cs;
            __sincosf(a, &sn, &cs);
            vv[j] = (vv[j] * cs + oo[j] * sn) * qs;
        }
        __half* dst = isq ? (qh + (size_t)row * DD + c)
                          : (kh + (size_t)row * DD + (c - DD));
        *(__half2*)(dst)     = __floats2half2_rn(vv[0], vv[1]);
        *(__half2*)(dst + 2) = __floats2half2_rn(vv[2], vv[3]);
    } else {                                     // v: transpose to [b,h][d][s]
        const int cd = c - 2 * DD;               // 0..1023
        const int h  = cd >> 6;
        const int d0 = cd & 63;
        const int b  = row / SS;
        const int s  = row - b * SS;
        __half* dst = vth + ((size_t)(b * HH + h) * DH) * SS + s;
        dst[(size_t)(d0 + 0) * SS] = __float2half_rn(v.x);
        dst[(size_t)(d0 + 1) * SS] = __float2half_rn(v.y);
        dst[(size_t)(d0 + 2) * SS] = __float2half_rn(v.z);
        dst[(size_t)(d0 + 3) * SS] = __float2half_rn(v.w);
    }
}

// ---------------------------------------------------------------------------
// Flash attention, fp16 mma (m16n8k16). Block: 64 q x 1 head, 4 warps.
// 32-key tiles, cp.async double-buffered K and VT. P overlays Q smem.
// smem (halves): Qs[64*72], Ks[2][32*72], VTs[2][64*40]   = 28672 B
// ---------------------------------------------------------------------------
#define FH_Q    0
#define FH_K    (64*72)                   // 4608
#define FH_KSZ  (32*72)                   // 2304
#define FH_VT   (FH_K + 2*FH_KSZ)         // 9216
#define FH_VTSZ (64*40)                   // 2560
#define FH_TOT  (FH_VT + 2*FH_VTSZ)       // 14336 halves
#define FH_SMEM (FH_TOT * 2)              // 28672 bytes

__global__ void __launch_bounds__(128) flash_attn_f16_kernel(
    const __half* __restrict__ qh, const __half* __restrict__ kh,
    const __half* __restrict__ vth, __half* __restrict__ O)
{
    extern __shared__ __align__(16) char smc[];
    __half* smh = (__half*)smc;
    const int tid  = threadIdx.x;
    const int warp = tid >> 5;
    const int lane = tid & 31;
    const int g = lane >> 2;
    const int t = lane & 3;
    const int wq = warp * 16;

    const int qt = blockIdx.x, h = blockIdx.y, b = blockIdx.z;
    const int rowBase = b * SS + qt * 64;
    const int cq = h * DH;
    const uint32_t smb = smem_u32(smh);
    const __half* vbh = vth + (size_t)(b * HH + h) * DH * SS;

    // ---- load Q tile (64 x 64 halves, stride 72) ----
    for (int i = tid; i < 64 * 8; i += 128) {
        int r = i >> 3, ch = (i & 7) * 8;
        *(uint4*)&smh[FH_Q + r * 72 + ch] =
            *(const uint4*)&qh[(size_t)(rowBase + r) * DD + cq + ch];
    }

    // ---- K/V prefetch ----
    auto issue_tile = [&](int kt, int buf) {
        const __half* gK = kh + (size_t)(b * SS + kt * 32) * DD + cq;
        const uint32_t sK = smb + (FH_K + buf * FH_KSZ) * 2;
#pragma unroll
        for (int it = 0; it < 2; it++) {
            int i = tid + it * 128;       // 0..255
            int r = i >> 3, ch = (i & 7) * 8;
            cp_async16(sK + (r * 72 + ch) * 2, gK + (size_t)r * DD + ch);
        }
        const __half* gV = vbh + (size_t)kt * 32;
        const uint32_t sV = smb + (FH_VT + buf * FH_VTSZ) * 2;
#pragma unroll
        for (int it = 0; it < 2; it++) {
            int i = tid + it * 128;
            int r = i >> 2, ch = (i & 3) * 8;
            cp_async16(sV + (r * 40 + ch) * 2, gV + (size_t)r * SS + ch);
        }
        cp_commit();
    };
    issue_tile(0, 0);

    __syncthreads();

    // ---- Q fragments (4 k16-steps) ----
    uint32_t qf[4][4];
    {
        const uint32_t* Qw = (const uint32_t*)(smh + FH_Q);
#pragma unroll
        for (int ks = 0; ks < 4; ks++) {
            const int kb = ks * 8;
            qf[ks][0] = Qw[(wq + g    ) * 36 + kb + t    ];
            qf[ks][1] = Qw[(wq + g + 8) * 36 + kb + t    ];
            qf[ks][2] = Qw[(wq + g    ) * 36 + kb + t + 4];
            qf[ks][3] = Qw[(wq + g + 8) * 36 + kb + t + 4];
        }
    }

    uint32_t* Pw = (uint32_t*)(smh) + warp * (16 * 20);  // P overlay: 16x40 halves

    float m_i[2] = {-1e30f, -1e30f};
    float l_i[2] = {0.f, 0.f};
    float acc[8][4];
#pragma unroll
    for (int d = 0; d < 8; d++)
#pragma unroll
        for (int r = 0; r < 4; r++) acc[d][r] = 0.f;

    const int NT = SS / 32;   // 64
    for (int kt = 0; kt < NT; kt++) {
        const int cur = kt & 1;
        if (kt + 1 < NT) {
            issue_tile(kt + 1, 1 - cur);
            asm volatile("cp.async.wait_group 1;\n");
        } else {
            asm volatile("cp.async.wait_group 0;\n");
        }
        __syncthreads();

        const uint32_t* Kw  = (const uint32_t*)(smh + FH_K  + cur * FH_KSZ);
        const uint32_t* VTw = (const uint32_t*)(smh + FH_VT + cur * FH_VTSZ);

        // ---- S = Q K^T : 16 x 32 per warp, 4 ksteps x 4 n ----
        float s4[4][4];
#pragma unroll
        for (int n = 0; n < 4; n++)
#pragma unroll
            for (int r = 0; r < 4; r++) s4[n][r] = 0.f;

#pragma unroll
        for (int ks = 0; ks < 4; ks++) {
            const int kb = ks * 8;
#pragma unroll
            for (int n = 0; n < 4; n++) {
                uint32_t b0 = Kw[(n * 8 + g) * 36 + kb + t    ];
                uint32_t b1 = Kw[(n * 8 + g) * 36 + kb + t + 4];
                mma_f16(s4[n][0], s4[n][1], s4[n][2], s4[n][3],
                        qf[ks][0], qf[ks][1], qf[ks][2], qf[ks][3], b0, b1);
            }
        }

        // ---- online softmax (rows wq+g, wq+g+8) ----
        float mx0 = -1e30f, mx1 = -1e30f;
#pragma unroll
        for (int n = 0; n < 4; n++) {
            mx0 = fmaxf(mx0, fmaxf(s4[n][0], s4[n][1]));
            mx1 = fmaxf(mx1, fmaxf(s4[n][2], s4[n][3]));
        }
        mx0 = fmaxf(mx0, __shfl_xor_sync(0xffffffffu, mx0, 1));
        mx0 = fmaxf(mx0, __shfl_xor_sync(0xffffffffu, mx0, 2));
        mx1 = fmaxf(mx1, __shfl_xor_sync(0xffffffffu, mx1, 1));
        mx1 = fmaxf(mx1, __shfl_xor_sync(0xffffffffu, mx1, 2));

        float mn0 = fmaxf(m_i[0], mx0);
        float mn1 = fmaxf(m_i[1], mx1);
        float cr0 = __expf(m_i[0] - mn0);
        float cr1 = __expf(m_i[1] - mn1);

        float sum0 = 0.f, sum1 = 0.f;
#pragma unroll
        for (int n = 0; n < 4; n++) {
            s4[n][0] = __expf(s4[n][0] - mn0);
            s4[n][1] = __expf(s4[n][1] - mn0);
            s4[n][2] = __expf(s4[n][2] - mn1);
            s4[n][3] = __expf(s4[n][3] - mn1);
            sum0 += s4[n][0] + s4[n][1];
            sum1 += s4[n][2] + s4[n][3];
        }
        sum0 += __shfl_xor_sync(0xffffffffu, sum0, 1);
        sum0 += __shfl_xor_sync(0xffffffffu, sum0, 2);
        sum1 += __shfl_xor_sync(0xffffffffu, sum1, 1);
        sum1 += __shfl_xor_sync(0xffffffffu, sum1, 2);

        l_i[0] = l_i[0] * cr0 + sum0;
        l_i[1] = l_i[1] * cr1 + sum1;
        m_i[0] = mn0; m_i[1] = mn1;

#pragma unroll
        for (int d = 0; d < 8; d++) {
            acc[d][0] *= cr0; acc[d][1] *= cr0;
            acc[d][2] *= cr1; acc[d][3] *= cr1;
        }

        // ---- store P as fp16 half2 (cols n*8+2t, 2t+1) ----
#pragma unroll
        for (int n = 0; n < 4; n++) {
            Pw[ g      * 20 + n * 4 + t] =
                h2_as_u32(__floats2half2_rn(s4[n][0], s4[n][1]));
            Pw[(g + 8) * 20 + n * 4 + t] =
                h2_as_u32(__floats2half2_rn(s4[n][2], s4[n][3]));
        }
        __syncwarp();

        // ---- acc += P @ V : 2 ksteps x 8 d-cols ----
#pragma unroll
        for (int ks = 0; ks < 2; ks++) {
            const int kb = ks * 8;
            uint32_t a0 = Pw[ g      * 20 + kb + t    ];
            uint32_t a1 = Pw[(g + 8) * 20 + kb + t    ];
            uint32_t a2 = Pw[ g      * 20 + kb + t + 4];
            uint32_t a3 = Pw[(g + 8) * 20 + kb + t + 4];
#pragma unroll
            for (int d = 0; d < 8; d++) {
                uint32_t b0 = VTw[(d * 8 + g) * 20 + kb + t    ];
                uint32_t b1 = VTw[(d * 8 + g) * 20 + kb + t + 4];
                mma_f16(acc[d][0], acc[d][1], acc[d][2], acc[d][3],
                        a0, a1, a2, a3, b0, b1);
            }
        }
        __syncthreads();
    }

    const float inv0 = 1.0f / l_i[0];
    const float inv1 = 1.0f / l_i[1];
    const int r0 = rowBase + wq + g;
    const int r1 = r0 + 8;
#pragma unroll
    for (int d = 0; d < 8; d++) {
        const int col = cq + d * 8 + 2 * t;
        *(__half2*)&O[(size_t)r0 * DD + col] =
            __floats2half2_rn(acc[d][0] * inv0, acc[d][1] * inv0);
        *(__half2*)&O[(size_t)r1 * DD + col] =
            __floats2half2_rn(acc[d][2] * inv1, acc[d][3] * inv1);
    }
}

// ---------------------------------------------------------------------------
// Fused residual add + LayerNorm (+ optional fp16 copy)
// ---------------------------------------------------------------------------
__global__ void __launch_bounds__(256) add_ln_kernel(
    const float* __restrict__ A, const float* __restrict__ R,
    const float* __restrict__ g, const float* __restrict__ be,
    float* __restrict__ out, __half* __restrict__ out_h)
{
    __shared__ float red[8];
    const int row = blockIdx.x, tid = threadIdx.x;
    const int lane = tid & 31, wid = tid >> 5;

    float4 a = ((const float4*)(A + (size_t)row * DD))[tid];
    float4 r = ((const float4*)(R + (size_t)row * DD))[tid];
    float4 t = make_float4(a.x + r.x, a.y + r.y, a.z + r.z, a.w + r.w);

    float ssum = t.x + t.y + t.z + t.w;
#pragma unroll
    for (int o = 16; o; o >>= 1) ssum += __shfl_xor_sync(0xffffffffu, ssum, o);
    if (lane == 0) red[wid] = ssum;
    __syncthreads();
    float mean = (red[0] + red[1] + red[2] + red[3] +
                  red[4] + red[5] + red[6] + red[7]) * (1.0f / DD);
    __syncthreads();

    float4 d = make_float4(t.x - mean, t.y - mean, t.z - mean, t.w - mean);
    float sq = d.x * d.x + d.y * d.y + d.z * d.z + d.w * d.w;
#pragma unroll
    for (int o = 16; o; o >>= 1) sq += __shfl_xor_sync(0xffffffffu, sq, o);
    if (lane == 0) red[wid] = sq;
    __syncthreads();
    float var = (red[0] + red[1] + red[2] + red[3] +
                 red[4] + red[5] + red[6] + red[7]) * (1.0f / DD);
    float rs = rsqrtf(var + 1e-5f);

    float4 gv = ((const float4*)g)[tid];
    float4 bv = ((const float4*)be)[tid];
    float4 o4 = make_float4(d.x * rs * gv.x + bv.x,
                            d.y * rs * gv.y + bv.y,
                            d.z * rs * gv.z + bv.z,
                            d.w * rs * gv.w + bv.w);
    ((float4*)(out + (size_t)row * DD))[tid] = o4;
    if (out_h) {
        __half2* oh = (__half2*)(out_h + (size_t)row * DD);
        oh[2 * tid]     = __floats2half2_rn(o4.x, o4.y);
        oh[2 * tid + 1] = __floats2half2_rn(o4.z, o4.w);
    }
}

// ---------------------------------------------------------------------------
// GELU(exact) * gate, fp16 in / fp16 out
// ---------------------------------------------------------------------------
__global__ void __launch_bounds__(256) gelu_gate_kernel(
    const __half* __restrict__ u, __half* __restrict__ m)
{
    int gid = blockIdx.x * blockDim.x + threadIdx.x;
    const int f4_per_row = FF / 4;
    int row  = gid / f4_per_row;
    int col4 = gid - row * f4_per_row;
    if (row >= NTOK) return;

    const __half* base = u + (size_t)row * 2 * FF;
    __half2 a01 = ((const __half2*)base)[2 * col4];
    __half2 a23 = ((const __half2*)base)[2 * col4 + 1];
    __half2 g01 = ((const __half2*)(base + FF))[2 * col4];
    __half2 g23 = ((const __half2*)(base + FF))[2 * col4 + 1];

    float2 af0 = __half22float2(a01), af1 = __half22float2(a23);
    float2 gf0 = __half22float2(g01), gf1 = __half22float2(g23);

    const float is2 = 0.70710678118654752f;
    float o0 = 0.5f * af0.x * (1.0f + erff(af0.x * is2)) * gf0.x;
    float o1 = 0.5f * af0.y * (1.0f + erff(af0.y * is2)) * gf0.y;
    float o2 = 0.5f * af1.x * (1.0f + erff(af1.x * is2)) * gf1.x;
    float o3 = 0.5f * af1.y * (1.0f + erff(af1.y * is2)) * gf1.y;

    __half2* mo = (__half2*)(m + (size_t)row * FF);
    mo[2 * col4]     = __floats2half2_rn(o0, o1);
    mo[2 * col4 + 1] = __floats2half2_rn(o2, o3);
}

// ---------------------------------------------------------------------------
// kernel_launch
// ---------------------------------------------------------------------------
extern "C" void kernel_launch(void* const* d_in, const int* in_sizes, int n_in,
                              void* d_out, int out_size)
{
    const float* x      = (const float*)d_in[0];
    const int*   p      = (const int*)  d_in[1];
    const float* Wqkv   = (const float*)d_in[2];
    const float* bqkv   = (const float*)d_in[3];
    const float* Wo     = (const float*)d_in[4];
    const float* bo     = (const float*)d_in[5];
    const float* gattn  = (const float*)d_in[6];
    const float* battn  = (const float*)d_in[7];
    const float* W1     = (const float*)d_in[8];
    const float* b1     = (const float*)d_in[9];
    const float* W2     = (const float*)d_in[10];
    const float* b2     = (const float*)d_in[11];
    const float* gmlp   = (const float*)d_in[12];
    const float* bmlp   = (const float*)d_in[13];
    const float* freqs  = (const float*)d_in[14];
    float* out = (float*)d_out;

    float *qkv, *proj, *hbuf, *m2;
    __half *xh, *wqkvh, *woh, *w1h, *w2h, *attnh, *hh, *uh, *mh;
    __half *qh, *kh, *vth;
    cudaGetSymbolAddress((void**)&qkv,  g_qkv);
    cudaGetSymbolAddress((void**)&proj, g_proj);
    cudaGetSymbolAddress((void**)&hbuf, g_hbuf);
    cudaGetSymbolAddress((void**)&m2,   g_m2);
    cudaGetSymbolAddress((void**)&xh,    g_xh);
    cudaGetSymbolAddress((void**)&wqkvh, g_wqkvh);
    cudaGetSymbolAddress((void**)&woh,   g_woh);
    cudaGetSymbolAddress((void**)&w1h,   g_w1h);
    cudaGetSymbolAddress((void**)&w2h,   g_w2h);
    cudaGetSymbolAddress((void**)&attnh, g_attnh);
    cudaGetSymbolAddress((void**)&hh,    g_hh);
    cudaGetSymbolAddress((void**)&uh,    g_uh);
    cudaGetSymbolAddress((void**)&mh,    g_mh);
    cudaGetSymbolAddress((void**)&qh,    g_qh);
    cudaGetSymbolAddress((void**)&kh,    g_kh);
    cudaGetSymbolAddress((void**)&vth,   g_vth);

    cudaFuncSetAttribute(flash_attn_f16_kernel,
                         cudaFuncAttributeMaxDynamicSharedMemorySize, FH_SMEM);
    cudaFuncSetAttribute(gemm_f16_nt_bias<float>,
                         cudaFuncAttributeMaxDynamicSharedMemorySize, GH_SMEM);
    cudaFuncSetAttribute(gemm_f16_nt_bias<__half>,
                         cudaFuncAttributeMaxDynamicSharedMemorySize, GH_SMEM);

    // 0) fp16 pre-conversion of GEMM inputs
    h_copy_kernel<<<(NTOK * DD / 4 + 255) / 256, 256>>>(x,    xh,    NTOK * DD / 4);
    h_copy_kernel<<<(D3 * DD / 4 + 255) / 256, 256>>>(Wqkv, wqkvh, D3 * DD / 4);
    h_copy_kernel<<<(DD * DD / 4 + 255) / 256, 256>>>(Wo,   woh,   DD * DD / 4);
    h_copy_kernel<<<(2 * FF * DD / 4 + 255) / 256, 256>>>(W1, w1h,  2 * FF * DD / 4);
    h_copy_kernel<<<(DD * FF / 4 + 255) / 256, 256>>>(W2,   w2h,   DD * FF / 4);

    // 1) QKV projection (fp16 TC, fp32 out)
    gemm_f16_nt_bias<float><<<dim3(D3 / 128, NTOK / 128), 256, GH_SMEM>>>(
        xh, wqkvh, bqkv, qkv, NTOK, D3, DD);

    // 2) RoPE -> fp16 q/k (natural order) + transposed fp16 V
    rope_f16_kernel<<<(NTOK * D3 / 4) / 256, 256>>>(qkv, p, freqs, qh, kh, vth);

    // 3) Flash attention (fp16 TC), fp16 output
    flash_attn_f16_kernel<<<dim3(SS / 64, HH, BB), 128, FH_SMEM>>>(
        qh, kh, vth, attnh);

    // 4) Output projection
    gemm_f16_nt_bias<float><<<dim3(DD / 128, NTOK / 128), 256, GH_SMEM>>>(
        attnh, woh, bo, proj, NTOK, DD, DD);

    // 5) h = LN(proj + x); fp16 copy for W1 GEMM
    add_ln_kernel<<<NTOK, 256>>>(proj, x, gattn, battn, hbuf, hh);

    // 6) u = h @ W1^T + b1 (fp16 output)
    gemm_f16_nt_bias<__half><<<dim3(2 * FF / 128, NTOK / 128), 256, GH_SMEM>>>(
        hh, w1h, b1, uh, NTOK, 2 * FF, DD);

    // 7) m = gelu(a) * gate (fp16 in/out)
    gelu_gate_kernel<<<(NTOK * FF / 4) / 256, 256>>>(uh, mh);

    // 8) m2 = m @ W2^T + b2
    gemm_f16_nt_bias<float><<<dim3(DD / 128, NTOK / 128), 256, GH_SMEM>>>(
        mh, w2h, b2, m2, NTOK, DD, FF);

    // 9) out = LN(m2 + h)
    add_ln_kernel<<<NTOK, 256>>>(m2, hbuf, gmlp, bmlp, out, nullptr);
}

// round 9
// speedup vs baseline: 5.8877x; 1.0260x over previous
#include <cuda_runtime.h>
#include <cuda_fp16.h>
#include <math.h>
#include <stdint.h>
#include <string.h>

// Problem constants
#define BB   2
#define SS   2048
#define DD   1024
#define HH   16
#define DH   64
#define FF   4096
#define NTOK (BB*SS)          // 4096 rows
#define D3   (3*DD)           // 3072

// ---------------------------------------------------------------------------
// Scratch (static device globals)
// ---------------------------------------------------------------------------
__device__ float  g_proj[NTOK * DD];
__device__ float  g_hbuf[NTOK * DD];
__device__ float  g_m2  [NTOK * DD];
// fp16 operands
__device__ __half g_qkvh [NTOK * D3];    // QKV GEMM output (fp16)
__device__ __half g_xh   [NTOK * DD];
__device__ __half g_wqkvh[D3 * DD];
__device__ __half g_woh  [DD * DD];
__device__ __half g_w1h  [2 * FF * DD];
__device__ __half g_w2h  [DD * FF];
__device__ __half g_attnh[NTOK * DD];
__device__ __half g_hh   [NTOK * DD];
__device__ __half g_mh   [NTOK * FF];
// fp16 attention inputs
__device__ __half g_qh   [NTOK * DD];            // RoPE'd, scaled q
__device__ __half g_kh   [NTOK * DD];            // RoPE'd k
__device__ __half g_vth  [BB * HH * DH * SS];    // V transposed per (b,h): [d][s]

// ---------------------------------------------------------------------------
// helpers
// ---------------------------------------------------------------------------
__device__ __forceinline__ uint32_t h2_as_u32(__half2 h) {
    uint32_t u;
    memcpy(&u, &h, 4);
    return u;
}

__device__ __forceinline__ void mma_f16(
    float& d0, float& d1, float& d2, float& d3,
    uint32_t a0, uint32_t a1, uint32_t a2, uint32_t a3,
    uint32_t b0, uint32_t b1)
{
    asm volatile(
        "mma.sync.aligned.m16n8k16.row.col.f32.f16.f16.f32 "
        "{%0,%1,%2,%3}, {%4,%5,%6,%7}, {%8,%9}, {%0,%1,%2,%3};"
        : "+f"(d0), "+f"(d1), "+f"(d2), "+f"(d3)
        : "r"(a0), "r"(a1), "r"(a2), "r"(a3), "r"(b0), "r"(b1));
}

__device__ __forceinline__ uint32_t smem_u32(const void* p) {
    uint32_t a;
    asm("{ .reg .u64 t; cvta.to.shared.u64 t, %1; cvt.u32.u64 %0, t; }"
        : "=r"(a) : "l"(p));
    return a;
}

__device__ __forceinline__ void cp_async16(uint32_t s, const void* g) {
    asm volatile("cp.async.cg.shared.global [%0], [%1], 16;\n"
                 :: "r"(s), "l"(g));
}
__device__ __forceinline__ void cp_commit() {
    asm volatile("cp.async.commit_group;\n");
}

__device__ __forceinline__ void store2(float* C, size_t idx, float a, float b) {
    *(float2*)&C[idx] = make_float2(a, b);
}
__device__ __forceinline__ void store2(__half* C, size_t idx, float a, float b) {
    *(__half2*)&C[idx] = __floats2half2_rn(a, b);
}

// ---------------------------------------------------------------------------
// fp32 -> fp16 copy
// ---------------------------------------------------------------------------
__global__ void __launch_bounds__(256) h_copy_kernel(
    const float* __restrict__ s, __half* __restrict__ d, int n4)
{
    int i = blockIdx.x * blockDim.x + threadIdx.x;
    if (i < n4) {
        float4 v = ((const float4*)s)[i];
        ((__half2*)d)[2 * i]     = __floats2half2_rn(v.x, v.y);
        ((__half2*)d)[2 * i + 1] = __floats2half2_rn(v.z, v.w);
    }
}

// ---------------------------------------------------------------------------
// FP16 tensor-core GEMM: C = A @ W^T + bias   (CTA 128x128, BK=32, 8 warps)
// ---------------------------------------------------------------------------
#define HSTR    40
#define STAGE_H (2 * 128 * HSTR)
#define GH_SMEM (3 * STAGE_H * 2)          // 61440 B

template<typename OutT>
__global__ void __launch_bounds__(256) gemm_f16_nt_bias(
    const __half* __restrict__ A, const __half* __restrict__ W,
    const float* __restrict__ bias, OutT* __restrict__ C,
    int M, int N, int K)
{
    extern __shared__ __align__(16) char smc[];
    __half* smh = (__half*)smc;

    const int tid  = threadIdx.x;
    const int m0   = blockIdx.y * 128;
    const int n0   = blockIdx.x * 128;
    const int warp = tid >> 5;
    const int lane = tid & 31;
    const int g    = lane >> 2;
    const int t    = lane & 3;
    const int wm   = (warp >> 2) * 64;
    const int wn   = (warp & 3) * 32;

    const int lrow = tid >> 1;
    const int lc   = (tid & 1) * 16;
    const __half* Ag = A + (size_t)(m0 + lrow) * K + lc;
    const __half* Wg = W + (size_t)(n0 + lrow) * K + lc;
    const uint32_t smb = smem_u32(smh);

    const int NK = K >> 5;

    auto issue = [&](int kt) {
        const int buf = kt % 3;
        uint32_t dA = smb + (uint32_t)(buf * STAGE_H + lrow * HSTR + lc) * 2;
        uint32_t dB = dA + 128 * HSTR * 2;
        const __half* a = Ag + (size_t)kt * 32;
        const __half* w = Wg + (size_t)kt * 32;
        cp_async16(dA,      a);
        cp_async16(dA + 16, a + 8);
        cp_async16(dB,      w);
        cp_async16(dB + 16, w + 8);
        cp_commit();
    };

    uint32_t af0[4][4], bf0[4][2], af1[4][4], bf1[4][2];

    auto ldfrag = [&](int buf, int ks, uint32_t af[4][4], uint32_t bf[4][2]) {
        const uint32_t* Aw = (const uint32_t*)(smh + buf * STAGE_H);
        const uint32_t* Bw = Aw + 128 * (HSTR / 2);
        const int kb = ks * 8;
#pragma unroll
        for (int i = 0; i < 4; i++) {
            const int rb = wm + i * 16;
            af[i][0] = Aw[(rb + g    ) * 20 + kb + t    ];
            af[i][1] = Aw[(rb + g + 8) * 20 + kb + t    ];
            af[i][2] = Aw[(rb + g    ) * 20 + kb + t + 4];
            af[i][3] = Aw[(rb + g + 8) * 20 + kb + t + 4];
        }
#pragma unroll
        for (int j = 0; j < 4; j++) {
            const int cb = wn + j * 8 + g;
            bf[j][0] = Bw[cb * 20 + kb + t    ];
            bf[j][1] = Bw[cb * 20 + kb + t + 4];
        }
    };

    float acc[4][4][4];
#pragma unroll
    for (int i = 0; i < 4; i++)
#pragma unroll
        for (int j = 0; j < 4; j++)
#pragma unroll
            for (int r = 0; r < 4; r++) acc[i][j][r] = 0.f;

    auto mma16 = [&](uint32_t af[4][4], uint32_t bf[4][2]) {
#pragma unroll
        for (int j = 0; j < 4; j++)
#pragma unroll
            for (int i = 0; i < 4; i++)
                mma_f16(acc[i][j][0], acc[i][j][1], acc[i][j][2], acc[i][j][3],
                        af[i][0], af[i][1], af[i][2], af[i][3],
                        bf[j][0], bf[j][1]);
    };

    issue(0);
    issue(1);
    asm volatile("cp.async.wait_group 1;\n");
    __syncthreads();
    ldfrag(0, 0, af0, bf0);

    for (int kt = 0; kt < NK; kt++) {
        const int buf = kt % 3;
        ldfrag(buf, 1, af1, bf1);
        mma16(af0, bf0);
        const bool more2 = (kt + 2) < NK;
        if (more2) issue(kt + 2);
        mma16(af1, bf1);
        if (kt + 1 < NK) {
            if (more2) asm volatile("cp.async.wait_group 1;\n");
            else       asm volatile("cp.async.wait_group 0;\n");
            __syncthreads();
            ldfrag((kt + 1) % 3, 0, af0, bf0);
        }
    }

#pragma unroll
    for (int i = 0; i < 4; i++) {
        const int r0 = m0 + wm + i * 16 + g;
        const int r1 = r0 + 8;
#pragma unroll
        for (int j = 0; j < 4; j++) {
            const int col = n0 + wn + j * 8 + 2 * t;
            float2 bv = *(const float2*)&bias[col];
            store2(C, (size_t)r0 * N + col, acc[i][j][0] + bv.x, acc[i][j][1] + bv.y);
            store2(C, (size_t)r1 * N + col, acc[i][j][2] + bv.x, acc[i][j][3] + bv.y);
        }
    }
}

// ---------------------------------------------------------------------------
// W1 GEMM fused with GELU*gate: m[r][n] = gelu(a)*gate,
//   a    = h @ W1[n]^T      + b1[n]
//   gate = h @ W1[FF+n]^T   + b1[FF+n]
// CTA computes 128 rows x 64 m-cols. B tile rows: [0..64)=a rows, [64..128)=gate.
// Epilogue stages acc via smem (reuses pipeline smem), applies exact GELU.
// ---------------------------------------------------------------------------
#define CS_STR   132
#define W1_SMEM  (128 * CS_STR * 4)        // 67584 B (>= GH_SMEM)

__global__ void __launch_bounds__(256) gemm_w1_gelu(
    const __half* __restrict__ A, const __half* __restrict__ W,
    const float* __restrict__ bias, __half* __restrict__ Mout,
    int M, int K)
{
    extern __shared__ __align__(16) char smc[];
    __half* smh = (__half*)smc;

    const int tid  = threadIdx.x;
    const int m0   = blockIdx.y * 128;
    const int n0m  = blockIdx.x * 64;       // m-column base (0..FF-64)
    const int warp = tid >> 5;
    const int lane = tid & 31;
    const int g    = lane >> 2;
    const int t    = lane & 3;
    const int wm   = (warp >> 2) * 64;
    const int wn   = (warp & 3) * 32;

    const int lrow = tid >> 1;
    const int lc   = (tid & 1) * 16;
    const int wrow = (lrow < 64) ? (n0m + lrow) : (FF + n0m + lrow - 64);
    const __half* Ag = A + (size_t)(m0 + lrow) * K + lc;
    const __half* Wg = W + (size_t)wrow * K + lc;
    const uint32_t smb = smem_u32(smh);

    const int NK = K >> 5;

    auto issue = [&](int kt) {
        const int buf = kt % 3;
        uint32_t dA = smb + (uint32_t)(buf * STAGE_H + lrow * HSTR + lc) * 2;
        uint32_t dB = dA + 128 * HSTR * 2;
        const __half* a = Ag + (size_t)kt * 32;
        const __half* w = Wg + (size_t)kt * 32;
        cp_async16(dA,      a);
        cp_async16(dA + 16, a + 8);
        cp_async16(dB,      w);
        cp_async16(dB + 16, w + 8);
        cp_commit();
    };

    uint32_t af0[4][4], bf0[4][2], af1[4][4], bf1[4][2];

    auto ldfrag = [&](int buf, int ks, uint32_t af[4][4], uint32_t bf[4][2]) {
        const uint32_t* Aw = (const uint32_t*)(smh + buf * STAGE_H);
        const uint32_t* Bw = Aw + 128 * (HSTR / 2);
        const int kb = ks * 8;
#pragma unroll
        for (int i = 0; i < 4; i++) {
            const int rb = wm + i * 16;
            af[i][0] = Aw[(rb + g    ) * 20 + kb + t    ];
            af[i][1] = Aw[(rb + g + 8) * 20 + kb + t    ];
            af[i][2] = Aw[(rb + g    ) * 20 + kb + t + 4];
            af[i][3] = Aw[(rb + g + 8) * 20 + kb + t + 4];
        }
#pragma unroll
        for (int j = 0; j < 4; j++) {
            const int cb = wn + j * 8 + g;
            bf[j][0] = Bw[cb * 20 + kb + t    ];
            bf[j][1] = Bw[cb * 20 + kb + t + 4];
        }
    };

    float acc[4][4][4];
#pragma unroll
    for (int i = 0; i < 4; i++)
#pragma unroll
        for (int j = 0; j < 4; j++)
#pragma unroll
            for (int r = 0; r < 4; r++) acc[i][j][r] = 0.f;

    auto mma16 = [&](uint32_t af[4][4], uint32_t bf[4][2]) {
#pragma unroll
        for (int j = 0; j < 4; j++)
#pragma unroll
            for (int i = 0; i < 4; i++)
                mma_f16(acc[i][j][0], acc[i][j][1], acc[i][j][2], acc[i][j][3],
                        af[i][0], af[i][1], af[i][2], af[i][3],
                        bf[j][0], bf[j][1]);
    };

    issue(0);
    issue(1);
    asm volatile("cp.async.wait_group 1;\n");
    __syncthreads();
    ldfrag(0, 0, af0, bf0);

    for (int kt = 0; kt < NK; kt++) {
        const int buf = kt % 3;
        ldfrag(buf, 1, af1, bf1);
        mma16(af0, bf0);
        const bool more2 = (kt + 2) < NK;
        if (more2) issue(kt + 2);
        mma16(af1, bf1);
        if (kt + 1 < NK) {
            if (more2) asm volatile("cp.async.wait_group 1;\n");
            else       asm volatile("cp.async.wait_group 0;\n");
            __syncthreads();
            ldfrag((kt + 1) % 3, 0, af0, bf0);
        }
    }

    // ---- epilogue: stage raw acc to smem, then gelu(a)*gate -> Mout ----
    __syncthreads();                       // all warps done with pipeline smem
    float* Cs = (float*)smc;               // 128 x CS_STR
#pragma unroll
    for (int i = 0; i < 4; i++) {
        const int r0 = wm + i * 16 + g;
        const int r1 = r0 + 8;
#pragma unroll
        for (int j = 0; j < 4; j++) {
            const int col = wn + j * 8 + 2 * t;
            *(float2*)&Cs[r0 * CS_STR + col] = make_float2(acc[i][j][0], acc[i][j][1]);
            *(float2*)&Cs[r1 * CS_STR + col] = make_float2(acc[i][j][2], acc[i][j][3]);
        }
    }
    __syncthreads();

    const float is2 = 0.70710678118654752f;
    for (int i = tid; i < 128 * 32; i += 256) {   // 32 half2 per row
        const int r  = i >> 5;
        const int c2 = (i & 31) * 2;
        float a0 = Cs[r * CS_STR + c2    ] + bias[n0m + c2    ];
        float a1 = Cs[r * CS_STR + c2 + 1] + bias[n0m + c2 + 1];
        float g0 = Cs[r * CS_STR + 64 + c2    ] + bias[FF + n0m + c2    ];
        float g1 = Cs[r * CS_STR + 64 + c2 + 1] + bias[FF + n0m + c2 + 1];
        float o0 = 0.5f * a0 * (1.0f + erff(a0 * is2)) * g0;
        float o1 = 0.5f * a1 * (1.0f + erff(a1 * is2)) * g1;
        *(__half2*)&Mout[(size_t)(m0 + r) * FF + n0m + c2] =
            __floats2half2_rn(o0, o1);
    }
}

// ---------------------------------------------------------------------------
// RoPE -> fp16 attention operands (input qkv now fp16).
// ---------------------------------------------------------------------------
__global__ void __launch_bounds__(256) rope_f16_kernel(
    const __half* __restrict__ qkv, const int* __restrict__ p,
    const float* __restrict__ freqs,
    __half* __restrict__ qh, __half* __restrict__ kh,
    __half* __restrict__ vth)
{
    const int idx4 = blockIdx.x * blockDim.x + threadIdx.x;
    const int per_row = D3 / 4;                  // 768
    const int row = idx4 / per_row;
    const int c   = (idx4 - row * per_row) * 4;
    if (row >= NTOK) return;

    const __half* base = qkv + (size_t)row * D3 + c;
    float2 v01 = __half22float2(*(const __half2*)base);
    float2 v23 = __half22float2(*(const __half2*)(base + 2));

    if (c < 2 * DD) {                            // q or k: RoPE
        const float pos = (float)p[row];
        const int dh = c & 63;
        const int off = (dh < 32) ? 32 : -32;
        float2 o01 = __half22float2(*(const __half2*)(base + off));
        float2 o23 = __half22float2(*(const __half2*)(base + off + 2));
        float vv[4] = {v01.x, v01.y, v23.x, v23.y};
        float oo[4] = {o01.x, o01.y, o23.x, o23.y};
        const bool isq = (c < DD);
        const float qs = isq ? 0.125f : 1.0f;
#pragma unroll
        for (int j = 0; j < 4; j++) {
            float a = pos * freqs[dh + j];
            float sn, cs;
            __sincosf(a, &sn, &cs);
            vv[j] = (vv[j] * cs + oo[j] * sn) * qs;
        }
        __half* dst = isq ? (qh + (size_t)row * DD + c)
                          : (kh + (size_t)row * DD + (c - DD));
        *(__half2*)(dst)     = __floats2half2_rn(vv[0], vv[1]);
        *(__half2*)(dst + 2) = __floats2half2_rn(vv[2], vv[3]);
    } else {                                     // v: transpose to [b,h][d][s]
        const int cd = c - 2 * DD;               // 0..1023
        const int h  = cd >> 6;
        const int d0 = cd & 63;
        const int b  = row / SS;
        const int s  = row - b * SS;
        __half* dst = vth + ((size_t)(b * HH + h) * DH) * SS + s;
        dst[(size_t)(d0 + 0) * SS] = __float2half_rn(v01.x);
        dst[(size_t)(d0 + 1) * SS] = __float2half_rn(v01.y);
        dst[(size_t)(d0 + 2) * SS] = __float2half_rn(v23.x);
        dst[(size_t)(d0 + 3) * SS] = __float2half_rn(v23.y);
    }
}

// ---------------------------------------------------------------------------
// Flash attention, fp16 mma (unchanged from R8)
// ---------------------------------------------------------------------------
#define FH_Q    0
#define FH_K    (64*72)                   // 4608
#define FH_KSZ  (32*72)                   // 2304
#define FH_VT   (FH_K + 2*FH_KSZ)         // 9216
#define FH_VTSZ (64*40)                   // 2560
#define FH_TOT  (FH_VT + 2*FH_VTSZ)       // 14336 halves
#define FH_SMEM (FH_TOT * 2)              // 28672 bytes

__global__ void __launch_bounds__(128) flash_attn_f16_kernel(
    const __half* __restrict__ qh, const __half* __restrict__ kh,
    const __half* __restrict__ vth, __half* __restrict__ O)
{
    extern __shared__ __align__(16) char smc[];
    __half* smh = (__half*)smc;
    const int tid  = threadIdx.x;
    const int warp = tid >> 5;
    const int lane = tid & 31;
    const int g = lane >> 2;
    const int t = lane & 3;
    const int wq = warp * 16;

    const int qt = blockIdx.x, h = blockIdx.y, b = blockIdx.z;
    const int rowBase = b * SS + qt * 64;
    const int cq = h * DH;
    const uint32_t smb = smem_u32(smh);
    const __half* vbh = vth + (size_t)(b * HH + h) * DH * SS;

    for (int i = tid; i < 64 * 8; i += 128) {
        int r = i >> 3, ch = (i & 7) * 8;
        *(uint4*)&smh[FH_Q + r * 72 + ch] =
            *(const uint4*)&qh[(size_t)(rowBase + r) * DD + cq + ch];
    }

    auto issue_tile = [&](int kt, int buf) {
        const __half* gK = kh + (size_t)(b * SS + kt * 32) * DD + cq;
        const uint32_t sK = smb + (FH_K + buf * FH_KSZ) * 2;
#pragma unroll
        for (int it = 0; it < 2; it++) {
            int i = tid + it * 128;
            int r = i >> 3, ch = (i & 7) * 8;
            cp_async16(sK + (r * 72 + ch) * 2, gK + (size_t)r * DD + ch);
        }
        const __half* gV = vbh + (size_t)kt * 32;
        const uint32_t sV = smb + (FH_VT + buf * FH_VTSZ) * 2;
#pragma unroll
        for (int it = 0; it < 2; it++) {
            int i = tid + it * 128;
            int r = i >> 2, ch = (i & 3) * 8;
            cp_async16(sV + (r * 40 + ch) * 2, gV + (size_t)r * SS + ch);
        }
        cp_commit();
    };
    issue_tile(0, 0);

    __syncthreads();

    uint32_t qf[4][4];
    {
        const uint32_t* Qw = (const uint32_t*)(smh + FH_Q);
#pragma unroll
        for (int ks = 0; ks < 4; ks++) {
            const int kb = ks * 8;
            qf[ks][0] = Qw[(wq + g    ) * 36 + kb + t    ];
            qf[ks][1] = Qw[(wq + g + 8) * 36 + kb + t    ];
            qf[ks][2] = Qw[(wq + g    ) * 36 + kb + t + 4];
            qf[ks][3] = Qw[(wq + g + 8) * 36 + kb + t + 4];
        }
    }

    uint32_t* Pw = (uint32_t*)(smh) + warp * (16 * 20);

    float m_i[2] = {-1e30f, -1e30f};
    float l_i[2] = {0.f, 0.f};
    float acc[8][4];
#pragma unroll
    for (int d = 0; d < 8; d++)
#pragma unroll
        for (int r = 0; r < 4; r++) acc[d][r] = 0.f;

    const int NT = SS / 32;   // 64
    for (int kt = 0; kt < NT; kt++) {
        const int cur = kt & 1;
        if (kt + 1 < NT) {
            issue_tile(kt + 1, 1 - cur);
            asm volatile("cp.async.wait_group 1;\n");
        } else {
            asm volatile("cp.async.wait_group 0;\n");
        }
        __syncthreads();

        const uint32_t* Kw  = (const uint32_t*)(smh + FH_K  + cur * FH_KSZ);
        const uint32_t* VTw = (const uint32_t*)(smh + FH_VT + cur * FH_VTSZ);

        float s4[4][4];
#pragma unroll
        for (int n = 0; n < 4; n++)
#pragma unroll
            for (int r = 0; r < 4; r++) s4[n][r] = 0.f;

#pragma unroll
        for (int ks = 0; ks < 4; ks++) {
            const int kb = ks * 8;
#pragma unroll
            for (int n = 0; n < 4; n++) {
                uint32_t b0 = Kw[(n * 8 + g) * 36 + kb + t    ];
                uint32_t b1 = Kw[(n * 8 + g) * 36 + kb + t + 4];
                mma_f16(s4[n][0], s4[n][1], s4[n][2], s4[n][3],
                        qf[ks][0], qf[ks][1], qf[ks][2], qf[ks][3], b0, b1);
            }
        }

        float mx0 = -1e30f, mx1 = -1e30f;
#pragma unroll
        for (int n = 0; n < 4; n++) {
            mx0 = fmaxf(mx0, fmaxf(s4[n][0], s4[n][1]));
            mx1 = fmaxf(mx1, fmaxf(s4[n][2], s4[n][3]));
        }
        mx0 = fmaxf(mx0, __shfl_xor_sync(0xffffffffu, mx0, 1));
        mx0 = fmaxf(mx0, __shfl_xor_sync(0xffffffffu, mx0, 2));
        mx1 = fmaxf(mx1, __shfl_xor_sync(0xffffffffu, mx1, 1));
        mx1 = fmaxf(mx1, __shfl_xor_sync(0xffffffffu, mx1, 2));

        float mn0 = fmaxf(m_i[0], mx0);
        float mn1 = fmaxf(m_i[1], mx1);
        float cr0 = __expf(m_i[0] - mn0);
        float cr1 = __expf(m_i[1] - mn1);

        float sum0 = 0.f, sum1 = 0.f;
#pragma unroll
        for (int n = 0; n < 4; n++) {
            s4[n][0] = __expf(s4[n][0] - mn0);
            s4[n][1] = __expf(s4[n][1] - mn0);
            s4[n][2] = __expf(s4[n][2] - mn1);
            s4[n][3] = __expf(s4[n][3] - mn1);
            sum0 += s4[n][0] + s4[n][1];
            sum1 += s4[n][2] + s4[n][3];
        }
        sum0 += __shfl_xor_sync(0xffffffffu, sum0, 1);
        sum0 += __shfl_xor_sync(0xffffffffu, sum0, 2);
        sum1 += __shfl_xor_sync(0xffffffffu, sum1, 1);
        sum1 += __shfl_xor_sync(0xffffffffu, sum1, 2);

        l_i[0] = l_i[0] * cr0 + sum0;
        l_i[1] = l_i[1] * cr1 + sum1;
        m_i[0] = mn0; m_i[1] = mn1;

#pragma unroll
        for (int d = 0; d < 8; d++) {
            acc[d][0] *= cr0; acc[d][1] *= cr0;
            acc[d][2] *= cr1; acc[d][3] *= cr1;
        }

#pragma unroll
        for (int n = 0; n < 4; n++) {
            Pw[ g      * 20 + n * 4 + t] =
                h2_as_u32(__floats2half2_rn(s4[n][0], s4[n][1]));
            Pw[(g + 8) * 20 + n * 4 + t] =
                h2_as_u32(__floats2half2_rn(s4[n][2], s4[n][3]));
        }
        __syncwarp();

#pragma unroll
        for (int ks = 0; ks < 2; ks++) {
            const int kb = ks * 8;
            uint32_t a0 = Pw[ g      * 20 + kb + t    ];
            uint32_t a1 = Pw[(g + 8) * 20 + kb + t    ];
            uint32_t a2 = Pw[ g      * 20 + kb + t + 4];
            uint32_t a3 = Pw[(g + 8) * 20 + kb + t + 4];
#pragma unroll
            for (int d = 0; d < 8; d++) {
                uint32_t b0 = VTw[(d * 8 + g) * 20 + kb + t    ];
                uint32_t b1 = VTw[(d * 8 + g) * 20 + kb + t + 4];
                mma_f16(acc[d][0], acc[d][1], acc[d][2], acc[d][3],
                        a0, a1, a2, a3, b0, b1);
            }
        }
        __syncthreads();
    }

    const float inv0 = 1.0f / l_i[0];
    const float inv1 = 1.0f / l_i[1];
    const int r0 = rowBase + wq + g;
    const int r1 = r0 + 8;
#pragma unroll
    for (int d = 0; d < 8; d++) {
        const int col = cq + d * 8 + 2 * t;
        *(__half2*)&O[(size_t)r0 * DD + col] =
            __floats2half2_rn(acc[d][0] * inv0, acc[d][1] * inv0);
        *(__half2*)&O[(size_t)r1 * DD + col] =
            __floats2half2_rn(acc[d][2] * inv1, acc[d][3] * inv1);
    }
}

// ---------------------------------------------------------------------------
// Fused residual add + LayerNorm (+ optional fp16 copy)
// ---------------------------------------------------------------------------
__global__ void __launch_bounds__(256) add_ln_kernel(
    const float* __restrict__ A, const float* __restrict__ R,
    const float* __restrict__ g, const float* __restrict__ be,
    float* __restrict__ out, __half* __restrict__ out_h)
{
    __shared__ float red[8];
    const int row = blockIdx.x, tid = threadIdx.x;
    const int lane = tid & 31, wid = tid >> 5;

    float4 a = ((const float4*)(A + (size_t)row * DD))[tid];
    float4 r = ((const float4*)(R + (size_t)row * DD))[tid];
    float4 t = make_float4(a.x + r.x, a.y + r.y, a.z + r.z, a.w + r.w);

    float ssum = t.x + t.y + t.z + t.w;
#pragma unroll
    for (int o = 16; o; o >>= 1) ssum += __shfl_xor_sync(0xffffffffu, ssum, o);
    if (lane == 0) red[wid] = ssum;
    __syncthreads();
    float mean = (red[0] + red[1] + red[2] + red[3] +
                  red[4] + red[5] + red[6] + red[7]) * (1.0f / DD);
    __syncthreads();

    float4 d = make_float4(t.x - mean, t.y - mean, t.z - mean, t.w - mean);
    float sq = d.x * d.x + d.y * d.y + d.z * d.z + d.w * d.w;
#pragma unroll
    for (int o = 16; o; o >>= 1) sq += __shfl_xor_sync(0xffffffffu, sq, o);
    if (lane == 0) red[wid] = sq;
    __syncthreads();
    float var = (red[0] + red[1] + red[2] + red[3] +
                 red[4] + red[5] + red[6] + red[7]) * (1.0f / DD);
    float rs = rsqrtf(var + 1e-5f);

    float4 gv = ((const float4*)g)[tid];
    float4 bv = ((const float4*)be)[tid];
    float4 o4 = make_float4(d.x * rs * gv.x + bv.x,
                            d.y * rs * gv.y + bv.y,
                            d.z * rs * gv.z + bv.z,
                            d.w * rs * gv.w + bv.w);
    ((float4*)(out + (size_t)row * DD))[tid] = o4;
    if (out_h) {
        __half2* oh = (__half2*)(out_h + (size_t)row * DD);
        oh[2 * tid]     = __floats2half2_rn(o4.x, o4.y);
        oh[2 * tid + 1] = __floats2half2_rn(o4.z, o4.w);
    }
}

// ---------------------------------------------------------------------------
// kernel_launch
// ---------------------------------------------------------------------------
extern "C" void kernel_launch(void* const* d_in, const int* in_sizes, int n_in,
                              void* d_out, int out_size)
{
    const float* x      = (const float*)d_in[0];
    const int*   p      = (const int*)  d_in[1];
    const float* Wqkv   = (const float*)d_in[2];
    const float* bqkv   = (const float*)d_in[3];
    const float* Wo     = (const float*)d_in[4];
    const float* bo     = (const float*)d_in[5];
    const float* gattn  = (const float*)d_in[6];
    const float* battn  = (const float*)d_in[7];
    const float* W1     = (const float*)d_in[8];
    const float* b1     = (const float*)d_in[9];
    const float* W2     = (const float*)d_in[10];
    const float* b2     = (const float*)d_in[11];
    const float* gmlp   = (const float*)d_in[12];
    const float* bmlp   = (const float*)d_in[13];
    const float* freqs  = (const float*)d_in[14];
    float* out = (float*)d_out;

    float *proj, *hbuf, *m2;
    __half *qkvh, *xh, *wqkvh, *woh, *w1h, *w2h, *attnh, *hh, *mh;
    __half *qh, *kh, *vth;
    cudaGetSymbolAddress((void**)&proj, g_proj);
    cudaGetSymbolAddress((void**)&hbuf, g_hbuf);
    cudaGetSymbolAddress((void**)&m2,   g_m2);
    cudaGetSymbolAddress((void**)&qkvh, g_qkvh);
    cudaGetSymbolAddress((void**)&xh,    g_xh);
    cudaGetSymbolAddress((void**)&wqkvh, g_wqkvh);
    cudaGetSymbolAddress((void**)&woh,   g_woh);
    cudaGetSymbolAddress((void**)&w1h,   g_w1h);
    cudaGetSymbolAddress((void**)&w2h,   g_w2h);
    cudaGetSymbolAddress((void**)&attnh, g_attnh);
    cudaGetSymbolAddress((void**)&hh,    g_hh);
    cudaGetSymbolAddress((void**)&mh,    g_mh);
    cudaGetSymbolAddress((void**)&qh,    g_qh);
    cudaGetSymbolAddress((void**)&kh,    g_kh);
    cudaGetSymbolAddress((void**)&vth,   g_vth);

    cudaFuncSetAttribute(flash_attn_f16_kernel,
                         cudaFuncAttributeMaxDynamicSharedMemorySize, FH_SMEM);
    cudaFuncSetAttribute(gemm_f16_nt_bias<float>,
                         cudaFuncAttributeMaxDynamicSharedMemorySize, GH_SMEM);
    cudaFuncSetAttribute(gemm_f16_nt_bias<__half>,
                         cudaFuncAttributeMaxDynamicSharedMemorySize, GH_SMEM);
    cudaFuncSetAttribute(gemm_w1_gelu,
                         cudaFuncAttributeMaxDynamicSharedMemorySize, W1_SMEM);

    // 0) fp16 pre-conversion of GEMM inputs
    h_copy_kernel<<<(NTOK * DD / 4 + 255) / 256, 256>>>(x,    xh,    NTOK * DD / 4);
    h_copy_kernel<<<(D3 * DD / 4 + 255) / 256, 256>>>(Wqkv, wqkvh, D3 * DD / 4);
    h_copy_kernel<<<(DD * DD / 4 + 255) / 256, 256>>>(Wo,   woh,   DD * DD / 4);
    h_copy_kernel<<<(2 * FF * DD / 4 + 255) / 256, 256>>>(W1, w1h,  2 * FF * DD / 4);
    h_copy_kernel<<<(DD * FF / 4 + 255) / 256, 256>>>(W2,   w2h,   DD * FF / 4);

    // 1) QKV projection (fp16 TC, fp16 out)
    gemm_f16_nt_bias<__half><<<dim3(D3 / 128, NTOK / 128), 256, GH_SMEM>>>(
        xh, wqkvh, bqkv, qkvh, NTOK, D3, DD);

    // 2) RoPE -> fp16 q/k + transposed fp16 V
    rope_f16_kernel<<<(NTOK * D3 / 4) / 256, 256>>>(qkvh, p, freqs, qh, kh, vth);

    // 3) Flash attention (fp16 TC), fp16 output
    flash_attn_f16_kernel<<<dim3(SS / 64, HH, BB), 128, FH_SMEM>>>(
        qh, kh, vth, attnh);

    // 4) Output projection
    gemm_f16_nt_bias<float><<<dim3(DD / 128, NTOK / 128), 256, GH_SMEM>>>(
        attnh, woh, bo, proj, NTOK, DD, DD);

    // 5) h = LN(proj + x); fp16 copy for W1 GEMM
    add_ln_kernel<<<NTOK, 256>>>(proj, x, gattn, battn, hbuf, hh);

    // 6+7) m = gelu(h@W1a^T + b1a) * (h@W1g^T + b1g)  — fused
    gemm_w1_gelu<<<dim3(FF / 64, NTOK / 128), 256, W1_SMEM>>>(
        hh, w1h, b1, mh, NTOK, DD);

    // 8) m2 = m @ W2^T + b2
    gemm_f16_nt_bias<float><<<dim3(DD / 128, NTOK / 128), 256, GH_SMEM>>>(
        mh, w2h, b2, m2, NTOK, DD, FF);

    // 9) out = LN(m2 + h)
    add_ln_kernel<<<NTOK, 256>>>(m2, hbuf, gmlp, bmlp, out, nullptr);
}

// round 11
// speedup vs baseline: 6.4654x; 1.0981x over previous
#include <cuda_runtime.h>
#include <cuda_fp16.h>
#include <math.h>
#include <stdint.h>
#include <string.h>

// Problem constants
#define BB   2
#define SS   2048
#define DD   1024
#define HH   16
#define DH   64
#define FF   4096
#define NTOK (BB*SS)          // 4096 rows
#define D3   (3*DD)           // 3072

// ---------------------------------------------------------------------------
// Scratch (static device globals)
// ---------------------------------------------------------------------------
__device__ float  g_proj[NTOK * DD];
__device__ float  g_hbuf[NTOK * DD];
__device__ float  g_m2  [NTOK * DD];
__device__ __half g_qkvh [NTOK * D3];
__device__ __half g_xh   [NTOK * DD];
__device__ __half g_wqkvh[D3 * DD];
__device__ __half g_woh  [DD * DD];
__device__ __half g_w1h  [2 * FF * DD];
__device__ __half g_w2h  [DD * FF];
__device__ __half g_attnh[NTOK * DD];
__device__ __half g_hh   [NTOK * DD];
__device__ __half g_mh   [NTOK * FF];
__device__ __half g_qh   [NTOK * DD];
__device__ __half g_kh   [NTOK * DD];
__device__ __half g_vth  [BB * HH * DH * SS];

// ---------------------------------------------------------------------------
// helpers
// ---------------------------------------------------------------------------
__device__ __forceinline__ uint32_t h2_as_u32(__half2 h) {
    uint32_t u; memcpy(&u, &h, 4); return u;
}

__device__ __forceinline__ void mma_f16(
    float& d0, float& d1, float& d2, float& d3,
    uint32_t a0, uint32_t a1, uint32_t a2, uint32_t a3,
    uint32_t b0, uint32_t b1)
{
    asm volatile(
        "mma.sync.aligned.m16n8k16.row.col.f32.f16.f16.f32 "
        "{%0,%1,%2,%3}, {%4,%5,%6,%7}, {%8,%9}, {%0,%1,%2,%3};"
        : "+f"(d0), "+f"(d1), "+f"(d2), "+f"(d3)
        : "r"(a0), "r"(a1), "r"(a2), "r"(a3), "r"(b0), "r"(b1));
}

// ldmatrix x4: four 8x8 b16 matrices -> 4 regs
__device__ __forceinline__ void ldsm_x4(
    uint32_t& r0, uint32_t& r1, uint32_t& r2, uint32_t& r3, uint32_t addr)
{
    asm volatile(
        "ldmatrix.sync.aligned.m8n8.x4.shared.b16 {%0,%1,%2,%3}, [%4];"
        : "=r"(r0), "=r"(r1), "=r"(r2), "=r"(r3) : "r"(addr));
}

__device__ __forceinline__ uint32_t smem_u32(const void* p) {
    uint32_t a;
    asm("{ .reg .u64 t; cvta.to.shared.u64 t, %1; cvt.u32.u64 %0, t; }"
        : "=r"(a) : "l"(p));
    return a;
}

__device__ __forceinline__ void cp_async16(uint32_t s, const void* g) {
    asm volatile("cp.async.cg.shared.global [%0], [%1], 16;\n"
                 :: "r"(s), "l"(g));
}
__device__ __forceinline__ void cp_commit() {
    asm volatile("cp.async.commit_group;\n");
}
template<int N> __device__ __forceinline__ void cp_wait() {
    asm volatile("cp.async.wait_group %0;\n" :: "n"(N));
}

__device__ __forceinline__ void store2(float* C, size_t idx, float a, float b) {
    *(float2*)&C[idx] = make_float2(a, b);
}
__device__ __forceinline__ void store2(__half* C, size_t idx, float a, float b) {
    *(__half2*)&C[idx] = __floats2half2_rn(a, b);
}

// ---------------------------------------------------------------------------
// fp32 -> fp16 copy
// ---------------------------------------------------------------------------
__global__ void __launch_bounds__(256) h_copy_kernel(
    const float* __restrict__ s, __half* __restrict__ d, int n4)
{
    int i = blockIdx.x * blockDim.x + threadIdx.x;
    if (i < n4) {
        float4 v = ((const float4*)s)[i];
        ((__half2*)d)[2 * i]     = __floats2half2_rn(v.x, v.y);
        ((__half2*)d)[2 * i + 1] = __floats2half2_rn(v.z, v.w);
    }
}

// ---------------------------------------------------------------------------
// FP16 tensor-core GEMM: C = A @ W^T + bias   (CTA 128x128, BK=32, 8 warps)
// Fragment loads via ldmatrix.x4 (row stride 40 halves = conflict-free).
// ---------------------------------------------------------------------------
#define HSTR    40
#define STAGE_H (2 * 128 * HSTR)
#define GH_SMEM (3 * STAGE_H * 2)          // 61440 B

template<typename OutT>
__global__ void __launch_bounds__(256) gemm_f16_nt_bias(
    const __half* __restrict__ A, const __half* __restrict__ W,
    const float* __restrict__ bias, OutT* __restrict__ C,
    int M, int N, int K)
{
    extern __shared__ __align__(16) char smc[];
    __half* smh = (__half*)smc;

    const int tid  = threadIdx.x;
    const int m0   = blockIdx.y * 128;
    const int n0   = blockIdx.x * 128;
    const int warp = tid >> 5;
    const int lane = tid & 31;
    const int g    = lane >> 2;
    const int t    = lane & 3;
    const int wm   = (warp >> 2) * 64;
    const int wn   = (warp & 3) * 32;

    const int lrow = tid >> 1;
    const int lc   = (tid & 1) * 16;
    const __half* Ag = A + (size_t)(m0 + lrow) * K + lc;
    const __half* Wg = W + (size_t)(n0 + lrow) * K + lc;
    const uint32_t smb = smem_u32(smh);

    const int NK = K >> 5;

    auto issue = [&](int kt) {
        const int buf = kt % 3;
        uint32_t dA = smb + (uint32_t)(buf * STAGE_H + lrow * HSTR + lc) * 2;
        uint32_t dB = dA + 128 * HSTR * 2;
        const __half* a = Ag + (size_t)kt * 32;
        const __half* w = Wg + (size_t)kt * 32;
        cp_async16(dA,      a);
        cp_async16(dA + 16, a + 8);
        cp_async16(dB,      w);
        cp_async16(dB + 16, w + 8);
        cp_commit();
    };

    // ldmatrix lane-address components
    const uint32_t aRow = (uint32_t)(lane & 15);
    const uint32_t aKh  = (uint32_t)((lane >> 4) << 3);
    const uint32_t bRow = (uint32_t)((lane & 7) + ((lane >> 4) << 3));
    const uint32_t bKh  = (uint32_t)(lane & 8);

    uint32_t af0[4][4], bf0[4][2], af1[4][4], bf1[4][2];

    auto ldfrag = [&](int buf, int ks, uint32_t af[4][4], uint32_t bf[4][2]) {
        const uint32_t aBase = smb + (uint32_t)(buf * STAGE_H) * 2;
        const uint32_t bBase = aBase + 128 * HSTR * 2;
        const uint32_t kh = (uint32_t)(ks * 16);
#pragma unroll
        for (int i = 0; i < 4; i++) {
            uint32_t addr = aBase + (((uint32_t)(wm + i * 16) + aRow) * HSTR + kh + aKh) * 2;
            ldsm_x4(af[i][0], af[i][1], af[i][2], af[i][3], addr);
        }
#pragma unroll
        for (int jp = 0; jp < 2; jp++) {
            uint32_t addr = bBase + (((uint32_t)(wn + jp * 16) + bRow) * HSTR + kh + bKh) * 2;
            ldsm_x4(bf[2 * jp][0], bf[2 * jp][1], bf[2 * jp + 1][0], bf[2 * jp + 1][1], addr);
        }
    };

    float acc[4][4][4];
#pragma unroll
    for (int i = 0; i < 4; i++)
#pragma unroll
        for (int j = 0; j < 4; j++)
#pragma unroll
            for (int r = 0; r < 4; r++) acc[i][j][r] = 0.f;

    auto mma16 = [&](uint32_t af[4][4], uint32_t bf[4][2]) {
#pragma unroll
        for (int j = 0; j < 4; j++)
#pragma unroll
            for (int i = 0; i < 4; i++)
                mma_f16(acc[i][j][0], acc[i][j][1], acc[i][j][2], acc[i][j][3],
                        af[i][0], af[i][1], af[i][2], af[i][3],
                        bf[j][0], bf[j][1]);
    };

    issue(0);
    issue(1);
    cp_wait<1>();
    __syncthreads();
    ldfrag(0, 0, af0, bf0);

    for (int kt = 0; kt < NK; kt++) {
        const int buf = kt % 3;
        ldfrag(buf, 1, af1, bf1);
        mma16(af0, bf0);
        const bool more2 = (kt + 2) < NK;
        if (more2) issue(kt + 2);
        mma16(af1, bf1);
        if (kt + 1 < NK) {
            if (more2) cp_wait<1>();
            else       cp_wait<0>();
            __syncthreads();
            ldfrag((kt + 1) % 3, 0, af0, bf0);
        }
    }

#pragma unroll
    for (int i = 0; i < 4; i++) {
        const int r0 = m0 + wm + i * 16 + g;
        const int r1 = r0 + 8;
#pragma unroll
        for (int j = 0; j < 4; j++) {
            const int col = n0 + wn + j * 8 + 2 * t;
            float2 bv = *(const float2*)&bias[col];
            store2(C, (size_t)r0 * N + col, acc[i][j][0] + bv.x, acc[i][j][1] + bv.y);
            store2(C, (size_t)r1 * N + col, acc[i][j][2] + bv.x, acc[i][j][3] + bv.y);
        }
    }
}

// ---------------------------------------------------------------------------
// W1 GEMM fused with GELU*gate (as R9), ldmatrix fragment loads
// ---------------------------------------------------------------------------
#define CS_STR   132
#define W1_SMEM  (128 * CS_STR * 4)        // 67584 B (>= GH_SMEM)

__global__ void __launch_bounds__(256) gemm_w1_gelu(
    const __half* __restrict__ A, const __half* __restrict__ W,
    const float* __restrict__ bias, __half* __restrict__ Mout,
    int M, int K)
{
    extern __shared__ __align__(16) char smc[];
    __half* smh = (__half*)smc;

    const int tid  = threadIdx.x;
    const int m0   = blockIdx.y * 128;
    const int n0m  = blockIdx.x * 64;
    const int warp = tid >> 5;
    const int lane = tid & 31;
    const int g    = lane >> 2;
    const int t    = lane & 3;
    const int wm   = (warp >> 2) * 64;
    const int wn   = (warp & 3) * 32;

    const int lrow = tid >> 1;
    const int lc   = (tid & 1) * 16;
    const int wrow = (lrow < 64) ? (n0m + lrow) : (FF + n0m + lrow - 64);
    const __half* Ag = A + (size_t)(m0 + lrow) * K + lc;
    const __half* Wg = W + (size_t)wrow * K + lc;
    const uint32_t smb = smem_u32(smh);

    const int NK = K >> 5;

    auto issue = [&](int kt) {
        const int buf = kt % 3;
        uint32_t dA = smb + (uint32_t)(buf * STAGE_H + lrow * HSTR + lc) * 2;
        uint32_t dB = dA + 128 * HSTR * 2;
        const __half* a = Ag + (size_t)kt * 32;
        const __half* w = Wg + (size_t)kt * 32;
        cp_async16(dA,      a);
        cp_async16(dA + 16, a + 8);
        cp_async16(dB,      w);
        cp_async16(dB + 16, w + 8);
        cp_commit();
    };

    const uint32_t aRow = (uint32_t)(lane & 15);
    const uint32_t aKh  = (uint32_t)((lane >> 4) << 3);
    const uint32_t bRow = (uint32_t)((lane & 7) + ((lane >> 4) << 3));
    const uint32_t bKh  = (uint32_t)(lane & 8);

    uint32_t af0[4][4], bf0[4][2], af1[4][4], bf1[4][2];

    auto ldfrag = [&](int buf, int ks, uint32_t af[4][4], uint32_t bf[4][2]) {
        const uint32_t aBase = smb + (uint32_t)(buf * STAGE_H) * 2;
        const uint32_t bBase = aBase + 128 * HSTR * 2;
        const uint32_t kh = (uint32_t)(ks * 16);
#pragma unroll
        for (int i = 0; i < 4; i++) {
            uint32_t addr = aBase + (((uint32_t)(wm + i * 16) + aRow) * HSTR + kh + aKh) * 2;
            ldsm_x4(af[i][0], af[i][1], af[i][2], af[i][3], addr);
        }
#pragma unroll
        for (int jp = 0; jp < 2; jp++) {
            uint32_t addr = bBase + (((uint32_t)(wn + jp * 16) + bRow) * HSTR + kh + bKh) * 2;
            ldsm_x4(bf[2 * jp][0], bf[2 * jp][1], bf[2 * jp + 1][0], bf[2 * jp + 1][1], addr);
        }
    };

    float acc[4][4][4];
#pragma unroll
    for (int i = 0; i < 4; i++)
#pragma unroll
        for (int j = 0; j < 4; j++)
#pragma unroll
            for (int r = 0; r < 4; r++) acc[i][j][r] = 0.f;

    auto mma16 = [&](uint32_t af[4][4], uint32_t bf[4][2]) {
#pragma unroll
        for (int j = 0; j < 4; j++)
#pragma unroll
            for (int i = 0; i < 4; i++)
                mma_f16(acc[i][j][0], acc[i][j][1], acc[i][j][2], acc[i][j][3],
                        af[i][0], af[i][1], af[i][2], af[i][3],
                        bf[j][0], bf[j][1]);
    };

    issue(0);
    issue(1);
    cp_wait<1>();
    __syncthreads();
    ldfrag(0, 0, af0, bf0);

    for (int kt = 0; kt < NK; kt++) {
        const int buf = kt % 3;
        ldfrag(buf, 1, af1, bf1);
        mma16(af0, bf0);
        const bool more2 = (kt + 2) < NK;
        if (more2) issue(kt + 2);
        mma16(af1, bf1);
        if (kt + 1 < NK) {
            if (more2) cp_wait<1>();
            else       cp_wait<0>();
            __syncthreads();
            ldfrag((kt + 1) % 3, 0, af0, bf0);
        }
    }

    // ---- epilogue: stage raw acc to smem, then gelu(a)*gate -> Mout ----
    __syncthreads();
    float* Cs = (float*)smc;
#pragma unroll
    for (int i = 0; i < 4; i++) {
        const int r0 = wm + i * 16 + g;
        const int r1 = r0 + 8;
#pragma unroll
        for (int j = 0; j < 4; j++) {
            const int col = wn + j * 8 + 2 * t;
            *(float2*)&Cs[r0 * CS_STR + col] = make_float2(acc[i][j][0], acc[i][j][1]);
            *(float2*)&Cs[r1 * CS_STR + col] = make_float2(acc[i][j][2], acc[i][j][3]);
        }
    }
    __syncthreads();

    const float is2 = 0.70710678118654752f;
    for (int i = tid; i < 128 * 32; i += 256) {
        const int r  = i >> 5;
        const int c2 = (i & 31) * 2;
        float a0 = Cs[r * CS_STR + c2    ] + bias[n0m + c2    ];
        float a1 = Cs[r * CS_STR + c2 + 1] + bias[n0m + c2 + 1];
        float g0 = Cs[r * CS_STR + 64 + c2    ] + bias[FF + n0m + c2    ];
        float g1 = Cs[r * CS_STR + 64 + c2 + 1] + bias[FF + n0m + c2 + 1];
        float o0 = 0.5f * a0 * (1.0f + erff(a0 * is2)) * g0;
        float o1 = 0.5f * a1 * (1.0f + erff(a1 * is2)) * g1;
        *(__half2*)&Mout[(size_t)(m0 + r) * FF + n0m + c2] =
            __floats2half2_rn(o0, o1);
    }
}

// ---------------------------------------------------------------------------
// RoPE -> fp16 attention operands (qkv fp16 in)
// ---------------------------------------------------------------------------
__global__ void __launch_bounds__(256) rope_f16_kernel(
    const __half* __restrict__ qkv, const int* __restrict__ p,
    const float* __restrict__ freqs,
    __half* __restrict__ qh, __half* __restrict__ kh,
    __half* __restrict__ vth)
{
    const int idx4 = blockIdx.x * blockDim.x + threadIdx.x;
    const int per_row = D3 / 4;
    const int row = idx4 / per_row;
    const int c   = (idx4 - row * per_row) * 4;
    if (row >= NTOK) return;

    const __half* base = qkv + (size_t)row * D3 + c;
    float2 v01 = __half22float2(*(const __half2*)base);
    float2 v23 = __half22float2(*(const __half2*)(base + 2));

    if (c < 2 * DD) {
        const float pos = (float)p[row];
        const int dh = c & 63;
        const int off = (dh < 32) ? 32 : -32;
        float2 o01 = __half22float2(*(const __half2*)(base + off));
        float2 o23 = __half22float2(*(const __half2*)(base + off + 2));
        float vv[4] = {v01.x, v01.y, v23.x, v23.y};
        float oo[4] = {o01.x, o01.y, o23.x, o23.y};
        const bool isq = (c < DD);
        const float qs = isq ? 0.125f : 1.0f;
#pragma unroll
        for (int j = 0; j < 4; j++) {
            float a = pos * freqs[dh + j];
            float sn, cs;
            __sincosf(a, &sn, &cs);
            vv[j] = (vv[j] * cs + oo[j] * sn) * qs;
        }
        __half* dst = isq ? (qh + (size_t)row * DD + c)
                          : (kh + (size_t)row * DD + (c - DD));
        *(__half2*)(dst)     = __floats2half2_rn(vv[0], vv[1]);
        *(__half2*)(dst + 2) = __floats2half2_rn(vv[2], vv[3]);
    } else {
        const int cd = c - 2 * DD;
        const int h  = cd >> 6;
        const int d0 = cd & 63;
        const int b  = row / SS;
        const int s  = row - b * SS;
        __half* dst = vth + ((size_t)(b * HH + h) * DH) * SS + s;
        dst[(size_t)(d0 + 0) * SS] = __float2half_rn(v01.x);
        dst[(size_t)(d0 + 1) * SS] = __float2half_rn(v01.y);
        dst[(size_t)(d0 + 2) * SS] = __float2half_rn(v23.x);
        dst[(size_t)(d0 + 3) * SS] = __float2half_rn(v23.y);
    }
}

// ---------------------------------------------------------------------------
// Flash attention, fp16 mma, ldmatrix fragment loads for K / VT / P
// ---------------------------------------------------------------------------
#define FH_Q    0
#define FH_K    (64*72)
#define FH_KSZ  (32*72)
#define FH_VT   (FH_K + 2*FH_KSZ)
#define FH_VTSZ (64*40)
#define FH_TOT  (FH_VT + 2*FH_VTSZ)
#define FH_SMEM (FH_TOT * 2)

__global__ void __launch_bounds__(128) flash_attn_f16_kernel(
    const __half* __restrict__ qh, const __half* __restrict__ kh,
    const __half* __restrict__ vth, __half* __restrict__ O)
{
    extern __shared__ __align__(16) char smc[];
    __half* smh = (__half*)smc;
    const int tid  = threadIdx.x;
    const int warp = tid >> 5;
    const int lane = tid & 31;
    const int g = lane >> 2;
    const int t = lane & 3;
    const int wq = warp * 16;

    const int qt = blockIdx.x, h = blockIdx.y, b = blockIdx.z;
    const int rowBase = b * SS + qt * 64;
    const int cq = h * DH;
    const uint32_t smb = smem_u32(smh);
    const __half* vbh = vth + (size_t)(b * HH + h) * DH * SS;

    for (int i = tid; i < 64 * 8; i += 128) {
        int r = i >> 3, ch = (i & 7) * 8;
        *(uint4*)&smh[FH_Q + r * 72 + ch] =
            *(const uint4*)&qh[(size_t)(rowBase + r) * DD + cq + ch];
    }

    auto issue_tile = [&](int kt, int buf) {
        const __half* gK = kh + (size_t)(b * SS + kt * 32) * DD + cq;
        const uint32_t sK = smb + (FH_K + buf * FH_KSZ) * 2;
#pragma unroll
        for (int it = 0; it < 2; it++) {
            int i = tid + it * 128;
            int r = i >> 3, ch = (i & 7) * 8;
            cp_async16(sK + (r * 72 + ch) * 2, gK + (size_t)r * DD + ch);
        }
        const __half* gV = vbh + (size_t)kt * 32;
        const uint32_t sV = smb + (FH_VT + buf * FH_VTSZ) * 2;
#pragma unroll
        for (int it = 0; it < 2; it++) {
            int i = tid + it * 128;
            int r = i >> 2, ch = (i & 3) * 8;
            cp_async16(sV + (r * 40 + ch) * 2, gV + (size_t)r * SS + ch);
        }
        cp_commit();
    };
    issue_tile(0, 0);

    __syncthreads();

    uint32_t qf[4][4];
    {
        const uint32_t aRow = (uint32_t)(lane & 15);
        const uint32_t aKh  = (uint32_t)((lane >> 4) << 3);
#pragma unroll
        for (int ks = 0; ks < 4; ks++) {
            uint32_t addr = smb + (((uint32_t)wq + aRow) * 72 + ks * 16 + aKh) * 2;
            ldsm_x4(qf[ks][0], qf[ks][1], qf[ks][2], qf[ks][3], addr);
        }
    }

    uint32_t* Pw = (uint32_t*)(smh) + warp * (16 * 20);
    const uint32_t sPb = smb + (uint32_t)warp * 1280;   // 16*20 words * 4B

    const uint32_t aRow = (uint32_t)(lane & 15);
    const uint32_t aKh  = (uint32_t)((lane >> 4) << 3);
    const uint32_t bRow = (uint32_t)((lane & 7) + ((lane >> 4) << 3));
    const uint32_t bKh  = (uint32_t)(lane & 8);

    float m_i[2] = {-1e30f, -1e30f};
    float l_i[2] = {0.f, 0.f};
    float acc[8][4];
#pragma unroll
    for (int d = 0; d < 8; d++)
#pragma unroll
        for (int r = 0; r < 4; r++) acc[d][r] = 0.f;

    const int NT = SS / 32;
    for (int kt = 0; kt < NT; kt++) {
        const int cur = kt & 1;
        if (kt + 1 < NT) {
            issue_tile(kt + 1, 1 - cur);
            cp_wait<1>();
        } else {
            cp_wait<0>();
        }
        __syncthreads();

        const uint32_t sKb = smb + (FH_K  + cur * FH_KSZ)  * 2;
        const uint32_t sVb = smb + (FH_VT + cur * FH_VTSZ) * 2;

        // ---- S = Q K^T ----
        float s4[4][4];
#pragma unroll
        for (int n = 0; n < 4; n++)
#pragma unroll
            for (int r = 0; r < 4; r++) s4[n][r] = 0.f;

#pragma unroll
        for (int ks = 0; ks < 4; ks++) {
            uint32_t kf[4][2];
#pragma unroll
            for (int jp = 0; jp < 2; jp++) {
                uint32_t addr = sKb + (((uint32_t)(jp * 16) + bRow) * 72 + ks * 16 + bKh) * 2;
                ldsm_x4(kf[2 * jp][0], kf[2 * jp][1],
                        kf[2 * jp + 1][0], kf[2 * jp + 1][1], addr);
            }
#pragma unroll
            for (int n = 0; n < 4; n++)
                mma_f16(s4[n][0], s4[n][1], s4[n][2], s4[n][3],
                        qf[ks][0], qf[ks][1], qf[ks][2], qf[ks][3],
                        kf[n][0], kf[n][1]);
        }

        // ---- online softmax (rows wq+g, wq+g+8) ----
        float mx0 = -1e30f, mx1 = -1e30f;
#pragma unroll
        for (int n = 0; n < 4; n++) {
            mx0 = fmaxf(mx0, fmaxf(s4[n][0], s4[n][1]));
            mx1 = fmaxf(mx1, fmaxf(s4[n][2], s4[n][3]));
        }
        mx0 = fmaxf(mx0, __shfl_xor_sync(0xffffffffu, mx0, 1));
        mx0 = fmaxf(mx0, __shfl_xor_sync(0xffffffffu, mx0, 2));
        mx1 = fmaxf(mx1, __shfl_xor_sync(0xffffffffu, mx1, 1));
        mx1 = fmaxf(mx1, __shfl_xor_sync(0xffffffffu, mx1, 2));

        float mn0 = fmaxf(m_i[0], mx0);
        float mn1 = fmaxf(m_i[1], mx1);
        float cr0 = __expf(m_i[0] - mn0);
        float cr1 = __expf(m_i[1] - mn1);

        float sum0 = 0.f, sum1 = 0.f;
#pragma unroll
        for (int n = 0; n < 4; n++) {
            s4[n][0] = __expf(s4[n][0] - mn0);
            s4[n][1] = __expf(s4[n][1] - mn0);
            s4[n][2] = __expf(s4[n][2] - mn1);
            s4[n][3] = __expf(s4[n][3] - mn1);
            sum0 += s4[n][0] + s4[n][1];
            sum1 += s4[n][2] + s4[n][3];
        }
        sum0 += __shfl_xor_sync(0xffffffffu, sum0, 1);
        sum0 += __shfl_xor_sync(0xffffffffu, sum0, 2);
        sum1 += __shfl_xor_sync(0xffffffffu, sum1, 1);
        sum1 += __shfl_xor_sync(0xffffffffu, sum1, 2);

        l_i[0] = l_i[0] * cr0 + sum0;
        l_i[1] = l_i[1] * cr1 + sum1;
        m_i[0] = mn0; m_i[1] = mn1;

#pragma unroll
        for (int d = 0; d < 8; d++) {
            acc[d][0] *= cr0; acc[d][1] *= cr0;
            acc[d][2] *= cr1; acc[d][3] *= cr1;
        }

        // ---- store P as fp16 ----
#pragma unroll
        for (int n = 0; n < 4; n++) {
            Pw[ g      * 20 + n * 4 + t] =
                h2_as_u32(__floats2half2_rn(s4[n][0], s4[n][1]));
            Pw[(g + 8) * 20 + n * 4 + t] =
                h2_as_u32(__floats2half2_rn(s4[n][2], s4[n][3]));
        }
        __syncwarp();

        // ---- acc += P @ V ----
#pragma unroll
        for (int ks = 0; ks < 2; ks++) {
            uint32_t pa[4];
            {
                uint32_t addr = sPb + (aRow * 40 + ks * 16 + aKh) * 2;
                ldsm_x4(pa[0], pa[1], pa[2], pa[3], addr);
            }
            uint32_t vf[8][2];
#pragma unroll
            for (int dp = 0; dp < 4; dp++) {
                uint32_t addr = sVb + (((uint32_t)(dp * 16) + bRow) * 40 + ks * 16 + bKh) * 2;
                ldsm_x4(vf[2 * dp][0], vf[2 * dp][1],
                        vf[2 * dp + 1][0], vf[2 * dp + 1][1], addr);
            }
#pragma unroll
            for (int d = 0; d < 8; d++)
                mma_f16(acc[d][0], acc[d][1], acc[d][2], acc[d][3],
                        pa[0], pa[1], pa[2], pa[3], vf[d][0], vf[d][1]);
        }
        __syncthreads();
    }

    const float inv0 = 1.0f / l_i[0];
    const float inv1 = 1.0f / l_i[1];
    const int r0 = rowBase + wq + g;
    const int r1 = r0 + 8;
#pragma unroll
    for (int d = 0; d < 8; d++) {
        const int col = cq + d * 8 + 2 * t;
        *(__half2*)&O[(size_t)r0 * DD + col] =
            __floats2half2_rn(acc[d][0] * inv0, acc[d][1] * inv0);
        *(__half2*)&O[(size_t)r1 * DD + col] =
            __floats2half2_rn(acc[d][2] * inv1, acc[d][3] * inv1);
    }
}

// ---------------------------------------------------------------------------
// Fused residual add + LayerNorm (+ optional fp16 copy)
// ---------------------------------------------------------------------------
__global__ void __launch_bounds__(256) add_ln_kernel(
    const float* __restrict__ A, const float* __restrict__ R,
    const float* __restrict__ g, const float* __restrict__ be,
    float* __restrict__ out, __half* __restrict__ out_h)
{
    __shared__ float red[8];
    const int row = blockIdx.x, tid = threadIdx.x;
    const int lane = tid & 31, wid = tid >> 5;

    float4 a = ((const float4*)(A + (size_t)row * DD))[tid];
    float4 r = ((const float4*)(R + (size_t)row * DD))[tid];
    float4 t = make_float4(a.x + r.x, a.y + r.y, a.z + r.z, a.w + r.w);

    float ssum = t.x + t.y + t.z + t.w;
#pragma unroll
    for (int o = 16; o; o >>= 1) ssum += __shfl_xor_sync(0xffffffffu, ssum, o);
    if (lane == 0) red[wid] = ssum;
    __syncthreads();
    float mean = (red[0] + red[1] + red[2] + red[3] +
                  red[4] + red[5] + red[6] + red[7]) * (1.0f / DD);
    __syncthreads();

    float4 d = make_float4(t.x - mean, t.y - mean, t.z - mean, t.w - mean);
    float sq = d.x * d.x + d.y * d.y + d.z * d.z + d.w * d.w;
#pragma unroll
    for (int o = 16; o; o >>= 1) sq += __shfl_xor_sync(0xffffffffu, sq, o);
    if (lane == 0) red[wid] = sq;
    __syncthreads();
    float var = (red[0] + red[1] + red[2] + red[3] +
                 red[4] + red[5] + red[6] + red[7]) * (1.0f / DD);
    float rs = rsqrtf(var + 1e-5f);

    float4 gv = ((const float4*)g)[tid];
    float4 bv = ((const float4*)be)[tid];
    float4 o4 = make_float4(d.x * rs * gv.x + bv.x,
                            d.y * rs * gv.y + bv.y,
                            d.z * rs * gv.z + bv.z,
                            d.w * rs * gv.w + bv.w);
    ((float4*)(out + (size_t)row * DD))[tid] = o4;
    if (out_h) {
        __half2* oh = (__half2*)(out_h + (size_t)row * DD);
        oh[2 * tid]     = __floats2half2_rn(o4.x, o4.y);
        oh[2 * tid + 1] = __floats2half2_rn(o4.z, o4.w);
    }
}

// ---------------------------------------------------------------------------
// kernel_launch
// ---------------------------------------------------------------------------
extern "C" void kernel_launch(void* const* d_in, const int* in_sizes, int n_in,
                              void* d_out, int out_size)
{
    const float* x      = (const float*)d_in[0];
    const int*   p      = (const int*)  d_in[1];
    const float* Wqkv   = (const float*)d_in[2];
    const float* bqkv   = (const float*)d_in[3];
    const float* Wo     = (const float*)d_in[4];
    const float* bo     = (const float*)d_in[5];
    const float* gattn  = (const float*)d_in[6];
    const float* battn  = (const float*)d_in[7];
    const float* W1     = (const float*)d_in[8];
    const float* b1     = (const float*)d_in[9];
    const float* W2     = (const float*)d_in[10];
    const float* b2     = (const float*)d_in[11];
    const float* gmlp   = (const float*)d_in[12];
    const float* bmlp   = (const float*)d_in[13];
    const float* freqs  = (const float*)d_in[14];
    float* out = (float*)d_out;

    float *proj, *hbuf, *m2;
    __half *qkvh, *xh, *wqkvh, *woh, *w1h, *w2h, *attnh, *hh, *mh;
    __half *qh, *kh, *vth;
    cudaGetSymbolAddress((void**)&proj, g_proj);
    cudaGetSymbolAddress((void**)&hbuf, g_hbuf);
    cudaGetSymbolAddress((void**)&m2,   g_m2);
    cudaGetSymbolAddress((void**)&qkvh, g_qkvh);
    cudaGetSymbolAddress((void**)&xh,    g_xh);
    cudaGetSymbolAddress((void**)&wqkvh, g_wqkvh);
    cudaGetSymbolAddress((void**)&woh,   g_woh);
    cudaGetSymbolAddress((void**)&w1h,   g_w1h);
    cudaGetSymbolAddress((void**)&w2h,   g_w2h);
    cudaGetSymbolAddress((void**)&attnh, g_attnh);
    cudaGetSymbolAddress((void**)&hh,    g_hh);
    cudaGetSymbolAddress((void**)&mh,    g_mh);
    cudaGetSymbolAddress((void**)&qh,    g_qh);
    cudaGetSymbolAddress((void**)&kh,    g_kh);
    cudaGetSymbolAddress((void**)&vth,   g_vth);

    cudaFuncSetAttribute(flash_attn_f16_kernel,
                         cudaFuncAttributeMaxDynamicSharedMemorySize, FH_SMEM);
    cudaFuncSetAttribute(gemm_f16_nt_bias<float>,
                         cudaFuncAttributeMaxDynamicSharedMemorySize, GH_SMEM);
    cudaFuncSetAttribute(gemm_f16_nt_bias<__half>,
                         cudaFuncAttributeMaxDynamicSharedMemorySize, GH_SMEM);
    cudaFuncSetAttribute(gemm_w1_gelu,
                         cudaFuncAttributeMaxDynamicSharedMemorySize, W1_SMEM);

    // 0) fp16 pre-conversion of GEMM inputs
    h_copy_kernel<<<(NTOK * DD / 4 + 255) / 256, 256>>>(x,    xh,    NTOK * DD / 4);
    h_copy_kernel<<<(D3 * DD / 4 + 255) / 256, 256>>>(Wqkv, wqkvh, D3 * DD / 4);
    h_copy_kernel<<<(DD * DD / 4 + 255) / 256, 256>>>(Wo,   woh,   DD * DD / 4);
    h_copy_kernel<<<(2 * FF * DD / 4 + 255) / 256, 256>>>(W1, w1h,  2 * FF * DD / 4);
    h_copy_kernel<<<(DD * FF / 4 + 255) / 256, 256>>>(W2,   w2h,   DD * FF / 4);

    // 1) QKV projection (fp16 TC, fp16 out)
    gemm_f16_nt_bias<__half><<<dim3(D3 / 128, NTOK / 128), 256, GH_SMEM>>>(
        xh, wqkvh, bqkv, qkvh, NTOK, D3, DD);

    // 2) RoPE -> fp16 q/k + transposed fp16 V
    rope_f16_kernel<<<(NTOK * D3 / 4) / 256, 256>>>(qkvh, p, freqs, qh, kh, vth);

    // 3) Flash attention (fp16 TC), fp16 output
    flash_attn_f16_kernel<<<dim3(SS / 64, HH, BB), 128, FH_SMEM>>>(
        qh, kh, vth, attnh);

    // 4) Output projection
    gemm_f16_nt_bias<float><<<dim3(DD / 128, NTOK / 128), 256, GH_SMEM>>>(
        attnh, woh, bo, proj, NTOK, DD, DD);

    // 5) h = LN(proj + x); fp16 copy for W1 GEMM
    add_ln_kernel<<<NTOK, 256>>>(proj, x, gattn, battn, hbuf, hh);

    // 6+7) m = gelu(h@W1a^T + b1a) * (h@W1g^T + b1g) — fused
    gemm_w1_gelu<<<dim3(FF / 64, NTOK / 128), 256, W1_SMEM>>>(
        hh, w1h, b1, mh, NTOK, DD);

    // 8) m2 = m @ W2^T + b2
    gemm_f16_nt_bias<float><<<dim3(DD / 128, NTOK / 128), 256, GH_SMEM>>>(
        mh, w2h, b2, m2, NTOK, DD, FF);

    // 9) out = LN(m2 + h)
    add_ln_kernel<<<NTOK, 256>>>(m2, hbuf, gmlp, bmlp, out, nullptr);
}